// round 1
// baseline (speedup 1.0000x reference)
#include <cuda_runtime.h>
#include <math.h>

// Problem dims (fixed by the reference)
#define NTOK   4096      // B*T = 2*2048
#define SEQ    2048
#define BATCH  2
#define DMODEL 1024
#define NH     16
#define HDIM   64
#define FFDIM  4096
#define QKVW   3072      // 3*DMODEL

// ---------------- scratch (device globals; no allocs allowed) ----------------
__device__ float g_h   [NTOK * DMODEL];   // LN1 output
__device__ float g_qkv [NTOK * QKVW];     // qkv projections
__device__ float g_attn[NTOK * DMODEL];   // attention output (b,t,h*hd)
__device__ float g_x2  [NTOK * DMODEL];   // residual after attn proj
__device__ float g_hh  [NTOK * DMODEL];   // LN2 output
__device__ float g_ff  [NTOK * FFDIM];    // gelu(hh@W1+b1f)

// ---------------- LayerNorm: one block per row of 1024 ----------------
__global__ __launch_bounds__(256) void ln_kernel(const float* __restrict__ x,
                                                 const float* __restrict__ g,
                                                 const float* __restrict__ b,
                                                 float* __restrict__ y)
{
    const int row = blockIdx.x;
    const int tid = threadIdx.x;
    const float* xr = x + (long)row * DMODEL;
    float4 v = *(const float4*)(xr + tid * 4);

    float s  = v.x + v.y + v.z + v.w;
    float sq = v.x*v.x + v.y*v.y + v.z*v.z + v.w*v.w;

    // warp reduce
    #pragma unroll
    for (int off = 16; off > 0; off >>= 1) {
        s  += __shfl_xor_sync(0xffffffffu, s,  off);
        sq += __shfl_xor_sync(0xffffffffu, sq, off);
    }
    __shared__ float reds[8], redq[8];
    const int wid = tid >> 5;
    if ((tid & 31) == 0) { reds[wid] = s; redq[wid] = sq; }
    __syncthreads();
    float st = 0.f, qt = 0.f;
    #pragma unroll
    for (int w = 0; w < 8; w++) { st += reds[w]; qt += redq[w]; }

    const float mu   = st * (1.0f / DMODEL);
    const float var  = qt * (1.0f / DMODEL) - mu * mu;
    const float rstd = rsqrtf(var + 1e-5f);

    float4 gv = *(const float4*)(g + tid * 4);
    float4 bv = *(const float4*)(b + tid * 4);
    float4 o;
    o.x = (v.x - mu) * rstd * gv.x + bv.x;
    o.y = (v.y - mu) * rstd * gv.y + bv.y;
    o.z = (v.z - mu) * rstd * gv.z + bv.z;
    o.w = (v.w - mu) * rstd * gv.w + bv.w;
    *(float4*)(y + (long)row * DMODEL + tid * 4) = o;
}

// ---------------- fp32 SGEMM 128x128x8, 8x8 micro, fused epilogue ----------------
// OP: 0 = bias, 1 = bias + exact GELU, 2 = bias + residual add
template<int OP>
__global__ __launch_bounds__(256) void gemm128(const float* __restrict__ A,
                                               const float* __restrict__ B,
                                               const float* __restrict__ bias,
                                               const float* __restrict__ res,
                                               float* __restrict__ C,
                                               int M, int N, int K)
{
    __shared__ float As[8][128];
    __shared__ float Bs[8][128];

    const int tid = threadIdx.x;
    const int tx  = tid & 15;
    const int ty  = tid >> 4;
    const int rowBase = blockIdx.y * 128;
    const int colBase = blockIdx.x * 128;

    const int aRow = tid >> 1;
    const int aCol = (tid & 1) << 2;
    const int bRow = tid >> 5;
    const int bCol = (tid & 31) << 2;

    const float* Aptr = A + (long)(rowBase + aRow) * K + aCol;
    const float* Bptr = B + (long)bRow * N + colBase + bCol;

    float acc[8][8];
    #pragma unroll
    for (int i = 0; i < 8; i++)
        #pragma unroll
        for (int j = 0; j < 8; j++) acc[i][j] = 0.f;

    for (int k0 = 0; k0 < K; k0 += 8) {
        float4 av = *(const float4*)(Aptr + k0);
        float4 bv = *(const float4*)(Bptr + (long)k0 * N);
        As[aCol + 0][aRow] = av.x;
        As[aCol + 1][aRow] = av.y;
        As[aCol + 2][aRow] = av.z;
        As[aCol + 3][aRow] = av.w;
        *(float4*)&Bs[bRow][bCol] = bv;
        __syncthreads();

        #pragma unroll
        for (int k = 0; k < 8; k++) {
            float4 a0 = *(const float4*)&As[k][ty * 8];
            float4 a1 = *(const float4*)&As[k][ty * 8 + 4];
            float4 b0 = *(const float4*)&Bs[k][tx * 8];
            float4 b1 = *(const float4*)&Bs[k][tx * 8 + 4];
            float a[8] = {a0.x, a0.y, a0.z, a0.w, a1.x, a1.y, a1.z, a1.w};
            float bb[8] = {b0.x, b0.y, b0.z, b0.w, b1.x, b1.y, b1.z, b1.w};
            #pragma unroll
            for (int i = 0; i < 8; i++)
                #pragma unroll
                for (int j = 0; j < 8; j++)
                    acc[i][j] = fmaf(a[i], bb[j], acc[i][j]);
        }
        __syncthreads();
    }

    #pragma unroll
    for (int i = 0; i < 8; i++) {
        const int r = rowBase + ty * 8 + i;
        #pragma unroll
        for (int j = 0; j < 8; j++) {
            const int c = colBase + tx * 8 + j;
            float v = acc[i][j] + bias[c];
            if (OP == 1) v = 0.5f * v * (1.0f + erff(v * 0.70710678118654752f));
            if (OP == 2) v += res[(long)r * N + c];
            C[(long)r * N + c] = v;
        }
    }
}

// ---------------- causal flash attention, fp32, 64x64 tiles ----------------
// grid: (qtile=32, head=16, batch=2), block = 256 (16x16), 4x4 micro
#define ATTN_SMEM ((64*64 + 64*65 + 64*64 + 64*64) * 4)

__global__ __launch_bounds__(256) void attn_kernel(const float* __restrict__ qkv,
                                                   float* __restrict__ out)
{
    extern __shared__ float sm[];
    float* Qs = sm;               // [64][64]
    float* Ks = Qs + 64 * 64;     // [64][65] (padded)
    float* Vs = Ks + 64 * 65;     // [64][64]
    float* Ps = Vs + 64 * 64;     // [64][64]

    const int qt   = blockIdx.x;
    const int head = blockIdx.y;
    const int bat  = blockIdx.z;
    const int tid  = threadIdx.x;
    const int tx   = tid & 15;
    const int ty   = tid >> 4;
    const int r0   = ty * 4;      // local query rows
    const int c0   = tx * 4;      // local key cols / head-dim cols
    const float scale = 0.125f;   // 1/sqrt(64)

    const float* base = qkv + (long)bat * SEQ * QKVW;

    // load Q tile (scaled)
    for (int idx = tid; idx < 64 * 64; idx += 256) {
        const int r = idx >> 6, c = idx & 63;
        Qs[idx] = base[(long)(qt * 64 + r) * QKVW + head * 64 + c] * scale;
    }

    float o[4][4];
    float m_i[4], l_i[4];
    #pragma unroll
    for (int i = 0; i < 4; i++) {
        m_i[i] = -1e30f; l_i[i] = 0.f;
        #pragma unroll
        for (int j = 0; j < 4; j++) o[i][j] = 0.f;
    }

    for (int kt = 0; kt <= qt; kt++) {
        __syncthreads();   // previous-iter consumers done (also covers Q load on iter 0)
        for (int idx = tid; idx < 64 * 64; idx += 256) {
            const int r = idx >> 6, c = idx & 63;
            const long g = (long)(kt * 64 + r) * QKVW + head * 64 + c;
            Ks[r * 65 + c] = base[g + 1024];
            Vs[idx]        = base[g + 2048];
        }
        __syncthreads();

        // S = Q K^T
        float s[4][4];
        #pragma unroll
        for (int i = 0; i < 4; i++)
            #pragma unroll
            for (int j = 0; j < 4; j++) s[i][j] = 0.f;
        for (int kk = 0; kk < 64; kk++) {
            float qa[4], kb[4];
            #pragma unroll
            for (int i = 0; i < 4; i++) qa[i] = Qs[(r0 + i) * 64 + kk];
            #pragma unroll
            for (int j = 0; j < 4; j++) kb[j] = Ks[(c0 + j) * 65 + kk];
            #pragma unroll
            for (int i = 0; i < 4; i++)
                #pragma unroll
                for (int j = 0; j < 4; j++)
                    s[i][j] = fmaf(qa[i], kb[j], s[i][j]);
        }

        // causal mask (only diagonal tile needs it)
        if (kt == qt) {
            #pragma unroll
            for (int i = 0; i < 4; i++)
                #pragma unroll
                for (int j = 0; j < 4; j++)
                    if (c0 + j > r0 + i) s[i][j] = -1e30f;
        }

        // online softmax; row group = 16 lanes sharing ty (same half-warp)
        #pragma unroll
        for (int i = 0; i < 4; i++) {
            float mloc = fmaxf(fmaxf(s[i][0], s[i][1]), fmaxf(s[i][2], s[i][3]));
            #pragma unroll
            for (int off = 8; off > 0; off >>= 1)
                mloc = fmaxf(mloc, __shfl_xor_sync(0xffffffffu, mloc, off));
            const float mnew = fmaxf(m_i[i], mloc);
            const float sc   = __expf(m_i[i] - mnew);
            float p[4], ssum = 0.f;
            #pragma unroll
            for (int j = 0; j < 4; j++) { p[j] = __expf(s[i][j] - mnew); ssum += p[j]; }
            #pragma unroll
            for (int off = 8; off > 0; off >>= 1)
                ssum += __shfl_xor_sync(0xffffffffu, ssum, off);
            l_i[i] = l_i[i] * sc + ssum;
            m_i[i] = mnew;
            #pragma unroll
            for (int j = 0; j < 4; j++) o[i][j] *= sc;
            #pragma unroll
            for (int j = 0; j < 4; j++) Ps[(r0 + i) * 64 + (c0 + j)] = p[j];
        }
        __syncthreads();

        // O += P V
        for (int kk = 0; kk < 64; kk++) {
            float pa[4];
            #pragma unroll
            for (int i = 0; i < 4; i++) pa[i] = Ps[(r0 + i) * 64 + kk];
            const float4 vb = *(const float4*)&Vs[kk * 64 + c0];
            #pragma unroll
            for (int i = 0; i < 4; i++) {
                o[i][0] = fmaf(pa[i], vb.x, o[i][0]);
                o[i][1] = fmaf(pa[i], vb.y, o[i][1]);
                o[i][2] = fmaf(pa[i], vb.z, o[i][2]);
                o[i][3] = fmaf(pa[i], vb.w, o[i][3]);
            }
        }
    }

    // write normalized output: out[b, t, head*64 + d]
    #pragma unroll
    for (int i = 0; i < 4; i++) {
        const int q = qt * 64 + r0 + i;
        const float inv_l = 1.0f / l_i[i];
        #pragma unroll
        for (int j = 0; j < 4; j++)
            out[(long)(bat * SEQ + q) * DMODEL + head * 64 + c0 + j] = o[i][j] * inv_l;
    }
}

// ---------------- driver ----------------
extern "C" void kernel_launch(void* const* d_in, const int* in_sizes, int n_in,
                              void* d_out, int out_size)
{
    const float* x    = (const float*)d_in[0];
    const float* g1   = (const float*)d_in[1];
    const float* b1   = (const float*)d_in[2];
    const float* Wqkv = (const float*)d_in[3];
    const float* bqkv = (const float*)d_in[4];
    const float* Wo   = (const float*)d_in[5];
    const float* bo   = (const float*)d_in[6];
    const float* g2   = (const float*)d_in[7];
    const float* b2   = (const float*)d_in[8];
    const float* W1   = (const float*)d_in[9];
    const float* b1f  = (const float*)d_in[10];
    const float* W2   = (const float*)d_in[11];
    const float* b2f  = (const float*)d_in[12];
    float* out = (float*)d_out;

    float *h, *qkv, *attn, *x2, *hh, *ff;
    cudaGetSymbolAddress((void**)&h,    g_h);
    cudaGetSymbolAddress((void**)&qkv,  g_qkv);
    cudaGetSymbolAddress((void**)&attn, g_attn);
    cudaGetSymbolAddress((void**)&x2,   g_x2);
    cudaGetSymbolAddress((void**)&hh,   g_hh);
    cudaGetSymbolAddress((void**)&ff,   g_ff);

    cudaFuncSetAttribute(attn_kernel,
                         cudaFuncAttributeMaxDynamicSharedMemorySize, ATTN_SMEM);

    // LN1
    ln_kernel<<<NTOK, 256>>>(x, g1, b1, h);
    // QKV projection: (4096,1024) @ (1024,3072)
    gemm128<0><<<dim3(QKVW / 128, NTOK / 128), 256>>>(h, Wqkv, bqkv, nullptr, qkv,
                                                      NTOK, QKVW, DMODEL);
    // causal attention
    attn_kernel<<<dim3(SEQ / 64, NH, BATCH), 256, ATTN_SMEM>>>(qkv, attn);
    // output projection + residual: x2 = x + attn @ Wo + bo
    gemm128<2><<<dim3(DMODEL / 128, NTOK / 128), 256>>>(attn, Wo, bo, x, x2,
                                                        NTOK, DMODEL, DMODEL);
    // LN2
    ln_kernel<<<NTOK, 256>>>(x2, g2, b2, hh);
    // FF1 + exact GELU
    gemm128<1><<<dim3(FFDIM / 128, NTOK / 128), 256>>>(hh, W1, b1f, nullptr, ff,
                                                       NTOK, FFDIM, DMODEL);
    // FF2 + residual: out = x2 + ff @ W2 + b2f
    gemm128<2><<<dim3(DMODEL / 128, NTOK / 128), 256>>>(ff, W2, b2f, x2, out,
                                                        NTOK, DMODEL, FFDIM);
}

// round 3
// speedup vs baseline: 2.6270x; 2.6270x over previous
#include <cuda_runtime.h>
#include <cuda_bf16.h>
#include <math.h>
#include <stdint.h>

// Problem dims (fixed by the reference)
#define NTOK   4096      // B*T = 2*2048
#define SEQ    2048
#define BATCH  2
#define DMODEL 1024
#define NH     16
#define HDIM   64
#define FFDIM  4096
#define QKVW   3072      // 3*DMODEL

// tcgen05 only exists in the arch-specific (sm_103a / sm_103f) compilation pass.
#if defined(__CUDA_ARCH__) && (__CUDA_ARCH__ == 1030) && \
    (defined(__CUDA_ARCH_FEAT_SM103_ALL) || defined(__CUDA_ARCH_SPECIFIC__) || \
     defined(__CUDA_ARCH_FAMILY_SPECIFIC__))
#define HAS_TCGEN05 1
#else
#define HAS_TCGEN05 0
#endif

#if HAS_TCGEN05
// ======================= PTX helpers (arch-specific pass only) =======================
__device__ __forceinline__ uint32_t smem_to_u32(const void* p) {
    uint32_t a;
    asm("{ .reg .u64 t; cvta.to.shared.u64 t, %1; cvt.u32.u64 %0, t; }" : "=r"(a) : "l"(p));
    return a;
}
__device__ __forceinline__ uint32_t elect_one_pred() {
    uint32_t pred;
    asm volatile("{\n\t.reg .pred p;\n\telect.sync _|p, 0xFFFFFFFF;\n\tselp.b32 %0, 1, 0, p;\n\t}"
                 : "=r"(pred));
    return pred;
}

static constexpr uint64_t SMEM_DESC_BASE_SW128 =
    (uint64_t(2) << 61) | (uint64_t(1) << 46) | (uint64_t(64) << 32) | (uint64_t(1) << 16);
#define MAKE_SMEM_DESC(base_addr) \
    (SMEM_DESC_BASE_SW128 | ((uint64_t)((base_addr) >> 4) & 0x3FFF))

#define TCGEN05_ALLOC(sa, n) \
    asm volatile("tcgen05.alloc.cta_group::1.sync.aligned.shared::cta.b32 [%0], %1;" \
                 :: "r"((uint32_t)(sa)), "r"((uint32_t)(n)) : "memory")
#define TCGEN05_DEALLOC(t, n) \
    asm volatile("tcgen05.dealloc.cta_group::1.sync.aligned.b32 %0, %1;" :: "r"(t), "r"((uint32_t)(n)))
#define TCGEN05_RELINQUISH() \
    asm volatile("tcgen05.relinquish_alloc_permit.cta_group::1.sync.aligned;")
#define TCGEN05_COMMIT(mb) \
    asm volatile("tcgen05.commit.cta_group::1.mbarrier::arrive::one.shared::cluster.b64 [%0];" \
                 :: "r"((uint32_t)(mb)) : "memory")
#define TCGEN05_FENCE_AFTER() asm volatile("tcgen05.fence::after_thread_sync;" ::: "memory")
#define TCGEN05_WAIT_LD() asm volatile("tcgen05.wait::ld.sync.aligned;" ::: "memory")
#define FENCE_PROXY_ASYNC() asm volatile("fence.proxy.async.shared::cta;" ::: "memory")

#define MBARRIER_INIT(mb, cnt) \
    asm volatile("mbarrier.init.shared.b64 [%0], %1;" :: "r"((uint32_t)(mb)), "r"((uint32_t)(cnt)) : "memory")

#define MBARRIER_WAIT_PARITY(mb, par) do { \
    uint32_t _mb = (uint32_t)(mb), _p = (uint32_t)(par), _d; \
    asm volatile("{\n\t.reg .pred p;\n\t" \
        "mbarrier.try_wait.parity.acquire.cta.shared::cta.b64 p, [%1], %2;\n\t" \
        "selp.b32 %0, 1, 0, p;\n\t}" : "=r"(_d) : "r"(_mb), "r"(_p) : "memory"); \
    if (!_d) { \
        asm volatile("{\n\t.reg .pred P1;\n\t" \
            "WL_%=:\n\t" \
            "mbarrier.try_wait.parity.acquire.cta.shared::cta.b64 P1, [%0], %1, 0x989680;\n\t" \
            "@P1 bra.uni WD_%=;\n\t" \
            "bra.uni WL_%=;\n\t" \
            "WD_%=:\n\t}" :: "r"(_mb), "r"(_p) : "memory"); \
    } \
} while (0)

#define TCGEN05_LD_X32(r, ta) \
    asm volatile("tcgen05.ld.sync.aligned.32x32b.x32.b32 " \
        "{%0, %1, %2, %3, %4, %5, %6, %7, %8, %9, %10, %11, %12, %13, %14, %15, " \
        "%16, %17, %18, %19, %20, %21, %22, %23, %24, %25, %26, %27, %28, %29, %30, %31}, [%32];" \
        : "=r"((r)[0]), "=r"((r)[1]), "=r"((r)[2]), "=r"((r)[3]), \
          "=r"((r)[4]), "=r"((r)[5]), "=r"((r)[6]), "=r"((r)[7]), \
          "=r"((r)[8]), "=r"((r)[9]), "=r"((r)[10]), "=r"((r)[11]), \
          "=r"((r)[12]), "=r"((r)[13]), "=r"((r)[14]), "=r"((r)[15]), \
          "=r"((r)[16]), "=r"((r)[17]), "=r"((r)[18]), "=r"((r)[19]), \
          "=r"((r)[20]), "=r"((r)[21]), "=r"((r)[22]), "=r"((r)[23]), \
          "=r"((r)[24]), "=r"((r)[25]), "=r"((r)[26]), "=r"((r)[27]), \
          "=r"((r)[28]), "=r"((r)[29]), "=r"((r)[30]), "=r"((r)[31]) \
        : "r"(ta))

// cg1 kind::f16 SS-mode MMA (A and B both in SMEM, bf16 in / fp32 accum)
__device__ __forceinline__ void mma_f16_ss(uint32_t d, uint64_t ad, uint64_t bd,
                                           uint32_t idesc, bool acc) {
    uint32_t en = acc ? 1u : 0u;
    asm volatile(
        "{\n\t.reg .pred p;\n\tsetp.ne.u32 p, %5, 0;\n\t"
        "tcgen05.mma.cta_group::1.kind::f16 [%0], %1, %2, %3, {%4, %4, %4, %4}, p;\n\t}"
        :: "r"(d), "l"(ad), "l"(bd), "r"(idesc), "r"(0u), "r"(en) : "memory");
}

// idesc: fp32 accum, bf16 A/B, M=128, N=128, K-major both
static constexpr uint32_t GEMM_IDESC =
    (1u << 4) | (1u << 7) | (1u << 10) | ((128u / 8u) << 17) | ((128u / 16u) << 24);
#endif  // HAS_TCGEN05

#define SMEM_SWIZZLE_128B(off) ((off) ^ (((off) >> 3) & 0x70))

// ======================= scratch (device globals) =======================
__device__ float g_qkv [NTOK * QKVW];            // fp32 qkv (attention input)
__device__ float g_x2  [NTOK * DMODEL];          // residual after attn proj
__device__ __nv_bfloat16 g_h_hi  [NTOK * DMODEL], g_h_lo  [NTOK * DMODEL];
__device__ __nv_bfloat16 g_attn_hi[NTOK * DMODEL], g_attn_lo[NTOK * DMODEL];
__device__ __nv_bfloat16 g_hh_hi [NTOK * DMODEL], g_hh_lo [NTOK * DMODEL];
__device__ __nv_bfloat16 g_ff_hi [NTOK * FFDIM],  g_ff_lo [NTOK * FFDIM];
__device__ __nv_bfloat16 g_WqkvT_hi[QKVW * DMODEL],  g_WqkvT_lo[QKVW * DMODEL];
__device__ __nv_bfloat16 g_WoT_hi [DMODEL * DMODEL], g_WoT_lo [DMODEL * DMODEL];
__device__ __nv_bfloat16 g_W1T_hi [FFDIM * DMODEL],  g_W1T_lo [FFDIM * DMODEL];
__device__ __nv_bfloat16 g_W2T_hi [DMODEL * FFDIM],  g_W2T_lo [DMODEL * FFDIM];

__device__ __forceinline__ void split_store(__nv_bfloat16* hi, __nv_bfloat16* lo,
                                            long ofs, float v) {
    __nv_bfloat16 h = __float2bfloat16(v);
    hi[ofs] = h;
    lo[ofs] = __float2bfloat16(v - __bfloat162float(h));
}

__device__ __forceinline__ float gelu_exact(float x) {
    return 0.5f * x * (1.0f + erff(x * 0.70710678118654752f));
}

// ======================= LayerNorm -> bf16 hi/lo planes =======================
__global__ __launch_bounds__(256) void ln_kernel(const float* __restrict__ x,
                                                 const float* __restrict__ g,
                                                 const float* __restrict__ b,
                                                 __nv_bfloat16* __restrict__ yhi,
                                                 __nv_bfloat16* __restrict__ ylo)
{
    const int row = blockIdx.x;
    const int tid = threadIdx.x;
    const float* xr = x + (long)row * DMODEL;
    float4 v = *(const float4*)(xr + tid * 4);

    float s  = v.x + v.y + v.z + v.w;
    float sq = v.x*v.x + v.y*v.y + v.z*v.z + v.w*v.w;
    #pragma unroll
    for (int off = 16; off > 0; off >>= 1) {
        s  += __shfl_xor_sync(0xffffffffu, s,  off);
        sq += __shfl_xor_sync(0xffffffffu, sq, off);
    }
    __shared__ float reds[8], redq[8];
    const int wid = tid >> 5;
    if ((tid & 31) == 0) { reds[wid] = s; redq[wid] = sq; }
    __syncthreads();
    float st = 0.f, qt = 0.f;
    #pragma unroll
    for (int w = 0; w < 8; w++) { st += reds[w]; qt += redq[w]; }

    const float mu   = st * (1.0f / DMODEL);
    const float var  = qt * (1.0f / DMODEL) - mu * mu;
    const float rstd = rsqrtf(var + 1e-5f);

    float4 gv = *(const float4*)(g + tid * 4);
    float4 bv = *(const float4*)(b + tid * 4);
    float o0 = (v.x - mu) * rstd * gv.x + bv.x;
    float o1 = (v.y - mu) * rstd * gv.y + bv.y;
    float o2 = (v.z - mu) * rstd * gv.z + bv.z;
    float o3 = (v.w - mu) * rstd * gv.w + bv.w;
    const long base = (long)row * DMODEL + tid * 4;
    split_store(yhi, ylo, base + 0, o0);
    split_store(yhi, ylo, base + 1, o1);
    split_store(yhi, ylo, base + 2, o2);
    split_store(yhi, ylo, base + 3, o3);
}

// ============== weight transpose + bf16 hi/lo: W[K,N] -> T[N,K] ==============
__global__ __launch_bounds__(256) void wtrans_kernel(const float* __restrict__ W,
                                                     __nv_bfloat16* __restrict__ Thi,
                                                     __nv_bfloat16* __restrict__ Tlo,
                                                     int K, int N)
{
    __shared__ float tile[32][33];
    const int nb = blockIdx.x * 32;
    const int kb = blockIdx.y * 32;
    const int tx = threadIdx.x;       // 0..31
    const int ty = threadIdx.y;       // 0..7
    #pragma unroll
    for (int i = ty; i < 32; i += 8)
        tile[i][tx] = W[(long)(kb + i) * N + nb + tx];
    __syncthreads();
    #pragma unroll
    for (int i = ty; i < 32; i += 8) {
        float v = tile[tx][i];        // = W[kb+tx][nb+i]
        const long ofs = (long)(nb + i) * K + kb + tx;
        __nv_bfloat16 h = __float2bfloat16(v);
        Thi[ofs] = h;
        Tlo[ofs] = __float2bfloat16(v - __bfloat162float(h));
    }
}

// ======================= GEMM =======================
// C[M,N] = A[M,K] @ B[N,K]^T with A,B given as bf16 hi/lo planes (K-major).
// OP: 0 = +bias -> fp32 ; 1 = +bias, GELU -> bf16 hi/lo ; 2 = +bias +res -> fp32
#define SM_TMEMPTR 0
#define SM_MBAR    16          // two mbarriers at 16, 24
#define SM_TILES   1024
#define TILE_B     16384       // 128 rows x 128 bytes (64 bf16)
#define STAGE_B    (4 * TILE_B)
#define GEMM_SMEM  (SM_TILES + 2 * STAGE_B)

template<int OP>
__global__ __launch_bounds__(256, 1) void gemm_tc(
    const __nv_bfloat16* __restrict__ Ahi, const __nv_bfloat16* __restrict__ Alo,
    const __nv_bfloat16* __restrict__ Bhi, const __nv_bfloat16* __restrict__ Blo,
    const float* __restrict__ bias, const float* __restrict__ res,
    float* __restrict__ Cf,
    __nv_bfloat16* __restrict__ Chi, __nv_bfloat16* __restrict__ Clo,
    int N, int K)
{
    extern __shared__ __align__(1024) char smem[];
    const int tid = threadIdx.x;
    const int mBase = blockIdx.y * 128;
    const int nBase = blockIdx.x * 128;

#if HAS_TCGEN05
    const uint32_t smem_base = smem_to_u32(smem);
    const int wid = tid >> 5;
    const int lid = tid & 31;

    if (wid == 0) {
        TCGEN05_ALLOC(smem_base + SM_TMEMPTR, 128);
        TCGEN05_RELINQUISH();
    }
    if (tid == 0) {
        MBARRIER_INIT(smem_base + SM_MBAR + 0, 1);
        MBARRIER_INIT(smem_base + SM_MBAR + 8, 1);
    }
    __syncthreads();
    uint32_t tmem;
    asm volatile("ld.shared.b32 %0, [%1];" : "=r"(tmem) : "r"(smem_base + SM_TMEMPTR));

    const int NC = K >> 6;   // K-chunks of 64
    for (int c = 0; c < NC; c++) {
        const int s = c & 1;
        if (c >= 2)
            MBARRIER_WAIT_PARITY(smem_base + SM_MBAR + s * 8, ((c >> 1) - 1) & 1);

        const int k0 = c << 6;
        const __nv_bfloat16* src0 = Ahi + (long)mBase * K + k0;
        const __nv_bfloat16* src1 = Alo + (long)mBase * K + k0;
        const __nv_bfloat16* src2 = Bhi + (long)nBase * K + k0;
        const __nv_bfloat16* src3 = Blo + (long)nBase * K + k0;
        const int stage_off = SM_TILES + s * STAGE_B;
        #pragma unroll
        for (int i = 0; i < 4; i++) {
            const int idx = tid + i * 256;      // 0..1023
            const int r   = idx >> 3;
            const int c16 = idx & 7;
            const long gofs = (long)r * K + (c16 << 3);
            const int  sofs = stage_off + SMEM_SWIZZLE_128B((r << 7) | (c16 << 4));
            *(uint4*)(smem + sofs + 0 * TILE_B) = *(const uint4*)(src0 + gofs);
            *(uint4*)(smem + sofs + 1 * TILE_B) = *(const uint4*)(src1 + gofs);
            *(uint4*)(smem + sofs + 2 * TILE_B) = *(const uint4*)(src2 + gofs);
            *(uint4*)(smem + sofs + 3 * TILE_B) = *(const uint4*)(src3 + gofs);
        }
        FENCE_PROXY_ASYNC();
        __syncthreads();

        if (wid == 0) {
            const uint32_t st = smem_base + stage_off;
            const uint64_t dAhi = MAKE_SMEM_DESC(st + 0 * TILE_B);
            const uint64_t dAlo = MAKE_SMEM_DESC(st + 1 * TILE_B);
            const uint64_t dBhi = MAKE_SMEM_DESC(st + 2 * TILE_B);
            const uint64_t dBlo = MAKE_SMEM_DESC(st + 3 * TILE_B);
            if (elect_one_pred()) {
                #pragma unroll
                for (int kk = 0; kk < 4; kk++) {
                    mma_f16_ss(tmem, dAhi + kk * 2, dBhi + kk * 2, GEMM_IDESC,
                               !(c == 0 && kk == 0));
                    mma_f16_ss(tmem, dAlo + kk * 2, dBhi + kk * 2, GEMM_IDESC, true);
                    mma_f16_ss(tmem, dAhi + kk * 2, dBlo + kk * 2, GEMM_IDESC, true);
                }
                TCGEN05_COMMIT(smem_base + SM_MBAR + s * 8);
            }
        }
    }

    // wait for ALL MMAs (last commit covers all prior)
    {
        const int s_last = (NC - 1) & 1;
        const int nlast  = ((NC - 1 - s_last) >> 1) + 1;
        MBARRIER_WAIT_PARITY(smem_base + SM_MBAR + s_last * 8, (nlast - 1) & 1);
    }
    TCGEN05_FENCE_AFTER();

    // Epilogue: TMEM -> SMEM (row-stage) -> coalesced global
    float* sout = (float*)(smem + SM_TILES);
    if (wid < 4) {
        const int r = (wid << 5) + lid;
        #pragma unroll
        for (int cb = 0; cb < 4; cb++) {
            uint32_t regs[32];
            TCGEN05_LD_X32(regs, tmem + (cb << 5));
            TCGEN05_WAIT_LD();
            #pragma unroll
            for (int j = 0; j < 32; j += 4) {
                float4 v = make_float4(__uint_as_float(regs[j]),
                                       __uint_as_float(regs[j + 1]),
                                       __uint_as_float(regs[j + 2]),
                                       __uint_as_float(regs[j + 3]));
                *(float4*)&sout[r * 132 + (cb << 5) + j] = v;
            }
        }
    }
    __syncthreads();
    if (wid == 0) TCGEN05_DEALLOC(tmem, 128);

    for (int idx = tid; idx < 128 * 32; idx += 256) {
        const int r = idx >> 5;
        const int cc = (idx & 31) << 2;
        float4 v = *(float4*)&sout[r * 132 + cc];
        const long gr = mBase + r;
        const int  gc = nBase + cc;
        float4 bb = *(const float4*)&bias[gc];
        v.x += bb.x; v.y += bb.y; v.z += bb.z; v.w += bb.w;
        if (OP == 1) {
            v.x = gelu_exact(v.x); v.y = gelu_exact(v.y);
            v.z = gelu_exact(v.z); v.w = gelu_exact(v.w);
            const long o = gr * N + gc;
            split_store(Chi, Clo, o + 0, v.x);
            split_store(Chi, Clo, o + 1, v.y);
            split_store(Chi, Clo, o + 2, v.z);
            split_store(Chi, Clo, o + 3, v.w);
        } else if (OP == 2) {
            float4 rr = *(const float4*)&res[gr * N + gc];
            v.x += rr.x; v.y += rr.y; v.z += rr.z; v.w += rr.w;
            *(float4*)&Cf[gr * N + gc] = v;
        } else {
            *(float4*)&Cf[gr * N + gc] = v;
        }
    }

#else  // =================== FFMA fallback (non-103a passes) ===================
    float* As = (float*)smem;                 // [8][128]
    float* Bs = As + 8 * 128;                 // [8][128]

    const int tx = tid & 15;
    const int ty = tid >> 4;
    const int row  = tid >> 1;                // 0..127
    const int kc   = (tid & 1) << 2;          // 0 or 4

    float acc[8][8];
    #pragma unroll
    for (int i = 0; i < 8; i++)
        #pragma unroll
        for (int j = 0; j < 8; j++) acc[i][j] = 0.f;

    for (int k0 = 0; k0 < K; k0 += 8) {
        // A operand: row (mBase+row), k = k0+kc..k0+kc+3
        {
            const long o = (long)(mBase + row) * K + k0 + kc;
            ushort4 h = *(const ushort4*)(Ahi + o);
            ushort4 l = *(const ushort4*)(Alo + o);
            As[(kc + 0) * 128 + row] = __bfloat162float(*(__nv_bfloat16*)&h.x) + __bfloat162float(*(__nv_bfloat16*)&l.x);
            As[(kc + 1) * 128 + row] = __bfloat162float(*(__nv_bfloat16*)&h.y) + __bfloat162float(*(__nv_bfloat16*)&l.y);
            As[(kc + 2) * 128 + row] = __bfloat162float(*(__nv_bfloat16*)&h.z) + __bfloat162float(*(__nv_bfloat16*)&l.z);
            As[(kc + 3) * 128 + row] = __bfloat162float(*(__nv_bfloat16*)&h.w) + __bfloat162float(*(__nv_bfloat16*)&l.w);
        }
        {
            const long o = (long)(nBase + row) * K + k0 + kc;
            ushort4 h = *(const ushort4*)(Bhi + o);
            ushort4 l = *(const ushort4*)(Blo + o);
            Bs[(kc + 0) * 128 + row] = __bfloat162float(*(__nv_bfloat16*)&h.x) + __bfloat162float(*(__nv_bfloat16*)&l.x);
            Bs[(kc + 1) * 128 + row] = __bfloat162float(*(__nv_bfloat16*)&h.y) + __bfloat162float(*(__nv_bfloat16*)&l.y);
            Bs[(kc + 2) * 128 + row] = __bfloat162float(*(__nv_bfloat16*)&h.z) + __bfloat162float(*(__nv_bfloat16*)&l.z);
            Bs[(kc + 3) * 128 + row] = __bfloat162float(*(__nv_bfloat16*)&h.w) + __bfloat162float(*(__nv_bfloat16*)&l.w);
        }
        __syncthreads();

        #pragma unroll
        for (int k = 0; k < 8; k++) {
            float a[8], bb[8];
            #pragma unroll
            for (int i = 0; i < 8; i++) a[i]  = As[k * 128 + ty * 8 + i];
            #pragma unroll
            for (int j = 0; j < 8; j++) bb[j] = Bs[k * 128 + tx * 8 + j];
            #pragma unroll
            for (int i = 0; i < 8; i++)
                #pragma unroll
                for (int j = 0; j < 8; j++)
                    acc[i][j] = fmaf(a[i], bb[j], acc[i][j]);
        }
        __syncthreads();
    }

    #pragma unroll
    for (int i = 0; i < 8; i++) {
        const long gr = mBase + ty * 8 + i;
        #pragma unroll
        for (int j = 0; j < 8; j++) {
            const int gc = nBase + tx * 8 + j;
            float v = acc[i][j] + bias[gc];
            if (OP == 1) {
                v = gelu_exact(v);
                split_store(Chi, Clo, gr * N + gc, v);
            } else if (OP == 2) {
                Cf[gr * N + gc] = v + res[gr * N + gc];
            } else {
                Cf[gr * N + gc] = v;
            }
        }
    }
#endif
}

// ======================= causal flash attention (fp32) =======================
#define ATTN_SMEM ((64*64 + 64*65 + 64*64 + 64*64) * 4)

__global__ __launch_bounds__(256) void attn_kernel(const float* __restrict__ qkv,
                                                   __nv_bfloat16* __restrict__ ohi,
                                                   __nv_bfloat16* __restrict__ olo)
{
    extern __shared__ float sm[];
    float* Qs = sm;
    float* Ks = Qs + 64 * 64;
    float* Vs = Ks + 64 * 65;
    float* Ps = Vs + 64 * 64;

    const int qt   = blockIdx.x;
    const int head = blockIdx.y;
    const int bat  = blockIdx.z;
    const int tid  = threadIdx.x;
    const int tx   = tid & 15;
    const int ty   = tid >> 4;
    const int r0   = ty * 4;
    const int c0   = tx * 4;
    const float scale = 0.125f;

    const float* base = qkv + (long)bat * SEQ * QKVW;

    for (int idx = tid; idx < 64 * 64; idx += 256) {
        const int r = idx >> 6, c = idx & 63;
        Qs[idx] = base[(long)(qt * 64 + r) * QKVW + head * 64 + c] * scale;
    }

    float o[4][4];
    float m_i[4], l_i[4];
    #pragma unroll
    for (int i = 0; i < 4; i++) {
        m_i[i] = -1e30f; l_i[i] = 0.f;
        #pragma unroll
        for (int j = 0; j < 4; j++) o[i][j] = 0.f;
    }

    for (int kt = 0; kt <= qt; kt++) {
        __syncthreads();
        for (int idx = tid; idx < 64 * 64; idx += 256) {
            const int r = idx >> 6, c = idx & 63;
            const long g = (long)(kt * 64 + r) * QKVW + head * 64 + c;
            Ks[r * 65 + c] = base[g + 1024];
            Vs[idx]        = base[g + 2048];
        }
        __syncthreads();

        float s[4][4];
        #pragma unroll
        for (int i = 0; i < 4; i++)
            #pragma unroll
            for (int j = 0; j < 4; j++) s[i][j] = 0.f;
        for (int kk = 0; kk < 64; kk++) {
            float qa[4], kb[4];
            #pragma unroll
            for (int i = 0; i < 4; i++) qa[i] = Qs[(r0 + i) * 64 + kk];
            #pragma unroll
            for (int j = 0; j < 4; j++) kb[j] = Ks[(c0 + j) * 65 + kk];
            #pragma unroll
            for (int i = 0; i < 4; i++)
                #pragma unroll
                for (int j = 0; j < 4; j++)
                    s[i][j] = fmaf(qa[i], kb[j], s[i][j]);
        }

        if (kt == qt) {
            #pragma unroll
            for (int i = 0; i < 4; i++)
                #pragma unroll
                for (int j = 0; j < 4; j++)
                    if (c0 + j > r0 + i) s[i][j] = -1e30f;
        }

        #pragma unroll
        for (int i = 0; i < 4; i++) {
            float mloc = fmaxf(fmaxf(s[i][0], s[i][1]), fmaxf(s[i][2], s[i][3]));
            #pragma unroll
            for (int off = 8; off > 0; off >>= 1)
                mloc = fmaxf(mloc, __shfl_xor_sync(0xffffffffu, mloc, off));
            const float mnew = fmaxf(m_i[i], mloc);
            const float sc   = __expf(m_i[i] - mnew);
            float p[4], ssum = 0.f;
            #pragma unroll
            for (int j = 0; j < 4; j++) { p[j] = __expf(s[i][j] - mnew); ssum += p[j]; }
            #pragma unroll
            for (int off = 8; off > 0; off >>= 1)
                ssum += __shfl_xor_sync(0xffffffffu, ssum, off);
            l_i[i] = l_i[i] * sc + ssum;
            m_i[i] = mnew;
            #pragma unroll
            for (int j = 0; j < 4; j++) o[i][j] *= sc;
            #pragma unroll
            for (int j = 0; j < 4; j++) Ps[(r0 + i) * 64 + (c0 + j)] = p[j];
        }
        __syncthreads();

        for (int kk = 0; kk < 64; kk++) {
            float pa[4];
            #pragma unroll
            for (int i = 0; i < 4; i++) pa[i] = Ps[(r0 + i) * 64 + kk];
            const float4 vb = *(const float4*)&Vs[kk * 64 + c0];
            #pragma unroll
            for (int i = 0; i < 4; i++) {
                o[i][0] = fmaf(pa[i], vb.x, o[i][0]);
                o[i][1] = fmaf(pa[i], vb.y, o[i][1]);
                o[i][2] = fmaf(pa[i], vb.z, o[i][2]);
                o[i][3] = fmaf(pa[i], vb.w, o[i][3]);
            }
        }
    }

    #pragma unroll
    for (int i = 0; i < 4; i++) {
        const int q = qt * 64 + r0 + i;
        const float inv_l = 1.0f / l_i[i];
        #pragma unroll
        for (int j = 0; j < 4; j++) {
            const long ofs = (long)(bat * SEQ + q) * DMODEL + head * 64 + c0 + j;
            split_store(ohi, olo, ofs, o[i][j] * inv_l);
        }
    }
}

// ======================= driver =======================
extern "C" void kernel_launch(void* const* d_in, const int* in_sizes, int n_in,
                              void* d_out, int out_size)
{
    const float* x    = (const float*)d_in[0];
    const float* g1   = (const float*)d_in[1];
    const float* b1   = (const float*)d_in[2];
    const float* Wqkv = (const float*)d_in[3];
    const float* bqkv = (const float*)d_in[4];
    const float* Wo   = (const float*)d_in[5];
    const float* bo   = (const float*)d_in[6];
    const float* g2   = (const float*)d_in[7];
    const float* b2   = (const float*)d_in[8];
    const float* W1   = (const float*)d_in[9];
    const float* b1f  = (const float*)d_in[10];
    const float* W2   = (const float*)d_in[11];
    const float* b2f  = (const float*)d_in[12];
    float* out = (float*)d_out;

    float *qkv, *x2;
    __nv_bfloat16 *h_hi, *h_lo, *attn_hi, *attn_lo, *hh_hi, *hh_lo, *ff_hi, *ff_lo;
    __nv_bfloat16 *WqkvT_hi, *WqkvT_lo, *WoT_hi, *WoT_lo, *W1T_hi, *W1T_lo, *W2T_hi, *W2T_lo;
    cudaGetSymbolAddress((void**)&qkv,      g_qkv);
    cudaGetSymbolAddress((void**)&x2,       g_x2);
    cudaGetSymbolAddress((void**)&h_hi,     g_h_hi);
    cudaGetSymbolAddress((void**)&h_lo,     g_h_lo);
    cudaGetSymbolAddress((void**)&attn_hi,  g_attn_hi);
    cudaGetSymbolAddress((void**)&attn_lo,  g_attn_lo);
    cudaGetSymbolAddress((void**)&hh_hi,    g_hh_hi);
    cudaGetSymbolAddress((void**)&hh_lo,    g_hh_lo);
    cudaGetSymbolAddress((void**)&ff_hi,    g_ff_hi);
    cudaGetSymbolAddress((void**)&ff_lo,    g_ff_lo);
    cudaGetSymbolAddress((void**)&WqkvT_hi, g_WqkvT_hi);
    cudaGetSymbolAddress((void**)&WqkvT_lo, g_WqkvT_lo);
    cudaGetSymbolAddress((void**)&WoT_hi,   g_WoT_hi);
    cudaGetSymbolAddress((void**)&WoT_lo,   g_WoT_lo);
    cudaGetSymbolAddress((void**)&W1T_hi,   g_W1T_hi);
    cudaGetSymbolAddress((void**)&W1T_lo,   g_W1T_lo);
    cudaGetSymbolAddress((void**)&W2T_hi,   g_W2T_hi);
    cudaGetSymbolAddress((void**)&W2T_lo,   g_W2T_lo);

    cudaFuncSetAttribute(attn_kernel, cudaFuncAttributeMaxDynamicSharedMemorySize, ATTN_SMEM);
    cudaFuncSetAttribute(gemm_tc<0>,  cudaFuncAttributeMaxDynamicSharedMemorySize, GEMM_SMEM);
    cudaFuncSetAttribute(gemm_tc<1>,  cudaFuncAttributeMaxDynamicSharedMemorySize, GEMM_SMEM);
    cudaFuncSetAttribute(gemm_tc<2>,  cudaFuncAttributeMaxDynamicSharedMemorySize, GEMM_SMEM);

    // weight conversion + transpose (K-major for MMA B operand)
    wtrans_kernel<<<dim3(QKVW / 32, DMODEL / 32), dim3(32, 8)>>>(Wqkv, WqkvT_hi, WqkvT_lo, DMODEL, QKVW);
    wtrans_kernel<<<dim3(DMODEL / 32, DMODEL / 32), dim3(32, 8)>>>(Wo, WoT_hi, WoT_lo, DMODEL, DMODEL);
    wtrans_kernel<<<dim3(FFDIM / 32, DMODEL / 32), dim3(32, 8)>>>(W1, W1T_hi, W1T_lo, DMODEL, FFDIM);
    wtrans_kernel<<<dim3(DMODEL / 32, FFDIM / 32), dim3(32, 8)>>>(W2, W2T_hi, W2T_lo, FFDIM, DMODEL);

    // LN1 -> hi/lo
    ln_kernel<<<NTOK, 256>>>(x, g1, b1, h_hi, h_lo);
    // QKV projection (fp32 out for attention)
    gemm_tc<0><<<dim3(QKVW / 128, NTOK / 128), 256, GEMM_SMEM>>>(
        h_hi, h_lo, WqkvT_hi, WqkvT_lo, bqkv, nullptr, qkv, nullptr, nullptr, QKVW, DMODEL);
    // causal attention -> hi/lo
    attn_kernel<<<dim3(SEQ / 64, NH, BATCH), 256, ATTN_SMEM>>>(qkv, attn_hi, attn_lo);
    // output projection + residual -> x2 (fp32)
    gemm_tc<2><<<dim3(DMODEL / 128, NTOK / 128), 256, GEMM_SMEM>>>(
        attn_hi, attn_lo, WoT_hi, WoT_lo, bo, x, x2, nullptr, nullptr, DMODEL, DMODEL);
    // LN2 -> hi/lo
    ln_kernel<<<NTOK, 256>>>(x2, g2, b2, hh_hi, hh_lo);
    // FF1 + GELU -> hi/lo
    gemm_tc<1><<<dim3(FFDIM / 128, NTOK / 128), 256, GEMM_SMEM>>>(
        hh_hi, hh_lo, W1T_hi, W1T_lo, b1f, nullptr, nullptr, ff_hi, ff_lo, FFDIM, DMODEL);
    // FF2 + residual -> out (fp32)
    gemm_tc<2><<<dim3(DMODEL / 128, NTOK / 128), 256, GEMM_SMEM>>>(
        ff_hi, ff_lo, W2T_hi, W2T_lo, b2f, x2, out, nullptr, nullptr, DMODEL, FFDIM);
}

// round 4
// speedup vs baseline: 3.6896x; 1.4045x over previous
#include <cuda_runtime.h>
#include <cuda_bf16.h>
#include <math.h>
#include <stdint.h>

// Problem dims (fixed by the reference)
#define NTOK   4096      // B*T = 2*2048
#define SEQ    2048
#define BATCH  2
#define DMODEL 1024
#define NH     16
#define HDIM   64
#define FFDIM  4096
#define QKVW   3072      // 3*DMODEL

// tcgen05 only exists in the arch-specific (sm_103a / sm_103f) compilation pass.
#if defined(__CUDA_ARCH__) && (__CUDA_ARCH__ == 1030) && \
    (defined(__CUDA_ARCH_FEAT_SM103_ALL) || defined(__CUDA_ARCH_SPECIFIC__) || \
     defined(__CUDA_ARCH_FAMILY_SPECIFIC__))
#define HAS_TCGEN05 1
#else
#define HAS_TCGEN05 0
#endif

#if HAS_TCGEN05
// ======================= PTX helpers (arch-specific pass only) =======================
__device__ __forceinline__ uint32_t smem_to_u32(const void* p) {
    uint32_t a;
    asm("{ .reg .u64 t; cvta.to.shared.u64 t, %1; cvt.u32.u64 %0, t; }" : "=r"(a) : "l"(p));
    return a;
}
__device__ __forceinline__ uint32_t elect_one_pred() {
    uint32_t pred;
    asm volatile("{\n\t.reg .pred p;\n\telect.sync _|p, 0xFFFFFFFF;\n\tselp.b32 %0, 1, 0, p;\n\t}"
                 : "=r"(pred));
    return pred;
}

static constexpr uint64_t SMEM_DESC_BASE_SW128 =
    (uint64_t(2) << 61) | (uint64_t(1) << 46) | (uint64_t(64) << 32) | (uint64_t(1) << 16);
#define MAKE_SMEM_DESC(base_addr) \
    (SMEM_DESC_BASE_SW128 | ((uint64_t)((base_addr) >> 4) & 0x3FFF))

#define TCGEN05_ALLOC(sa, n) \
    asm volatile("tcgen05.alloc.cta_group::1.sync.aligned.shared::cta.b32 [%0], %1;" \
                 :: "r"((uint32_t)(sa)), "r"((uint32_t)(n)) : "memory")
#define TCGEN05_DEALLOC(t, n) \
    asm volatile("tcgen05.dealloc.cta_group::1.sync.aligned.b32 %0, %1;" :: "r"(t), "r"((uint32_t)(n)))
#define TCGEN05_RELINQUISH() \
    asm volatile("tcgen05.relinquish_alloc_permit.cta_group::1.sync.aligned;")
#define TCGEN05_COMMIT(mb) \
    asm volatile("tcgen05.commit.cta_group::1.mbarrier::arrive::one.shared::cluster.b64 [%0];" \
                 :: "r"((uint32_t)(mb)) : "memory")
#define TCGEN05_FENCE_AFTER() asm volatile("tcgen05.fence::after_thread_sync;" ::: "memory")
#define TCGEN05_WAIT_LD() asm volatile("tcgen05.wait::ld.sync.aligned;" ::: "memory")
#define FENCE_PROXY_ASYNC() asm volatile("fence.proxy.async.shared::cta;" ::: "memory")

#define MBARRIER_INIT(mb, cnt) \
    asm volatile("mbarrier.init.shared.b64 [%0], %1;" :: "r"((uint32_t)(mb)), "r"((uint32_t)(cnt)) : "memory")

#define MBARRIER_WAIT_PARITY(mb, par) do { \
    uint32_t _mb = (uint32_t)(mb), _p = (uint32_t)(par), _d; \
    asm volatile("{\n\t.reg .pred p;\n\t" \
        "mbarrier.try_wait.parity.acquire.cta.shared::cta.b64 p, [%1], %2;\n\t" \
        "selp.b32 %0, 1, 0, p;\n\t}" : "=r"(_d) : "r"(_mb), "r"(_p) : "memory"); \
    if (!_d) { \
        asm volatile("{\n\t.reg .pred P1;\n\t" \
            "WL_%=:\n\t" \
            "mbarrier.try_wait.parity.acquire.cta.shared::cta.b64 P1, [%0], %1, 0x989680;\n\t" \
            "@P1 bra.uni WD_%=;\n\t" \
            "bra.uni WL_%=;\n\t" \
            "WD_%=:\n\t}" :: "r"(_mb), "r"(_p) : "memory"); \
    } \
} while (0)

#define TCGEN05_LD_X32(r, ta) \
    asm volatile("tcgen05.ld.sync.aligned.32x32b.x32.b32 " \
        "{%0, %1, %2, %3, %4, %5, %6, %7, %8, %9, %10, %11, %12, %13, %14, %15, " \
        "%16, %17, %18, %19, %20, %21, %22, %23, %24, %25, %26, %27, %28, %29, %30, %31}, [%32];" \
        : "=r"((r)[0]), "=r"((r)[1]), "=r"((r)[2]), "=r"((r)[3]), \
          "=r"((r)[4]), "=r"((r)[5]), "=r"((r)[6]), "=r"((r)[7]), \
          "=r"((r)[8]), "=r"((r)[9]), "=r"((r)[10]), "=r"((r)[11]), \
          "=r"((r)[12]), "=r"((r)[13]), "=r"((r)[14]), "=r"((r)[15]), \
          "=r"((r)[16]), "=r"((r)[17]), "=r"((r)[18]), "=r"((r)[19]), \
          "=r"((r)[20]), "=r"((r)[21]), "=r"((r)[22]), "=r"((r)[23]), \
          "=r"((r)[24]), "=r"((r)[25]), "=r"((r)[26]), "=r"((r)[27]), \
          "=r"((r)[28]), "=r"((r)[29]), "=r"((r)[30]), "=r"((r)[31]) \
        : "r"(ta))

// cg1 kind::f16 SS-mode MMA (A and B both in SMEM, bf16 in / fp32 accum)
__device__ __forceinline__ void mma_f16_ss(uint32_t d, uint64_t ad, uint64_t bd,
                                           uint32_t idesc, bool acc) {
    uint32_t en = acc ? 1u : 0u;
    asm volatile(
        "{\n\t.reg .pred p;\n\tsetp.ne.u32 p, %5, 0;\n\t"
        "tcgen05.mma.cta_group::1.kind::f16 [%0], %1, %2, %3, {%4, %4, %4, %4}, p;\n\t}"
        :: "r"(d), "l"(ad), "l"(bd), "r"(idesc), "r"(0u), "r"(en) : "memory");
}

// idesc: fp32 accum, bf16 A/B, M=128, N=128, K-major both
static constexpr uint32_t GEMM_IDESC =
    (1u << 4) | (1u << 7) | (1u << 10) | ((128u / 8u) << 17) | ((128u / 16u) << 24);
// idesc for attention MMAs: M=128, N=64
static constexpr uint32_t ATTN_IDESC =
    (1u << 4) | (1u << 7) | (1u << 10) | ((64u / 8u) << 17) | ((128u / 16u) << 24);
#endif  // HAS_TCGEN05

#define SMEM_SWIZZLE_128B(off) ((off) ^ (((off) >> 3) & 0x70))

// ======================= scratch (device globals) =======================
__device__ float g_x2  [NTOK * DMODEL];          // residual after attn proj
__device__ __nv_bfloat16 g_qkv_hi[NTOK * QKVW],  g_qkv_lo[NTOK * QKVW];
__device__ __nv_bfloat16 g_h_hi  [NTOK * DMODEL], g_h_lo  [NTOK * DMODEL];
__device__ __nv_bfloat16 g_attn_hi[NTOK * DMODEL], g_attn_lo[NTOK * DMODEL];
__device__ __nv_bfloat16 g_hh_hi [NTOK * DMODEL], g_hh_lo [NTOK * DMODEL];
__device__ __nv_bfloat16 g_ff_hi [NTOK * FFDIM],  g_ff_lo [NTOK * FFDIM];
__device__ __nv_bfloat16 g_WqkvT_hi[QKVW * DMODEL],  g_WqkvT_lo[QKVW * DMODEL];
__device__ __nv_bfloat16 g_WoT_hi [DMODEL * DMODEL], g_WoT_lo [DMODEL * DMODEL];
__device__ __nv_bfloat16 g_W1T_hi [FFDIM * DMODEL],  g_W1T_lo [FFDIM * DMODEL];
__device__ __nv_bfloat16 g_W2T_hi [DMODEL * FFDIM],  g_W2T_lo [DMODEL * FFDIM];

__device__ __forceinline__ void split_store(__nv_bfloat16* hi, __nv_bfloat16* lo,
                                            long ofs, float v) {
    __nv_bfloat16 h = __float2bfloat16(v);
    hi[ofs] = h;
    lo[ofs] = __float2bfloat16(v - __bfloat162float(h));
}

__device__ __forceinline__ float gelu_exact(float x) {
    return 0.5f * x * (1.0f + erff(x * 0.70710678118654752f));
}

// ======================= LayerNorm -> bf16 hi/lo planes =======================
__global__ __launch_bounds__(256) void ln_kernel(const float* __restrict__ x,
                                                 const float* __restrict__ g,
                                                 const float* __restrict__ b,
                                                 __nv_bfloat16* __restrict__ yhi,
                                                 __nv_bfloat16* __restrict__ ylo)
{
    const int row = blockIdx.x;
    const int tid = threadIdx.x;
    const float* xr = x + (long)row * DMODEL;
    float4 v = *(const float4*)(xr + tid * 4);

    float s  = v.x + v.y + v.z + v.w;
    float sq = v.x*v.x + v.y*v.y + v.z*v.z + v.w*v.w;
    #pragma unroll
    for (int off = 16; off > 0; off >>= 1) {
        s  += __shfl_xor_sync(0xffffffffu, s,  off);
        sq += __shfl_xor_sync(0xffffffffu, sq, off);
    }
    __shared__ float reds[8], redq[8];
    const int wid = tid >> 5;
    if ((tid & 31) == 0) { reds[wid] = s; redq[wid] = sq; }
    __syncthreads();
    float st = 0.f, qt = 0.f;
    #pragma unroll
    for (int w = 0; w < 8; w++) { st += reds[w]; qt += redq[w]; }

    const float mu   = st * (1.0f / DMODEL);
    const float var  = qt * (1.0f / DMODEL) - mu * mu;
    const float rstd = rsqrtf(var + 1e-5f);

    float4 gv = *(const float4*)(g + tid * 4);
    float4 bv = *(const float4*)(b + tid * 4);
    float o0 = (v.x - mu) * rstd * gv.x + bv.x;
    float o1 = (v.y - mu) * rstd * gv.y + bv.y;
    float o2 = (v.z - mu) * rstd * gv.z + bv.z;
    float o3 = (v.w - mu) * rstd * gv.w + bv.w;
    const long base = (long)row * DMODEL + tid * 4;
    split_store(yhi, ylo, base + 0, o0);
    split_store(yhi, ylo, base + 1, o1);
    split_store(yhi, ylo, base + 2, o2);
    split_store(yhi, ylo, base + 3, o3);
}

// ============== weight transpose + bf16 hi/lo: W[K,N] -> T[N,K] ==============
__global__ __launch_bounds__(256) void wtrans_kernel(const float* __restrict__ W,
                                                     __nv_bfloat16* __restrict__ Thi,
                                                     __nv_bfloat16* __restrict__ Tlo,
                                                     int K, int N)
{
    __shared__ float tile[32][33];
    const int nb = blockIdx.x * 32;
    const int kb = blockIdx.y * 32;
    const int tx = threadIdx.x;       // 0..31
    const int ty = threadIdx.y;       // 0..7
    #pragma unroll
    for (int i = ty; i < 32; i += 8)
        tile[i][tx] = W[(long)(kb + i) * N + nb + tx];
    __syncthreads();
    #pragma unroll
    for (int i = ty; i < 32; i += 8) {
        float v = tile[tx][i];        // = W[kb+tx][nb+i]
        const long ofs = (long)(nb + i) * K + kb + tx;
        __nv_bfloat16 h = __float2bfloat16(v);
        Thi[ofs] = h;
        Tlo[ofs] = __float2bfloat16(v - __bfloat162float(h));
    }
}

// ======================= GEMM =======================
// C[M,N] = A[M,K] @ B[N,K]^T with A,B given as bf16 hi/lo planes (K-major).
// OP: 0 = +bias -> fp32 ; 1 = +bias, GELU -> bf16 hi/lo ; 2 = +bias +res -> fp32 ;
//     3 = +bias -> bf16 hi/lo
#define SM_TMEMPTR 0
#define SM_MBAR    16          // two mbarriers at 16, 24
#define SM_TILES   1024
#define TILE_B     16384       // 128 rows x 128 bytes (64 bf16)
#define STAGE_B    (4 * TILE_B)
#define GEMM_SMEM  (SM_TILES + 2 * STAGE_B)

template<int OP>
__global__ __launch_bounds__(256, 1) void gemm_tc(
    const __nv_bfloat16* __restrict__ Ahi, const __nv_bfloat16* __restrict__ Alo,
    const __nv_bfloat16* __restrict__ Bhi, const __nv_bfloat16* __restrict__ Blo,
    const float* __restrict__ bias, const float* __restrict__ res,
    float* __restrict__ Cf,
    __nv_bfloat16* __restrict__ Chi, __nv_bfloat16* __restrict__ Clo,
    int N, int K)
{
    extern __shared__ __align__(1024) char smem[];
    const int tid = threadIdx.x;
    const int mBase = blockIdx.y * 128;
    const int nBase = blockIdx.x * 128;

#if HAS_TCGEN05
    const uint32_t smem_base = smem_to_u32(smem);
    const int wid = tid >> 5;
    const int lid = tid & 31;

    if (wid == 0) {
        TCGEN05_ALLOC(smem_base + SM_TMEMPTR, 128);
        TCGEN05_RELINQUISH();
    }
    if (tid == 0) {
        MBARRIER_INIT(smem_base + SM_MBAR + 0, 1);
        MBARRIER_INIT(smem_base + SM_MBAR + 8, 1);
    }
    __syncthreads();
    uint32_t tmem;
    asm volatile("ld.shared.b32 %0, [%1];" : "=r"(tmem) : "r"(smem_base + SM_TMEMPTR));

    const int NC = K >> 6;   // K-chunks of 64
    for (int c = 0; c < NC; c++) {
        const int s = c & 1;
        if (c >= 2)
            MBARRIER_WAIT_PARITY(smem_base + SM_MBAR + s * 8, ((c >> 1) - 1) & 1);

        const int k0 = c << 6;
        const __nv_bfloat16* src0 = Ahi + (long)mBase * K + k0;
        const __nv_bfloat16* src1 = Alo + (long)mBase * K + k0;
        const __nv_bfloat16* src2 = Bhi + (long)nBase * K + k0;
        const __nv_bfloat16* src3 = Blo + (long)nBase * K + k0;
        const int stage_off = SM_TILES + s * STAGE_B;
        #pragma unroll
        for (int i = 0; i < 4; i++) {
            const int idx = tid + i * 256;      // 0..1023
            const int r   = idx >> 3;
            const int c16 = idx & 7;
            const long gofs = (long)r * K + (c16 << 3);
            const int  sofs = stage_off + SMEM_SWIZZLE_128B((r << 7) | (c16 << 4));
            *(uint4*)(smem + sofs + 0 * TILE_B) = *(const uint4*)(src0 + gofs);
            *(uint4*)(smem + sofs + 1 * TILE_B) = *(const uint4*)(src1 + gofs);
            *(uint4*)(smem + sofs + 2 * TILE_B) = *(const uint4*)(src2 + gofs);
            *(uint4*)(smem + sofs + 3 * TILE_B) = *(const uint4*)(src3 + gofs);
        }
        FENCE_PROXY_ASYNC();
        __syncthreads();

        if (wid == 0) {
            const uint32_t st = smem_base + stage_off;
            const uint64_t dAhi = MAKE_SMEM_DESC(st + 0 * TILE_B);
            const uint64_t dAlo = MAKE_SMEM_DESC(st + 1 * TILE_B);
            const uint64_t dBhi = MAKE_SMEM_DESC(st + 2 * TILE_B);
            const uint64_t dBlo = MAKE_SMEM_DESC(st + 3 * TILE_B);
            if (elect_one_pred()) {
                #pragma unroll
                for (int kk = 0; kk < 4; kk++) {
                    mma_f16_ss(tmem, dAhi + kk * 2, dBhi + kk * 2, GEMM_IDESC,
                               !(c == 0 && kk == 0));
                    mma_f16_ss(tmem, dAlo + kk * 2, dBhi + kk * 2, GEMM_IDESC, true);
                    mma_f16_ss(tmem, dAhi + kk * 2, dBlo + kk * 2, GEMM_IDESC, true);
                }
                TCGEN05_COMMIT(smem_base + SM_MBAR + s * 8);
            }
        }
    }

    // wait for ALL MMAs (last commit covers all prior)
    {
        const int s_last = (NC - 1) & 1;
        const int nlast  = ((NC - 1 - s_last) >> 1) + 1;
        MBARRIER_WAIT_PARITY(smem_base + SM_MBAR + s_last * 8, (nlast - 1) & 1);
    }
    TCGEN05_FENCE_AFTER();

    // Epilogue: TMEM -> SMEM (row-stage) -> coalesced global
    float* sout = (float*)(smem + SM_TILES);
    if (wid < 4) {
        const int r = (wid << 5) + lid;
        #pragma unroll
        for (int cb = 0; cb < 4; cb++) {
            uint32_t regs[32];
            TCGEN05_LD_X32(regs, tmem + (cb << 5));
            TCGEN05_WAIT_LD();
            #pragma unroll
            for (int j = 0; j < 32; j += 4) {
                float4 v = make_float4(__uint_as_float(regs[j]),
                                       __uint_as_float(regs[j + 1]),
                                       __uint_as_float(regs[j + 2]),
                                       __uint_as_float(regs[j + 3]));
                *(float4*)&sout[r * 132 + (cb << 5) + j] = v;
            }
        }
    }
    __syncthreads();
    if (wid == 0) TCGEN05_DEALLOC(tmem, 128);

    for (int idx = tid; idx < 128 * 32; idx += 256) {
        const int r = idx >> 5;
        const int cc = (idx & 31) << 2;
        float4 v = *(float4*)&sout[r * 132 + cc];
        const long gr = mBase + r;
        const int  gc = nBase + cc;
        float4 bb = *(const float4*)&bias[gc];
        v.x += bb.x; v.y += bb.y; v.z += bb.z; v.w += bb.w;
        if (OP == 1 || OP == 3) {
            if (OP == 1) {
                v.x = gelu_exact(v.x); v.y = gelu_exact(v.y);
                v.z = gelu_exact(v.z); v.w = gelu_exact(v.w);
            }
            const long o = gr * N + gc;
            split_store(Chi, Clo, o + 0, v.x);
            split_store(Chi, Clo, o + 1, v.y);
            split_store(Chi, Clo, o + 2, v.z);
            split_store(Chi, Clo, o + 3, v.w);
        } else if (OP == 2) {
            float4 rr = *(const float4*)&res[gr * N + gc];
            v.x += rr.x; v.y += rr.y; v.z += rr.z; v.w += rr.w;
            *(float4*)&Cf[gr * N + gc] = v;
        } else {
            *(float4*)&Cf[gr * N + gc] = v;
        }
    }

#else  // =================== FFMA fallback (non-103a passes) ===================
    float* As = (float*)smem;                 // [8][128]
    float* Bs = As + 8 * 128;                 // [8][128]

    const int tx = tid & 15;
    const int ty = tid >> 4;
    const int row  = tid >> 1;                // 0..127
    const int kc   = (tid & 1) << 2;          // 0 or 4

    float acc[8][8];
    #pragma unroll
    for (int i = 0; i < 8; i++)
        #pragma unroll
        for (int j = 0; j < 8; j++) acc[i][j] = 0.f;

    for (int k0 = 0; k0 < K; k0 += 8) {
        {
            const long o = (long)(mBase + row) * K + k0 + kc;
            ushort4 h = *(const ushort4*)(Ahi + o);
            ushort4 l = *(const ushort4*)(Alo + o);
            As[(kc + 0) * 128 + row] = __bfloat162float(*(__nv_bfloat16*)&h.x) + __bfloat162float(*(__nv_bfloat16*)&l.x);
            As[(kc + 1) * 128 + row] = __bfloat162float(*(__nv_bfloat16*)&h.y) + __bfloat162float(*(__nv_bfloat16*)&l.y);
            As[(kc + 2) * 128 + row] = __bfloat162float(*(__nv_bfloat16*)&h.z) + __bfloat162float(*(__nv_bfloat16*)&l.z);
            As[(kc + 3) * 128 + row] = __bfloat162float(*(__nv_bfloat16*)&h.w) + __bfloat162float(*(__nv_bfloat16*)&l.w);
        }
        {
            const long o = (long)(nBase + row) * K + k0 + kc;
            ushort4 h = *(const ushort4*)(Bhi + o);
            ushort4 l = *(const ushort4*)(Blo + o);
            Bs[(kc + 0) * 128 + row] = __bfloat162float(*(__nv_bfloat16*)&h.x) + __bfloat162float(*(__nv_bfloat16*)&l.x);
            Bs[(kc + 1) * 128 + row] = __bfloat162float(*(__nv_bfloat16*)&h.y) + __bfloat162float(*(__nv_bfloat16*)&l.y);
            Bs[(kc + 2) * 128 + row] = __bfloat162float(*(__nv_bfloat16*)&h.z) + __bfloat162float(*(__nv_bfloat16*)&l.z);
            Bs[(kc + 3) * 128 + row] = __bfloat162float(*(__nv_bfloat16*)&h.w) + __bfloat162float(*(__nv_bfloat16*)&l.w);
        }
        __syncthreads();

        #pragma unroll
        for (int k = 0; k < 8; k++) {
            float a[8], bb[8];
            #pragma unroll
            for (int i = 0; i < 8; i++) a[i]  = As[k * 128 + ty * 8 + i];
            #pragma unroll
            for (int j = 0; j < 8; j++) bb[j] = Bs[k * 128 + tx * 8 + j];
            #pragma unroll
            for (int i = 0; i < 8; i++)
                #pragma unroll
                for (int j = 0; j < 8; j++)
                    acc[i][j] = fmaf(a[i], bb[j], acc[i][j]);
        }
        __syncthreads();
    }

    #pragma unroll
    for (int i = 0; i < 8; i++) {
        const long gr = mBase + ty * 8 + i;
        #pragma unroll
        for (int j = 0; j < 8; j++) {
            const int gc = nBase + tx * 8 + j;
            float v = acc[i][j] + bias[gc];
            if (OP == 1) {
                v = gelu_exact(v);
                split_store(Chi, Clo, gr * N + gc, v);
            } else if (OP == 3) {
                split_store(Chi, Clo, gr * N + gc, v);
            } else if (OP == 2) {
                Cf[gr * N + gc] = v + res[gr * N + gc];
            } else {
                Cf[gr * N + gc] = v;
            }
        }
    }
#endif
}

// ======================= tcgen05 causal flash attention =======================
// CTA = (128 q rows, head, batch). S = Q K^T via 3 hi/lo MMAs -> TMEM;
// softmax in registers (TMEM lane r == row r, full row per lane);
// P hi/lo -> SMEM; O_part = P V via 3 MMAs -> TMEM; O accumulated in registers.
#define A_TMEMPTR 0
#define A_MBAR0   8
#define A_MBAR1   16
#define A_QHI     1024
#define A_QLO     (A_QHI  + 16384)
#define A_KHI     (A_QLO  + 16384)
#define A_KLO     (A_KHI  + 8192)
#define A_VTHI    (A_KLO  + 8192)
#define A_VTLO    (A_VTHI + 8192)
#define A_PHI     (A_VTLO + 8192)
#define A_PLO     (A_PHI  + 16384)
#define ATTN_SMEM (A_PLO + 16384)

__global__ __launch_bounds__(256, 1) void attn_tc(
    const __nv_bfloat16* __restrict__ qkv_hi,
    const __nv_bfloat16* __restrict__ qkv_lo,
    __nv_bfloat16* __restrict__ ohi,
    __nv_bfloat16* __restrict__ olo)
{
    extern __shared__ __align__(1024) char smem[];
    const int tid  = threadIdx.x;
    const int wid  = tid >> 5;
    const int lid  = tid & 31;
    const int qt   = blockIdx.x;     // 0..15 (128 rows each)
    const int head = blockIdx.y;
    const int bat  = blockIdx.z;
    const long tok0 = (long)bat * SEQ;

#if HAS_TCGEN05
    const uint32_t sb = smem_to_u32(smem);
    if (wid == 0) {
        TCGEN05_ALLOC(sb + A_TMEMPTR, 128);
        TCGEN05_RELINQUISH();
    }
    if (tid == 0) {
        MBARRIER_INIT(sb + A_MBAR0, 1);
        MBARRIER_INIT(sb + A_MBAR1, 1);
    }
    __syncthreads();
    uint32_t tmem;
    asm volatile("ld.shared.b32 %0, [%1];" : "=r"(tmem) : "r"(sb + A_TMEMPTR));

    // load Q tile: 128 rows x 64 bf16 per plane (chunks of 8 bf16 = 16B)
    #pragma unroll
    for (int i = 0; i < 4; i++) {
        const int idx = tid + i * 256;        // 0..1023
        const int r = idx >> 3, c8 = idx & 7;
        const long g = (tok0 + qt * 128 + r) * (long)QKVW + head * 64 + (c8 << 3);
        const int sofs = SMEM_SWIZZLE_128B((r << 7) | (c8 << 4));
        *(uint4*)(smem + A_QHI + sofs) = *(const uint4*)(qkv_hi + g);
        *(uint4*)(smem + A_QLO + sofs) = *(const uint4*)(qkv_lo + g);
    }

    float o[64];
    #pragma unroll
    for (int j = 0; j < 64; j++) o[j] = 0.f;
    float m = -1e30f, l = 0.f;
    const int grow = qt * 128 + (wid << 5) + lid;   // global query row (wid<4)
    const int nkt = 2 * qt + 2;

    for (int kt = 0; kt < nkt; kt++) {
        __syncthreads();   // prior PV MMA complete & P consumed -> safe to overwrite K/Vt

        // load K tile (64x64, K-major over hd)
        #pragma unroll
        for (int i = 0; i < 2; i++) {
            const int idx = tid + i * 256;    // 0..511
            const int r = idx >> 3, c8 = idx & 7;
            const long g = (tok0 + kt * 64 + r) * (long)QKVW + 1024 + head * 64 + (c8 << 3);
            const int sofs = SMEM_SWIZZLE_128B((r << 7) | (c8 << 4));
            *(uint4*)(smem + A_KHI + sofs) = *(const uint4*)(qkv_hi + g);
            *(uint4*)(smem + A_KLO + sofs) = *(const uint4*)(qkv_lo + g);
        }
        // load V tile transposed: Vt[hd][kt]
        #pragma unroll
        for (int i = 0; i < 2; i++) {
            const int idx = tid + i * 256;
            const int r = idx >> 3, c8 = idx & 7;  // key r, hd cols c8*8..+7
            const long g = (tok0 + kt * 64 + r) * (long)QKVW + 2048 + head * 64 + (c8 << 3);
            uint4 vh = *(const uint4*)(qkv_hi + g);
            uint4 vl = *(const uint4*)(qkv_lo + g);
            const __nv_bfloat16* ph = (const __nv_bfloat16*)&vh;
            const __nv_bfloat16* pl = (const __nv_bfloat16*)&vl;
            #pragma unroll
            for (int j = 0; j < 8; j++) {
                const int col = (c8 << 3) + j;   // hd index -> Vt row
                const int so = SMEM_SWIZZLE_128B((col << 7) | (r << 1));
                *(__nv_bfloat16*)(smem + A_VTHI + so) = ph[j];
                *(__nv_bfloat16*)(smem + A_VTLO + so) = pl[j];
            }
        }
        FENCE_PROXY_ASYNC();
        __syncthreads();

        // QK^T -> S (TMEM cols 0..63)
        if (wid == 0) {
            const uint64_t dQh = MAKE_SMEM_DESC(sb + A_QHI);
            const uint64_t dQl = MAKE_SMEM_DESC(sb + A_QLO);
            const uint64_t dKh = MAKE_SMEM_DESC(sb + A_KHI);
            const uint64_t dKl = MAKE_SMEM_DESC(sb + A_KLO);
            if (elect_one_pred()) {
                #pragma unroll
                for (int kk = 0; kk < 4; kk++) {
                    mma_f16_ss(tmem, dQh + kk * 2, dKh + kk * 2, ATTN_IDESC, kk != 0);
                    mma_f16_ss(tmem, dQl + kk * 2, dKh + kk * 2, ATTN_IDESC, true);
                    mma_f16_ss(tmem, dQh + kk * 2, dKl + kk * 2, ATTN_IDESC, true);
                }
                TCGEN05_COMMIT(sb + A_MBAR0);
            }
        }

        float sc = 1.f;
        if (wid < 4) {
            MBARRIER_WAIT_PARITY(sb + A_MBAR0, kt & 1);
            TCGEN05_FENCE_AFTER();
            uint32_t r0[32], r1[32];
            TCGEN05_LD_X32(r0, tmem + 0);
            TCGEN05_LD_X32(r1, tmem + 32);
            TCGEN05_WAIT_LD();
            float s[64];
            #pragma unroll
            for (int j = 0; j < 32; j++) s[j]      = __uint_as_float(r0[j]) * 0.125f;
            #pragma unroll
            for (int j = 0; j < 32; j++) s[32 + j] = __uint_as_float(r1[j]) * 0.125f;

            if (kt >= 2 * qt) {                 // diagonal tiles need causal mask
                const int jbase = kt * 64;
                #pragma unroll
                for (int j = 0; j < 64; j++)
                    if (jbase + j > grow) s[j] = -1e30f;
            }
            float mx = -1e30f;
            #pragma unroll
            for (int j = 0; j < 64; j++) mx = fmaxf(mx, s[j]);
            const float mnew = fmaxf(m, mx);
            sc = __expf(m - mnew);
            float ls = 0.f;
            #pragma unroll
            for (int j = 0; j < 64; j++) { s[j] = __expf(s[j] - mnew); ls += s[j]; }
            l = l * sc + ls;
            m = mnew;

            // store P hi/lo to SMEM (row = this lane's row)
            const int r = (wid << 5) + lid;
            #pragma unroll
            for (int j8 = 0; j8 < 8; j8++) {
                __align__(16) __nv_bfloat16 hb[8], lb[8];
                #pragma unroll
                for (int j = 0; j < 8; j++) {
                    const float v = s[(j8 << 3) + j];
                    const __nv_bfloat16 h = __float2bfloat16(v);
                    hb[j] = h;
                    lb[j] = __float2bfloat16(v - __bfloat162float(h));
                }
                const int so = SMEM_SWIZZLE_128B((r << 7) | (j8 << 4));
                *(uint4*)(smem + A_PHI + so) = *(uint4*)hb;
                *(uint4*)(smem + A_PLO + so) = *(uint4*)lb;
            }
            FENCE_PROXY_ASYNC();
        }
        __syncthreads();

        // P V -> O_part (TMEM cols 64..127), overwrite (first MMA no-acc)
        if (wid == 0) {
            const uint64_t dPh = MAKE_SMEM_DESC(sb + A_PHI);
            const uint64_t dPl = MAKE_SMEM_DESC(sb + A_PLO);
            const uint64_t dVh = MAKE_SMEM_DESC(sb + A_VTHI);
            const uint64_t dVl = MAKE_SMEM_DESC(sb + A_VTLO);
            if (elect_one_pred()) {
                #pragma unroll
                for (int kk = 0; kk < 4; kk++) {
                    mma_f16_ss(tmem + 64, dPh + kk * 2, dVh + kk * 2, ATTN_IDESC, kk != 0);
                    mma_f16_ss(tmem + 64, dPl + kk * 2, dVh + kk * 2, ATTN_IDESC, true);
                    mma_f16_ss(tmem + 64, dPh + kk * 2, dVl + kk * 2, ATTN_IDESC, true);
                }
                TCGEN05_COMMIT(sb + A_MBAR1);
            }
        }
        if (wid < 4) {
            MBARRIER_WAIT_PARITY(sb + A_MBAR1, kt & 1);
            TCGEN05_FENCE_AFTER();
            uint32_t r0[32], r1[32];
            TCGEN05_LD_X32(r0, tmem + 64);
            TCGEN05_LD_X32(r1, tmem + 96);
            TCGEN05_WAIT_LD();
            #pragma unroll
            for (int j = 0; j < 32; j++) o[j]      = o[j]      * sc + __uint_as_float(r0[j]);
            #pragma unroll
            for (int j = 0; j < 32; j++) o[32 + j] = o[32 + j] * sc + __uint_as_float(r1[j]);
        }
    }

    // epilogue: out[b, grow, head*64 + c] = o[c] / l  (bf16 hi/lo)
    if (wid < 4) {
        const float invl = 1.0f / l;
        const long gofs = (tok0 + grow) * (long)DMODEL + head * 64;
        #pragma unroll
        for (int j8 = 0; j8 < 8; j8++) {
            __align__(16) __nv_bfloat16 hb[8], lb[8];
            #pragma unroll
            for (int j = 0; j < 8; j++) {
                const float v = o[(j8 << 3) + j] * invl;
                const __nv_bfloat16 h = __float2bfloat16(v);
                hb[j] = h;
                lb[j] = __float2bfloat16(v - __bfloat162float(h));
            }
            *(uint4*)(ohi + gofs + (j8 << 3)) = *(uint4*)hb;
            *(uint4*)(olo + gofs + (j8 << 3)) = *(uint4*)lb;
        }
    }
    __syncthreads();
    if (wid == 0) TCGEN05_DEALLOC(tmem, 128);

#else  // =================== compile-only FFMA fallback ===================
    if (tid < 128) {
        const int grow2 = qt * 128 + tid;
        const long qofs = (tok0 + grow2) * (long)QKVW + head * 64;
        float q[64], o2[64];
        #pragma unroll
        for (int c = 0; c < 64; c++) {
            q[c] = (__bfloat162float(qkv_hi[qofs + c]) +
                    __bfloat162float(qkv_lo[qofs + c])) * 0.125f;
            o2[c] = 0.f;
        }
        float m2 = -1e30f, l2 = 0.f;
        for (int j = 0; j <= grow2; j++) {
            const long kofs = (tok0 + j) * (long)QKVW + 1024 + head * 64;
            float s = 0.f;
            for (int c = 0; c < 64; c++)
                s += q[c] * (__bfloat162float(qkv_hi[kofs + c]) +
                             __bfloat162float(qkv_lo[kofs + c]));
            const float mnew = fmaxf(m2, s);
            const float scf = expf(m2 - mnew);
            const float p = expf(s - mnew);
            l2 = l2 * scf + p;
            m2 = mnew;
            const long vofs = kofs + 1024;
            for (int c = 0; c < 64; c++)
                o2[c] = o2[c] * scf + p * (__bfloat162float(qkv_hi[vofs + c]) +
                                           __bfloat162float(qkv_lo[vofs + c]));
        }
        const long gofs = (tok0 + grow2) * (long)DMODEL + head * 64;
        for (int c = 0; c < 64; c++)
            split_store(ohi, olo, gofs + c, o2[c] / l2);
    }
#endif
}

// ======================= driver =======================
extern "C" void kernel_launch(void* const* d_in, const int* in_sizes, int n_in,
                              void* d_out, int out_size)
{
    const float* x    = (const float*)d_in[0];
    const float* g1   = (const float*)d_in[1];
    const float* b1   = (const float*)d_in[2];
    const float* Wqkv = (const float*)d_in[3];
    const float* bqkv = (const float*)d_in[4];
    const float* Wo   = (const float*)d_in[5];
    const float* bo   = (const float*)d_in[6];
    const float* g2   = (const float*)d_in[7];
    const float* b2   = (const float*)d_in[8];
    const float* W1   = (const float*)d_in[9];
    const float* b1f  = (const float*)d_in[10];
    const float* W2   = (const float*)d_in[11];
    const float* b2f  = (const float*)d_in[12];
    float* out = (float*)d_out;

    float *x2;
    __nv_bfloat16 *qkv_hi, *qkv_lo;
    __nv_bfloat16 *h_hi, *h_lo, *attn_hi, *attn_lo, *hh_hi, *hh_lo, *ff_hi, *ff_lo;
    __nv_bfloat16 *WqkvT_hi, *WqkvT_lo, *WoT_hi, *WoT_lo, *W1T_hi, *W1T_lo, *W2T_hi, *W2T_lo;
    cudaGetSymbolAddress((void**)&x2,       g_x2);
    cudaGetSymbolAddress((void**)&qkv_hi,   g_qkv_hi);
    cudaGetSymbolAddress((void**)&qkv_lo,   g_qkv_lo);
    cudaGetSymbolAddress((void**)&h_hi,     g_h_hi);
    cudaGetSymbolAddress((void**)&h_lo,     g_h_lo);
    cudaGetSymbolAddress((void**)&attn_hi,  g_attn_hi);
    cudaGetSymbolAddress((void**)&attn_lo,  g_attn_lo);
    cudaGetSymbolAddress((void**)&hh_hi,    g_hh_hi);
    cudaGetSymbolAddress((void**)&hh_lo,    g_hh_lo);
    cudaGetSymbolAddress((void**)&ff_hi,    g_ff_hi);
    cudaGetSymbolAddress((void**)&ff_lo,    g_ff_lo);
    cudaGetSymbolAddress((void**)&WqkvT_hi, g_WqkvT_hi);
    cudaGetSymbolAddress((void**)&WqkvT_lo, g_WqkvT_lo);
    cudaGetSymbolAddress((void**)&WoT_hi,   g_WoT_hi);
    cudaGetSymbolAddress((void**)&WoT_lo,   g_WoT_lo);
    cudaGetSymbolAddress((void**)&W1T_hi,   g_W1T_hi);
    cudaGetSymbolAddress((void**)&W1T_lo,   g_W1T_lo);
    cudaGetSymbolAddress((void**)&W2T_hi,   g_W2T_hi);
    cudaGetSymbolAddress((void**)&W2T_lo,   g_W2T_lo);

    cudaFuncSetAttribute(attn_tc,    cudaFuncAttributeMaxDynamicSharedMemorySize, ATTN_SMEM);
    cudaFuncSetAttribute(gemm_tc<1>, cudaFuncAttributeMaxDynamicSharedMemorySize, GEMM_SMEM);
    cudaFuncSetAttribute(gemm_tc<2>, cudaFuncAttributeMaxDynamicSharedMemorySize, GEMM_SMEM);
    cudaFuncSetAttribute(gemm_tc<3>, cudaFuncAttributeMaxDynamicSharedMemorySize, GEMM_SMEM);

    // weight conversion + transpose (K-major for MMA B operand)
    wtrans_kernel<<<dim3(QKVW / 32, DMODEL / 32), dim3(32, 8)>>>(Wqkv, WqkvT_hi, WqkvT_lo, DMODEL, QKVW);
    wtrans_kernel<<<dim3(DMODEL / 32, DMODEL / 32), dim3(32, 8)>>>(Wo, WoT_hi, WoT_lo, DMODEL, DMODEL);
    wtrans_kernel<<<dim3(FFDIM / 32, DMODEL / 32), dim3(32, 8)>>>(W1, W1T_hi, W1T_lo, DMODEL, FFDIM);
    wtrans_kernel<<<dim3(DMODEL / 32, FFDIM / 32), dim3(32, 8)>>>(W2, W2T_hi, W2T_lo, FFDIM, DMODEL);

    // LN1 -> hi/lo
    ln_kernel<<<NTOK, 256>>>(x, g1, b1, h_hi, h_lo);
    // QKV projection -> bf16 hi/lo (attention input)
    gemm_tc<3><<<dim3(QKVW / 128, NTOK / 128), 256, GEMM_SMEM>>>(
        h_hi, h_lo, WqkvT_hi, WqkvT_lo, bqkv, nullptr, nullptr, qkv_hi, qkv_lo, QKVW, DMODEL);
    // causal attention (tcgen05) -> hi/lo
    attn_tc<<<dim3(SEQ / 128, NH, BATCH), 256, ATTN_SMEM>>>(qkv_hi, qkv_lo, attn_hi, attn_lo);
    // output projection + residual -> x2 (fp32)
    gemm_tc<2><<<dim3(DMODEL / 128, NTOK / 128), 256, GEMM_SMEM>>>(
        attn_hi, attn_lo, WoT_hi, WoT_lo, bo, x, x2, nullptr, nullptr, DMODEL, DMODEL);
    // LN2 -> hi/lo
    ln_kernel<<<NTOK, 256>>>(x2, g2, b2, hh_hi, hh_lo);
    // FF1 + GELU -> hi/lo
    gemm_tc<1><<<dim3(FFDIM / 128, NTOK / 128), 256, GEMM_SMEM>>>(
        hh_hi, hh_lo, W1T_hi, W1T_lo, b1f, nullptr, nullptr, ff_hi, ff_lo, FFDIM, DMODEL);
    // FF2 + residual -> out (fp32)
    gemm_tc<2><<<dim3(DMODEL / 128, NTOK / 128), 256, GEMM_SMEM>>>(
        ff_hi, ff_lo, W2T_hi, W2T_lo, b2f, x2, out, nullptr, nullptr, DMODEL, FFDIM);
}

// round 6
// speedup vs baseline: 4.0951x; 1.1099x over previous
#include <cuda_runtime.h>
#include <cuda_bf16.h>
#include <math.h>
#include <stdint.h>

// Problem dims (fixed by the reference)
#define NTOK   4096      // B*T = 2*2048
#define SEQ    2048
#define BATCH  2
#define DMODEL 1024
#define NH     16
#define HDIM   64
#define FFDIM  4096
#define QKVW   3072      // 3*DMODEL

// tcgen05 only exists in the arch-specific (sm_103a / sm_103f) compilation pass.
#if defined(__CUDA_ARCH__) && (__CUDA_ARCH__ == 1030) && \
    (defined(__CUDA_ARCH_FEAT_SM103_ALL) || defined(__CUDA_ARCH_SPECIFIC__) || \
     defined(__CUDA_ARCH_FAMILY_SPECIFIC__))
#define HAS_TCGEN05 1
#else
#define HAS_TCGEN05 0
#endif

#if HAS_TCGEN05
// ======================= PTX helpers (arch-specific pass only) =======================
__device__ __forceinline__ uint32_t smem_to_u32(const void* p) {
    uint32_t a;
    asm("{ .reg .u64 t; cvta.to.shared.u64 t, %1; cvt.u32.u64 %0, t; }" : "=r"(a) : "l"(p));
    return a;
}
__device__ __forceinline__ uint32_t elect_one_pred() {
    uint32_t pred;
    asm volatile("{\n\t.reg .pred p;\n\telect.sync _|p, 0xFFFFFFFF;\n\tselp.b32 %0, 1, 0, p;\n\t}"
                 : "=r"(pred));
    return pred;
}

static constexpr uint64_t SMEM_DESC_BASE_SW128 =
    (uint64_t(2) << 61) | (uint64_t(1) << 46) | (uint64_t(64) << 32) | (uint64_t(1) << 16);
#define MAKE_SMEM_DESC(base_addr) \
    (SMEM_DESC_BASE_SW128 | ((uint64_t)((base_addr) >> 4) & 0x3FFF))

#define TCGEN05_ALLOC(sa, n) \
    asm volatile("tcgen05.alloc.cta_group::1.sync.aligned.shared::cta.b32 [%0], %1;" \
                 :: "r"((uint32_t)(sa)), "r"((uint32_t)(n)) : "memory")
#define TCGEN05_DEALLOC(t, n) \
    asm volatile("tcgen05.dealloc.cta_group::1.sync.aligned.b32 %0, %1;" :: "r"(t), "r"((uint32_t)(n)))
#define TCGEN05_RELINQUISH() \
    asm volatile("tcgen05.relinquish_alloc_permit.cta_group::1.sync.aligned;")
#define TCGEN05_COMMIT(mb) \
    asm volatile("tcgen05.commit.cta_group::1.mbarrier::arrive::one.shared::cluster.b64 [%0];" \
                 :: "r"((uint32_t)(mb)) : "memory")
#define TCGEN05_FENCE_AFTER() asm volatile("tcgen05.fence::after_thread_sync;" ::: "memory")
#define TCGEN05_WAIT_LD() asm volatile("tcgen05.wait::ld.sync.aligned;" ::: "memory")
#define FENCE_PROXY_ASYNC() asm volatile("fence.proxy.async.shared::cta;" ::: "memory")

#define MBARRIER_INIT(mb, cnt) \
    asm volatile("mbarrier.init.shared.b64 [%0], %1;" :: "r"((uint32_t)(mb)), "r"((uint32_t)(cnt)) : "memory")

#define MBARRIER_WAIT_PARITY(mb, par) do { \
    uint32_t _mb = (uint32_t)(mb), _p = (uint32_t)(par), _d; \
    asm volatile("{\n\t.reg .pred p;\n\t" \
        "mbarrier.try_wait.parity.acquire.cta.shared::cta.b64 p, [%1], %2;\n\t" \
        "selp.b32 %0, 1, 0, p;\n\t}" : "=r"(_d) : "r"(_mb), "r"(_p) : "memory"); \
    if (!_d) { \
        asm volatile("{\n\t.reg .pred P1;\n\t" \
            "WL_%=:\n\t" \
            "mbarrier.try_wait.parity.acquire.cta.shared::cta.b64 P1, [%0], %1, 0x989680;\n\t" \
            "@P1 bra.uni WD_%=;\n\t" \
            "bra.uni WL_%=;\n\t" \
            "WD_%=:\n\t}" :: "r"(_mb), "r"(_p) : "memory"); \
    } \
} while (0)

#define TCGEN05_LD_X32(r, ta) \
    asm volatile("tcgen05.ld.sync.aligned.32x32b.x32.b32 " \
        "{%0, %1, %2, %3, %4, %5, %6, %7, %8, %9, %10, %11, %12, %13, %14, %15, " \
        "%16, %17, %18, %19, %20, %21, %22, %23, %24, %25, %26, %27, %28, %29, %30, %31}, [%32];" \
        : "=r"((r)[0]), "=r"((r)[1]), "=r"((r)[2]), "=r"((r)[3]), \
          "=r"((r)[4]), "=r"((r)[5]), "=r"((r)[6]), "=r"((r)[7]), \
          "=r"((r)[8]), "=r"((r)[9]), "=r"((r)[10]), "=r"((r)[11]), \
          "=r"((r)[12]), "=r"((r)[13]), "=r"((r)[14]), "=r"((r)[15]), \
          "=r"((r)[16]), "=r"((r)[17]), "=r"((r)[18]), "=r"((r)[19]), \
          "=r"((r)[20]), "=r"((r)[21]), "=r"((r)[22]), "=r"((r)[23]), \
          "=r"((r)[24]), "=r"((r)[25]), "=r"((r)[26]), "=r"((r)[27]), \
          "=r"((r)[28]), "=r"((r)[29]), "=r"((r)[30]), "=r"((r)[31]) \
        : "r"(ta))

// cg1 kind::f16 SS-mode MMA (A and B both in SMEM, bf16 in / fp32 accum)
__device__ __forceinline__ void mma_f16_ss(uint32_t d, uint64_t ad, uint64_t bd,
                                           uint32_t idesc, bool acc) {
    uint32_t en = acc ? 1u : 0u;
    asm volatile(
        "{\n\t.reg .pred p;\n\tsetp.ne.u32 p, %5, 0;\n\t"
        "tcgen05.mma.cta_group::1.kind::f16 [%0], %1, %2, %3, {%4, %4, %4, %4}, p;\n\t}"
        :: "r"(d), "l"(ad), "l"(bd), "r"(idesc), "r"(0u), "r"(en) : "memory");
}

// idesc: fp32 accum, bf16 A/B, M=128, N=128, K-major both
static constexpr uint32_t GEMM_IDESC =
    (1u << 4) | (1u << 7) | (1u << 10) | ((128u / 8u) << 17) | ((128u / 16u) << 24);
// idesc for attention PV MMA: M=128, N=64, K-major both (validated in R4)
static constexpr uint32_t ATTN_IDESC =
    (1u << 4) | (1u << 7) | (1u << 10) | ((64u / 8u) << 17) | ((128u / 16u) << 24);
#endif  // HAS_TCGEN05

#define SMEM_SWIZZLE_128B(off) ((off) ^ (((off) >> 3) & 0x70))

// ======================= scratch (device globals) =======================
__device__ float g_x2  [NTOK * DMODEL];          // residual after attn proj
__device__ __nv_bfloat16 g_qkv_hi[NTOK * QKVW],  g_qkv_lo[NTOK * QKVW];
__device__ __nv_bfloat16 g_h_hi  [NTOK * DMODEL], g_h_lo  [NTOK * DMODEL];
__device__ __nv_bfloat16 g_attn_hi[NTOK * DMODEL], g_attn_lo[NTOK * DMODEL];
__device__ __nv_bfloat16 g_hh_hi [NTOK * DMODEL], g_hh_lo [NTOK * DMODEL];
__device__ __nv_bfloat16 g_ff_hi [NTOK * FFDIM],  g_ff_lo [NTOK * FFDIM];
__device__ __nv_bfloat16 g_WqkvT_hi[QKVW * DMODEL],  g_WqkvT_lo[QKVW * DMODEL];
__device__ __nv_bfloat16 g_WoT_hi [DMODEL * DMODEL], g_WoT_lo [DMODEL * DMODEL];
__device__ __nv_bfloat16 g_W1T_hi [FFDIM * DMODEL],  g_W1T_lo [FFDIM * DMODEL];
__device__ __nv_bfloat16 g_W2T_hi [DMODEL * FFDIM],  g_W2T_lo [DMODEL * FFDIM];

__device__ __forceinline__ void split_store(__nv_bfloat16* hi, __nv_bfloat16* lo,
                                            long ofs, float v) {
    __nv_bfloat16 h = __float2bfloat16(v);
    hi[ofs] = h;
    lo[ofs] = __float2bfloat16(v - __bfloat162float(h));
}

__device__ __forceinline__ float gelu_exact(float x) {
    return 0.5f * x * (1.0f + erff(x * 0.70710678118654752f));
}

// ======================= LayerNorm -> bf16 hi/lo planes =======================
__global__ __launch_bounds__(256) void ln_kernel(const float* __restrict__ x,
                                                 const float* __restrict__ g,
                                                 const float* __restrict__ b,
                                                 __nv_bfloat16* __restrict__ yhi,
                                                 __nv_bfloat16* __restrict__ ylo)
{
    const int row = blockIdx.x;
    const int tid = threadIdx.x;
    const float* xr = x + (long)row * DMODEL;
    float4 v = *(const float4*)(xr + tid * 4);

    float s  = v.x + v.y + v.z + v.w;
    float sq = v.x*v.x + v.y*v.y + v.z*v.z + v.w*v.w;
    #pragma unroll
    for (int off = 16; off > 0; off >>= 1) {
        s  += __shfl_xor_sync(0xffffffffu, s,  off);
        sq += __shfl_xor_sync(0xffffffffu, sq, off);
    }
    __shared__ float reds[8], redq[8];
    const int wid = tid >> 5;
    if ((tid & 31) == 0) { reds[wid] = s; redq[wid] = sq; }
    __syncthreads();
    float st = 0.f, qt = 0.f;
    #pragma unroll
    for (int w = 0; w < 8; w++) { st += reds[w]; qt += redq[w]; }

    const float mu   = st * (1.0f / DMODEL);
    const float var  = qt * (1.0f / DMODEL) - mu * mu;
    const float rstd = rsqrtf(var + 1e-5f);

    float4 gv = *(const float4*)(g + tid * 4);
    float4 bv = *(const float4*)(b + tid * 4);
    float o0 = (v.x - mu) * rstd * gv.x + bv.x;
    float o1 = (v.y - mu) * rstd * gv.y + bv.y;
    float o2 = (v.z - mu) * rstd * gv.z + bv.z;
    float o3 = (v.w - mu) * rstd * gv.w + bv.w;
    const long base = (long)row * DMODEL + tid * 4;
    split_store(yhi, ylo, base + 0, o0);
    split_store(yhi, ylo, base + 1, o1);
    split_store(yhi, ylo, base + 2, o2);
    split_store(yhi, ylo, base + 3, o3);
}

// ============== weight transpose + bf16 hi/lo: W[K,N] -> T[N,K] ==============
__global__ __launch_bounds__(256) void wtrans_kernel(const float* __restrict__ W,
                                                     __nv_bfloat16* __restrict__ Thi,
                                                     __nv_bfloat16* __restrict__ Tlo,
                                                     int K, int N)
{
    __shared__ float tile[32][33];
    const int nb = blockIdx.x * 32;
    const int kb = blockIdx.y * 32;
    const int tx = threadIdx.x;       // 0..31
    const int ty = threadIdx.y;       // 0..7
    #pragma unroll
    for (int i = ty; i < 32; i += 8)
        tile[i][tx] = W[(long)(kb + i) * N + nb + tx];
    __syncthreads();
    #pragma unroll
    for (int i = ty; i < 32; i += 8) {
        float v = tile[tx][i];        // = W[kb+tx][nb+i]
        const long ofs = (long)(nb + i) * K + kb + tx;
        __nv_bfloat16 h = __float2bfloat16(v);
        Thi[ofs] = h;
        Tlo[ofs] = __float2bfloat16(v - __bfloat162float(h));
    }
}

// ======================= GEMM =======================
// C[M,N] = A[M,K] @ B[N,K]^T with A,B given as bf16 hi/lo planes (K-major).
// OP: 0 = +bias -> fp32 ; 1 = +bias, GELU -> bf16 hi/lo ; 2 = +bias +res -> fp32 ;
//     3 = +bias -> bf16 hi/lo
#define SM_TMEMPTR 0
#define SM_MBAR    16          // two mbarriers at 16, 24
#define SM_TILES   1024
#define TILE_B     16384       // 128 rows x 128 bytes (64 bf16)
#define STAGE_B    (4 * TILE_B)
#define GEMM_SMEM  (SM_TILES + 2 * STAGE_B)

template<int OP>
__global__ __launch_bounds__(256, 1) void gemm_tc(
    const __nv_bfloat16* __restrict__ Ahi, const __nv_bfloat16* __restrict__ Alo,
    const __nv_bfloat16* __restrict__ Bhi, const __nv_bfloat16* __restrict__ Blo,
    const float* __restrict__ bias, const float* __restrict__ res,
    float* __restrict__ Cf,
    __nv_bfloat16* __restrict__ Chi, __nv_bfloat16* __restrict__ Clo,
    int N, int K)
{
    extern __shared__ __align__(1024) char smem[];
    const int tid = threadIdx.x;
    const int mBase = blockIdx.y * 128;
    const int nBase = blockIdx.x * 128;

#if HAS_TCGEN05
    const uint32_t smem_base = smem_to_u32(smem);
    const int wid = tid >> 5;
    const int lid = tid & 31;

    if (wid == 0) {
        TCGEN05_ALLOC(smem_base + SM_TMEMPTR, 128);
        TCGEN05_RELINQUISH();
    }
    if (tid == 0) {
        MBARRIER_INIT(smem_base + SM_MBAR + 0, 1);
        MBARRIER_INIT(smem_base + SM_MBAR + 8, 1);
    }
    __syncthreads();
    uint32_t tmem;
    asm volatile("ld.shared.b32 %0, [%1];" : "=r"(tmem) : "r"(smem_base + SM_TMEMPTR));

    const int NC = K >> 6;   // K-chunks of 64
    for (int c = 0; c < NC; c++) {
        const int s = c & 1;
        if (c >= 2)
            MBARRIER_WAIT_PARITY(smem_base + SM_MBAR + s * 8, ((c >> 1) - 1) & 1);

        const int k0 = c << 6;
        const __nv_bfloat16* src0 = Ahi + (long)mBase * K + k0;
        const __nv_bfloat16* src1 = Alo + (long)mBase * K + k0;
        const __nv_bfloat16* src2 = Bhi + (long)nBase * K + k0;
        const __nv_bfloat16* src3 = Blo + (long)nBase * K + k0;
        const int stage_off = SM_TILES + s * STAGE_B;
        #pragma unroll
        for (int i = 0; i < 4; i++) {
            const int idx = tid + i * 256;      // 0..1023
            const int r   = idx >> 3;
            const int c16 = idx & 7;
            const long gofs = (long)r * K + (c16 << 3);
            const int  sofs = stage_off + SMEM_SWIZZLE_128B((r << 7) | (c16 << 4));
            *(uint4*)(smem + sofs + 0 * TILE_B) = *(const uint4*)(src0 + gofs);
            *(uint4*)(smem + sofs + 1 * TILE_B) = *(const uint4*)(src1 + gofs);
            *(uint4*)(smem + sofs + 2 * TILE_B) = *(const uint4*)(src2 + gofs);
            *(uint4*)(smem + sofs + 3 * TILE_B) = *(const uint4*)(src3 + gofs);
        }
        FENCE_PROXY_ASYNC();
        __syncthreads();

        if (wid == 0) {
            const uint32_t st = smem_base + stage_off;
            const uint64_t dAhi = MAKE_SMEM_DESC(st + 0 * TILE_B);
            const uint64_t dAlo = MAKE_SMEM_DESC(st + 1 * TILE_B);
            const uint64_t dBhi = MAKE_SMEM_DESC(st + 2 * TILE_B);
            const uint64_t dBlo = MAKE_SMEM_DESC(st + 3 * TILE_B);
            if (elect_one_pred()) {
                #pragma unroll
                for (int kk = 0; kk < 4; kk++) {
                    mma_f16_ss(tmem, dAhi + kk * 2, dBhi + kk * 2, GEMM_IDESC,
                               !(c == 0 && kk == 0));
                    mma_f16_ss(tmem, dAlo + kk * 2, dBhi + kk * 2, GEMM_IDESC, true);
                    mma_f16_ss(tmem, dAhi + kk * 2, dBlo + kk * 2, GEMM_IDESC, true);
                }
                TCGEN05_COMMIT(smem_base + SM_MBAR + s * 8);
            }
        }
    }

    // wait for ALL MMAs (last commit covers all prior)
    {
        const int s_last = (NC - 1) & 1;
        const int nlast  = ((NC - 1 - s_last) >> 1) + 1;
        MBARRIER_WAIT_PARITY(smem_base + SM_MBAR + s_last * 8, (nlast - 1) & 1);
    }
    TCGEN05_FENCE_AFTER();

    // Epilogue: TMEM -> SMEM (row-stage) -> coalesced global
    float* sout = (float*)(smem + SM_TILES);
    if (wid < 4) {
        const int r = (wid << 5) + lid;
        #pragma unroll
        for (int cb = 0; cb < 4; cb++) {
            uint32_t regs[32];
            TCGEN05_LD_X32(regs, tmem + (cb << 5));
            TCGEN05_WAIT_LD();
            #pragma unroll
            for (int j = 0; j < 32; j += 4) {
                float4 v = make_float4(__uint_as_float(regs[j]),
                                       __uint_as_float(regs[j + 1]),
                                       __uint_as_float(regs[j + 2]),
                                       __uint_as_float(regs[j + 3]));
                *(float4*)&sout[r * 132 + (cb << 5) + j] = v;
            }
        }
    }
    __syncthreads();
    if (wid == 0) TCGEN05_DEALLOC(tmem, 128);

    for (int idx = tid; idx < 128 * 32; idx += 256) {
        const int r = idx >> 5;
        const int cc = (idx & 31) << 2;
        float4 v = *(float4*)&sout[r * 132 + cc];
        const long gr = mBase + r;
        const int  gc = nBase + cc;
        float4 bb = *(const float4*)&bias[gc];
        v.x += bb.x; v.y += bb.y; v.z += bb.z; v.w += bb.w;
        if (OP == 1 || OP == 3) {
            if (OP == 1) {
                v.x = gelu_exact(v.x); v.y = gelu_exact(v.y);
                v.z = gelu_exact(v.z); v.w = gelu_exact(v.w);
            }
            const long o = gr * N + gc;
            split_store(Chi, Clo, o + 0, v.x);
            split_store(Chi, Clo, o + 1, v.y);
            split_store(Chi, Clo, o + 2, v.z);
            split_store(Chi, Clo, o + 3, v.w);
        } else if (OP == 2) {
            float4 rr = *(const float4*)&res[gr * N + gc];
            v.x += rr.x; v.y += rr.y; v.z += rr.z; v.w += rr.w;
            *(float4*)&Cf[gr * N + gc] = v;
        } else {
            *(float4*)&Cf[gr * N + gc] = v;
        }
    }

#else  // =================== FFMA fallback (non-103a passes) ===================
    float* As = (float*)smem;                 // [8][128]
    float* Bs = As + 8 * 128;                 // [8][128]

    const int tx = tid & 15;
    const int ty = tid >> 4;
    const int row  = tid >> 1;                // 0..127
    const int kc   = (tid & 1) << 2;          // 0 or 4

    float acc[8][8];
    #pragma unroll
    for (int i = 0; i < 8; i++)
        #pragma unroll
        for (int j = 0; j < 8; j++) acc[i][j] = 0.f;

    for (int k0 = 0; k0 < K; k0 += 8) {
        {
            const long o = (long)(mBase + row) * K + k0 + kc;
            ushort4 h = *(const ushort4*)(Ahi + o);
            ushort4 l = *(const ushort4*)(Alo + o);
            As[(kc + 0) * 128 + row] = __bfloat162float(*(__nv_bfloat16*)&h.x) + __bfloat162float(*(__nv_bfloat16*)&l.x);
            As[(kc + 1) * 128 + row] = __bfloat162float(*(__nv_bfloat16*)&h.y) + __bfloat162float(*(__nv_bfloat16*)&l.y);
            As[(kc + 2) * 128 + row] = __bfloat162float(*(__nv_bfloat16*)&h.z) + __bfloat162float(*(__nv_bfloat16*)&l.z);
            As[(kc + 3) * 128 + row] = __bfloat162float(*(__nv_bfloat16*)&h.w) + __bfloat162float(*(__nv_bfloat16*)&l.w);
        }
        {
            const long o = (long)(nBase + row) * K + k0 + kc;
            ushort4 h = *(const ushort4*)(Bhi + o);
            ushort4 l = *(const ushort4*)(Blo + o);
            Bs[(kc + 0) * 128 + row] = __bfloat162float(*(__nv_bfloat16*)&h.x) + __bfloat162float(*(__nv_bfloat16*)&l.x);
            Bs[(kc + 1) * 128 + row] = __bfloat162float(*(__nv_bfloat16*)&h.y) + __bfloat162float(*(__nv_bfloat16*)&l.y);
            Bs[(kc + 2) * 128 + row] = __bfloat162float(*(__nv_bfloat16*)&h.z) + __bfloat162float(*(__nv_bfloat16*)&l.z);
            Bs[(kc + 3) * 128 + row] = __bfloat162float(*(__nv_bfloat16*)&h.w) + __bfloat162float(*(__nv_bfloat16*)&l.w);
        }
        __syncthreads();

        #pragma unroll
        for (int k = 0; k < 8; k++) {
            float a[8], bb[8];
            #pragma unroll
            for (int i = 0; i < 8; i++) a[i]  = As[k * 128 + ty * 8 + i];
            #pragma unroll
            for (int j = 0; j < 8; j++) bb[j] = Bs[k * 128 + tx * 8 + j];
            #pragma unroll
            for (int i = 0; i < 8; i++)
                #pragma unroll
                for (int j = 0; j < 8; j++)
                    acc[i][j] = fmaf(a[i], bb[j], acc[i][j]);
        }
        __syncthreads();
    }

    #pragma unroll
    for (int i = 0; i < 8; i++) {
        const long gr = mBase + ty * 8 + i;
        #pragma unroll
        for (int j = 0; j < 8; j++) {
            const int gc = nBase + tx * 8 + j;
            float v = acc[i][j] + bias[gc];
            if (OP == 1) {
                v = gelu_exact(v);
                split_store(Chi, Clo, gr * N + gc, v);
            } else if (OP == 3) {
                split_store(Chi, Clo, gr * N + gc, v);
            } else if (OP == 2) {
                Cf[gr * N + gc] = v + res[gr * N + gc];
            } else {
                Cf[gr * N + gc] = v;
            }
        }
    }
#endif
}

// ======================= tcgen05 causal flash attention (pipelined, 128-key tiles) =======================
// CTA = (128 q rows, head, batch), qt reversed for load balance.
// TMEM: S cols 0..127, O cols 128..191 (alloc 256).
// V staged as-loaded into the (currently dead) P region, transposed in SMEM to
// Vt[hd][key] halves, consumed by the R4-validated K-major PV MMA. K double-
// buffered; K(kt+1) load + S(kt+1) issue overlap the PV(kt) wait. Softmax split
// across 8 warps (column halves).
#define A_TMEMPTR 0
#define A_MBAR0   8
#define A_MBAR1   16
#define A_QHI     1024
#define A_QLO     (A_QHI + 16384)      // 17408
#define A_K0      (A_QLO + 16384)      // 33792 : KHI(s)=A_K0+s*32768, KLO(s)=+16384
#define A_VT      (A_K0 + 65536)       // 99328 : Vt hi half h at +h*8192, lo at +16384+h*8192
#define A_P       (A_VT + 32768)       // 132096: P hi half h at +h*16384, lo at +32768+h*16384
                                       //         ALSO V staging (hi at +0, lo at +16384)
#define A_MX      (A_P + 65536)        // 197632 : float[256]
#define A_LS      (A_MX + 1024)        // 198656 : float[256]
#define ATTN_SMEM (A_LS + 1024)        // 199680

#if HAS_TCGEN05
__device__ __forceinline__ void attn_issue_S(uint32_t tmem, uint32_t sb, int s) {
    const uint64_t dQh = MAKE_SMEM_DESC(sb + A_QHI);
    const uint64_t dQl = MAKE_SMEM_DESC(sb + A_QLO);
    const uint64_t dKh = MAKE_SMEM_DESC(sb + A_K0 + s * 32768);
    const uint64_t dKl = MAKE_SMEM_DESC(sb + A_K0 + s * 32768 + 16384);
    #pragma unroll
    for (int kk = 0; kk < 4; kk++) {
        mma_f16_ss(tmem, dQh + kk * 2, dKh + kk * 2, GEMM_IDESC, kk != 0);
        mma_f16_ss(tmem, dQl + kk * 2, dKh + kk * 2, GEMM_IDESC, true);
        mma_f16_ss(tmem, dQh + kk * 2, dKl + kk * 2, GEMM_IDESC, true);
    }
}
__device__ __forceinline__ void attn_issue_PV(uint32_t tmem, uint32_t sb) {
    #pragma unroll
    for (int h = 0; h < 2; h++) {
        const uint64_t dPh = MAKE_SMEM_DESC(sb + A_P + h * 16384);
        const uint64_t dPl = MAKE_SMEM_DESC(sb + A_P + 32768 + h * 16384);
        const uint64_t dVh = MAKE_SMEM_DESC(sb + A_VT + h * 8192);
        const uint64_t dVl = MAKE_SMEM_DESC(sb + A_VT + 16384 + h * 8192);
        #pragma unroll
        for (int kk = 0; kk < 4; kk++) {
            mma_f16_ss(tmem + 128, dPh + kk * 2, dVh + kk * 2, ATTN_IDESC, !(h == 0 && kk == 0));
            mma_f16_ss(tmem + 128, dPl + kk * 2, dVh + kk * 2, ATTN_IDESC, true);
            mma_f16_ss(tmem + 128, dPh + kk * 2, dVl + kk * 2, ATTN_IDESC, true);
        }
    }
}
#endif

__global__ __launch_bounds__(256, 1) void attn_tc(
    const __nv_bfloat16* __restrict__ qkv_hi,
    const __nv_bfloat16* __restrict__ qkv_lo,
    __nv_bfloat16* __restrict__ ohi,
    __nv_bfloat16* __restrict__ olo)
{
    extern __shared__ __align__(1024) char smem[];
    const int tid  = threadIdx.x;
    const int wid  = tid >> 5;
    const int lid  = tid & 31;
    const int qt   = gridDim.x - 1 - blockIdx.x;   // reversed: long CTAs first
    const int head = blockIdx.y;
    const int bat  = blockIdx.z;
    const long tok0 = (long)bat * SEQ;

#if HAS_TCGEN05
    const uint32_t sb = smem_to_u32(smem);
    float* smx = (float*)(smem + A_MX);
    float* sls = (float*)(smem + A_LS);
    if (wid == 0) {
        TCGEN05_ALLOC(sb + A_TMEMPTR, 256);
        TCGEN05_RELINQUISH();
    }
    if (tid == 0) {
        MBARRIER_INIT(sb + A_MBAR0, 1);
        MBARRIER_INIT(sb + A_MBAR1, 1);
    }
    __syncthreads();
    uint32_t tmem;
    asm volatile("ld.shared.b32 %0, [%1];" : "=r"(tmem) : "r"(sb + A_TMEMPTR));

    // load Q tile (128 x 64 hi/lo) and K tile 0 (128 keys)
    #pragma unroll
    for (int i = 0; i < 4; i++) {
        const int idx = tid + i * 256;
        const int r = idx >> 3, c8 = idx & 7;
        const int sofs = SMEM_SWIZZLE_128B((r << 7) | (c8 << 4));
        const long gq = (tok0 + qt * 128 + r) * (long)QKVW + head * 64 + (c8 << 3);
        *(uint4*)(smem + A_QHI + sofs) = *(const uint4*)(qkv_hi + gq);
        *(uint4*)(smem + A_QLO + sofs) = *(const uint4*)(qkv_lo + gq);
        const long gk = (tok0 + r) * (long)QKVW + 1024 + head * 64 + (c8 << 3);
        *(uint4*)(smem + A_K0 + sofs)         = *(const uint4*)(qkv_hi + gk);
        *(uint4*)(smem + A_K0 + 16384 + sofs) = *(const uint4*)(qkv_lo + gk);
    }
    FENCE_PROXY_ASYNC();
    __syncthreads();
    if (wid == 0 && elect_one_pred()) {
        attn_issue_S(tmem, sb, 0);
        TCGEN05_COMMIT(sb + A_MBAR0);
    }

    const int half = wid >> 2;                 // column half this warp handles
    const int row  = ((wid & 3) << 5) + lid;   // q row (shared by both halves)
    const int grow = qt * 128 + row;
    const int nkt  = qt + 1;

    float o[64];
    #pragma unroll
    for (int j = 0; j < 64; j++) o[j] = 0.f;
    float m = -1e30f, l = 0.f;

    for (int kt = 0; kt < nkt; kt++) {
        // stage V(kt) as-loaded into the P region (dead until P store below);
        // runs while S(kt) MMA is in flight
        #pragma unroll
        for (int i = 0; i < 4; i++) {
            const int idx = tid + i * 256;
            const int r = idx >> 3, c8 = idx & 7;
            const int sofs = SMEM_SWIZZLE_128B((r << 7) | (c8 << 4));
            const long gv = (tok0 + kt * 128 + r) * (long)QKVW + 2048 + head * 64 + (c8 << 3);
            *(uint4*)(smem + A_P + sofs)         = *(const uint4*)(qkv_hi + gv);
            *(uint4*)(smem + A_P + 16384 + sofs) = *(const uint4*)(qkv_lo + gv);
        }

        // wait S(kt), pull this warp's column half
        MBARRIER_WAIT_PARITY(sb + A_MBAR0, kt & 1);
        TCGEN05_FENCE_AFTER();
        uint32_t r0[32], r1[32];
        TCGEN05_LD_X32(r0, tmem + half * 64);
        TCGEN05_LD_X32(r1, tmem + half * 64 + 32);
        TCGEN05_WAIT_LD();
        __syncthreads();   // S1: V staging visible to all threads

        // transpose staged V -> Vt[hd][key] halves (hi + lo planes)
        #pragma unroll
        for (int i = 0; i < 16; i++) {
            const int idx = tid + i * 256;        // 0..4095
            const int c  = idx & 63;              // hd
            const int kp = idx >> 6;              // key pair 0..63
            const int h  = kp >> 5;
            const int lk = (kp & 31) << 1;        // local key (even)
            const int so0 = SMEM_SWIZZLE_128B(((2 * kp)     << 7) | (c << 1));
            const int so1 = SMEM_SWIZZLE_128B(((2 * kp + 1) << 7) | (c << 1));
            const int dd  = SMEM_SWIZZLE_128B((c << 7) | (lk << 1));
            uint32_t a = *(const uint16_t*)(smem + A_P + so0);
            uint32_t b = *(const uint16_t*)(smem + A_P + so1);
            *(uint32_t*)(smem + A_VT + h * 8192 + dd) = a | (b << 16);
            a = *(const uint16_t*)(smem + A_P + 16384 + so0);
            b = *(const uint16_t*)(smem + A_P + 16384 + so1);
            *(uint32_t*)(smem + A_VT + 16384 + h * 8192 + dd) = a | (b << 16);
        }

        float s[64];
        #pragma unroll
        for (int j = 0; j < 32; j++) s[j]      = __uint_as_float(r0[j]) * 0.125f;
        #pragma unroll
        for (int j = 0; j < 32; j++) s[32 + j] = __uint_as_float(r1[j]) * 0.125f;

        if (kt == qt) {   // diagonal tile: causal mask
            const int kbase = kt * 128 + half * 64;
            #pragma unroll
            for (int j = 0; j < 64; j++)
                if (kbase + j > grow) s[j] = -1e30f;
        }
        float lmx = -1e30f;
        #pragma unroll
        for (int j = 0; j < 64; j++) lmx = fmaxf(lmx, s[j]);
        smx[half * 128 + row] = lmx;
        __syncthreads();   // S2: smx visible; transpose reads done (staging now dead)

        const float mnew = fmaxf(m, fmaxf(smx[row], smx[128 + row]));
        const float scl  = __expf(m - mnew);
        m = mnew;
        float ls = 0.f;
        #pragma unroll
        for (int j = 0; j < 64; j++) { s[j] = __expf(s[j] - mnew); ls += s[j]; }
        sls[half * 128 + row] = ls;

        // store this half's P (hi/lo) — row-owned, K-major 128B rows (overwrites staging)
        #pragma unroll
        for (int j8 = 0; j8 < 8; j8++) {
            __align__(16) __nv_bfloat16 hb[8], lb[8];
            #pragma unroll
            for (int j = 0; j < 8; j++) {
                const float v = s[(j8 << 3) + j];
                const __nv_bfloat16 h = __float2bfloat16(v);
                hb[j] = h;
                lb[j] = __float2bfloat16(v - __bfloat162float(h));
            }
            const int so = SMEM_SWIZZLE_128B((row << 7) | (j8 << 4));
            *(uint4*)(smem + A_P + half * 16384 + so)         = *(uint4*)hb;
            *(uint4*)(smem + A_P + 32768 + half * 16384 + so) = *(uint4*)lb;
        }
        FENCE_PROXY_ASYNC();
        __syncthreads();   // S3: P + Vt visible for MMA; sls visible

        if (wid < 4) l = l * scl + sls[row] + sls[128 + row];

        if (wid == 0 && elect_one_pred()) {
            attn_issue_PV(tmem, sb);
            TCGEN05_COMMIT(sb + A_MBAR1);
        }

        // prefetch K(kt+1) + issue S(kt+1) while PV(kt) runs
        if (kt + 1 < nkt) {
            const int s2 = (kt + 1) & 1;
            #pragma unroll
            for (int i = 0; i < 4; i++) {
                const int idx = tid + i * 256;
                const int r = idx >> 3, c8 = idx & 7;
                const int sofs = SMEM_SWIZZLE_128B((r << 7) | (c8 << 4));
                const long gk = (tok0 + (kt + 1) * 128 + r) * (long)QKVW + 1024 + head * 64 + (c8 << 3);
                *(uint4*)(smem + A_K0 + s2 * 32768 + sofs)         = *(const uint4*)(qkv_hi + gk);
                *(uint4*)(smem + A_K0 + s2 * 32768 + 16384 + sofs) = *(const uint4*)(qkv_lo + gk);
            }
            FENCE_PROXY_ASYNC();
            __syncthreads();
            if (wid == 0 && elect_one_pred()) {
                attn_issue_S(tmem, sb, s2);
                TCGEN05_COMMIT(sb + A_MBAR0);
            }
        }

        // wait PV(kt), accumulate O
        MBARRIER_WAIT_PARITY(sb + A_MBAR1, kt & 1);
        TCGEN05_FENCE_AFTER();
        if (wid < 4) {
            uint32_t p0[32], p1[32];
            TCGEN05_LD_X32(p0, tmem + 128);
            TCGEN05_LD_X32(p1, tmem + 160);
            TCGEN05_WAIT_LD();
            #pragma unroll
            for (int j = 0; j < 32; j++) o[j]      = o[j]      * scl + __uint_as_float(p0[j]);
            #pragma unroll
            for (int j = 0; j < 32; j++) o[32 + j] = o[32 + j] * scl + __uint_as_float(p1[j]);
        }
    }

    // epilogue
    if (wid < 4) {
        const float invl = 1.0f / l;
        const long gofs = (tok0 + grow) * (long)DMODEL + head * 64;
        #pragma unroll
        for (int j8 = 0; j8 < 8; j8++) {
            __align__(16) __nv_bfloat16 hb[8], lb[8];
            #pragma unroll
            for (int j = 0; j < 8; j++) {
                const float v = o[(j8 << 3) + j] * invl;
                const __nv_bfloat16 h = __float2bfloat16(v);
                hb[j] = h;
                lb[j] = __float2bfloat16(v - __bfloat162float(h));
            }
            *(uint4*)(ohi + gofs + (j8 << 3)) = *(uint4*)hb;
            *(uint4*)(olo + gofs + (j8 << 3)) = *(uint4*)lb;
        }
    }
    __syncthreads();
    if (wid == 0) TCGEN05_DEALLOC(tmem, 256);

#else  // =================== compile-only FFMA fallback ===================
    if (tid < 128) {
        const int grow2 = qt * 128 + tid;
        const long qofs = (tok0 + grow2) * (long)QKVW + head * 64;
        float q[64], o2[64];
        #pragma unroll
        for (int c = 0; c < 64; c++) {
            q[c] = (__bfloat162float(qkv_hi[qofs + c]) +
                    __bfloat162float(qkv_lo[qofs + c])) * 0.125f;
            o2[c] = 0.f;
        }
        float m2 = -1e30f, l2 = 0.f;
        for (int j = 0; j <= grow2; j++) {
            const long kofs = (tok0 + j) * (long)QKVW + 1024 + head * 64;
            float s = 0.f;
            for (int c = 0; c < 64; c++)
                s += q[c] * (__bfloat162float(qkv_hi[kofs + c]) +
                             __bfloat162float(qkv_lo[kofs + c]));
            const float mnew = fmaxf(m2, s);
            const float scf = expf(m2 - mnew);
            const float p = expf(s - mnew);
            l2 = l2 * scf + p;
            m2 = mnew;
            const long vofs = kofs + 1024;
            for (int c = 0; c < 64; c++)
                o2[c] = o2[c] * scf + p * (__bfloat162float(qkv_hi[vofs + c]) +
                                           __bfloat162float(qkv_lo[vofs + c]));
        }
        const long gofs = (tok0 + grow2) * (long)DMODEL + head * 64;
        for (int c = 0; c < 64; c++)
            split_store(ohi, olo, gofs + c, o2[c] / l2);
    }
#endif
}

// ======================= driver =======================
extern "C" void kernel_launch(void* const* d_in, const int* in_sizes, int n_in,
                              void* d_out, int out_size)
{
    const float* x    = (const float*)d_in[0];
    const float* g1   = (const float*)d_in[1];
    const float* b1   = (const float*)d_in[2];
    const float* Wqkv = (const float*)d_in[3];
    const float* bqkv = (const float*)d_in[4];
    const float* Wo   = (const float*)d_in[5];
    const float* bo   = (const float*)d_in[6];
    const float* g2   = (const float*)d_in[7];
    const float* b2   = (const float*)d_in[8];
    const float* W1   = (const float*)d_in[9];
    const float* b1f  = (const float*)d_in[10];
    const float* W2   = (const float*)d_in[11];
    const float* b2f  = (const float*)d_in[12];
    float* out = (float*)d_out;

    float *x2;
    __nv_bfloat16 *qkv_hi, *qkv_lo;
    __nv_bfloat16 *h_hi, *h_lo, *attn_hi, *attn_lo, *hh_hi, *hh_lo, *ff_hi, *ff_lo;
    __nv_bfloat16 *WqkvT_hi, *WqkvT_lo, *WoT_hi, *WoT_lo, *W1T_hi, *W1T_lo, *W2T_hi, *W2T_lo;
    cudaGetSymbolAddress((void**)&x2,       g_x2);
    cudaGetSymbolAddress((void**)&qkv_hi,   g_qkv_hi);
    cudaGetSymbolAddress((void**)&qkv_lo,   g_qkv_lo);
    cudaGetSymbolAddress((void**)&h_hi,     g_h_hi);
    cudaGetSymbolAddress((void**)&h_lo,     g_h_lo);
    cudaGetSymbolAddress((void**)&attn_hi,  g_attn_hi);
    cudaGetSymbolAddress((void**)&attn_lo,  g_attn_lo);
    cudaGetSymbolAddress((void**)&hh_hi,    g_hh_hi);
    cudaGetSymbolAddress((void**)&hh_lo,    g_hh_lo);
    cudaGetSymbolAddress((void**)&ff_hi,    g_ff_hi);
    cudaGetSymbolAddress((void**)&ff_lo,    g_ff_lo);
    cudaGetSymbolAddress((void**)&WqkvT_hi, g_WqkvT_hi);
    cudaGetSymbolAddress((void**)&WqkvT_lo, g_WqkvT_lo);
    cudaGetSymbolAddress((void**)&WoT_hi,   g_WoT_hi);
    cudaGetSymbolAddress((void**)&WoT_lo,   g_WoT_lo);
    cudaGetSymbolAddress((void**)&W1T_hi,   g_W1T_hi);
    cudaGetSymbolAddress((void**)&W1T_lo,   g_W1T_lo);
    cudaGetSymbolAddress((void**)&W2T_hi,   g_W2T_hi);
    cudaGetSymbolAddress((void**)&W2T_lo,   g_W2T_lo);

    cudaFuncSetAttribute(attn_tc,    cudaFuncAttributeMaxDynamicSharedMemorySize, ATTN_SMEM);
    cudaFuncSetAttribute(gemm_tc<1>, cudaFuncAttributeMaxDynamicSharedMemorySize, GEMM_SMEM);
    cudaFuncSetAttribute(gemm_tc<2>, cudaFuncAttributeMaxDynamicSharedMemorySize, GEMM_SMEM);
    cudaFuncSetAttribute(gemm_tc<3>, cudaFuncAttributeMaxDynamicSharedMemorySize, GEMM_SMEM);

    // weight conversion + transpose (K-major for MMA B operand)
    wtrans_kernel<<<dim3(QKVW / 32, DMODEL / 32), dim3(32, 8)>>>(Wqkv, WqkvT_hi, WqkvT_lo, DMODEL, QKVW);
    wtrans_kernel<<<dim3(DMODEL / 32, DMODEL / 32), dim3(32, 8)>>>(Wo, WoT_hi, WoT_lo, DMODEL, DMODEL);
    wtrans_kernel<<<dim3(FFDIM / 32, DMODEL / 32), dim3(32, 8)>>>(W1, W1T_hi, W1T_lo, DMODEL, FFDIM);
    wtrans_kernel<<<dim3(DMODEL / 32, FFDIM / 32), dim3(32, 8)>>>(W2, W2T_hi, W2T_lo, FFDIM, DMODEL);

    // LN1 -> hi/lo
    ln_kernel<<<NTOK, 256>>>(x, g1, b1, h_hi, h_lo);
    // QKV projection -> bf16 hi/lo (attention input)
    gemm_tc<3><<<dim3(QKVW / 128, NTOK / 128), 256, GEMM_SMEM>>>(
        h_hi, h_lo, WqkvT_hi, WqkvT_lo, bqkv, nullptr, nullptr, qkv_hi, qkv_lo, QKVW, DMODEL);
    // causal attention (tcgen05, pipelined) -> hi/lo
    attn_tc<<<dim3(SEQ / 128, NH, BATCH), 256, ATTN_SMEM>>>(qkv_hi, qkv_lo, attn_hi, attn_lo);
    // output projection + residual -> x2 (fp32)
    gemm_tc<2><<<dim3(DMODEL / 128, NTOK / 128), 256, GEMM_SMEM>>>(
        attn_hi, attn_lo, WoT_hi, WoT_lo, bo, x, x2, nullptr, nullptr, DMODEL, DMODEL);
    // LN2 -> hi/lo
    ln_kernel<<<NTOK, 256>>>(x2, g2, b2, hh_hi, hh_lo);
    // FF1 + GELU -> hi/lo
    gemm_tc<1><<<dim3(FFDIM / 128, NTOK / 128), 256, GEMM_SMEM>>>(
        hh_hi, hh_lo, W1T_hi, W1T_lo, b1f, nullptr, nullptr, ff_hi, ff_lo, FFDIM, DMODEL);
    // FF2 + residual -> out (fp32)
    gemm_tc<2><<<dim3(DMODEL / 128, NTOK / 128), 256, GEMM_SMEM>>>(
        ff_hi, ff_lo, W2T_hi, W2T_lo, b2f, x2, out, nullptr, nullptr, DMODEL, FFDIM);
}

// round 7
// speedup vs baseline: 4.5580x; 1.1131x over previous
#include <cuda_runtime.h>
#include <cuda_bf16.h>
#include <math.h>
#include <stdint.h>

// Problem dims (fixed by the reference)
#define NTOK   4096      // B*T = 2*2048
#define SEQ    2048
#define BATCH  2
#define DMODEL 1024
#define NH     16
#define HDIM   64
#define FFDIM  4096
#define QKVW   3072      // 3*DMODEL

// tcgen05 only exists in the arch-specific (sm_103a / sm_103f) compilation pass.
#if defined(__CUDA_ARCH__) && (__CUDA_ARCH__ == 1030) && \
    (defined(__CUDA_ARCH_FEAT_SM103_ALL) || defined(__CUDA_ARCH_SPECIFIC__) || \
     defined(__CUDA_ARCH_FAMILY_SPECIFIC__))
#define HAS_TCGEN05 1
#else
#define HAS_TCGEN05 0
#endif

// cp.async works on all passes (sm_80+)
#define CP_ASYNC16(smem_u32, gptr) \
    asm volatile("cp.async.cg.shared.global [%0], [%1], 16;" \
                 :: "r"((uint32_t)(smem_u32)), "l"(gptr) : "memory")
#define CP_COMMIT() asm volatile("cp.async.commit_group;" ::: "memory")
#define CP_WAIT_0() asm volatile("cp.async.wait_group 0;" ::: "memory")
#define CP_WAIT_1() asm volatile("cp.async.wait_group 1;" ::: "memory")

__device__ __forceinline__ uint32_t smem_u32_of(const void* p) {
    uint32_t a;
    asm("{ .reg .u64 t; cvta.to.shared.u64 t, %1; cvt.u32.u64 %0, t; }" : "=r"(a) : "l"(p));
    return a;
}

#if HAS_TCGEN05
// ======================= PTX helpers (arch-specific pass only) =======================
__device__ __forceinline__ uint32_t elect_one_pred() {
    uint32_t pred;
    asm volatile("{\n\t.reg .pred p;\n\telect.sync _|p, 0xFFFFFFFF;\n\tselp.b32 %0, 1, 0, p;\n\t}"
                 : "=r"(pred));
    return pred;
}

static constexpr uint64_t SMEM_DESC_BASE_SW128 =
    (uint64_t(2) << 61) | (uint64_t(1) << 46) | (uint64_t(64) << 32) | (uint64_t(1) << 16);
#define MAKE_SMEM_DESC(base_addr) \
    (SMEM_DESC_BASE_SW128 | ((uint64_t)((base_addr) >> 4) & 0x3FFF))

#define TCGEN05_ALLOC(sa, n) \
    asm volatile("tcgen05.alloc.cta_group::1.sync.aligned.shared::cta.b32 [%0], %1;" \
                 :: "r"((uint32_t)(sa)), "r"((uint32_t)(n)) : "memory")
#define TCGEN05_DEALLOC(t, n) \
    asm volatile("tcgen05.dealloc.cta_group::1.sync.aligned.b32 %0, %1;" :: "r"(t), "r"((uint32_t)(n)))
#define TCGEN05_RELINQUISH() \
    asm volatile("tcgen05.relinquish_alloc_permit.cta_group::1.sync.aligned;")
#define TCGEN05_COMMIT(mb) \
    asm volatile("tcgen05.commit.cta_group::1.mbarrier::arrive::one.shared::cluster.b64 [%0];" \
                 :: "r"((uint32_t)(mb)) : "memory")
#define TCGEN05_FENCE_AFTER() asm volatile("tcgen05.fence::after_thread_sync;" ::: "memory")
#define TCGEN05_WAIT_LD() asm volatile("tcgen05.wait::ld.sync.aligned;" ::: "memory")
#define FENCE_PROXY_ASYNC() asm volatile("fence.proxy.async.shared::cta;" ::: "memory")

#define MBARRIER_INIT(mb, cnt) \
    asm volatile("mbarrier.init.shared.b64 [%0], %1;" :: "r"((uint32_t)(mb)), "r"((uint32_t)(cnt)) : "memory")

#define MBARRIER_WAIT_PARITY(mb, par) do { \
    uint32_t _mb = (uint32_t)(mb), _p = (uint32_t)(par), _d; \
    asm volatile("{\n\t.reg .pred p;\n\t" \
        "mbarrier.try_wait.parity.acquire.cta.shared::cta.b64 p, [%1], %2;\n\t" \
        "selp.b32 %0, 1, 0, p;\n\t}" : "=r"(_d) : "r"(_mb), "r"(_p) : "memory"); \
    if (!_d) { \
        asm volatile("{\n\t.reg .pred P1;\n\t" \
            "WL_%=:\n\t" \
            "mbarrier.try_wait.parity.acquire.cta.shared::cta.b64 P1, [%0], %1, 0x989680;\n\t" \
            "@P1 bra.uni WD_%=;\n\t" \
            "bra.uni WL_%=;\n\t" \
            "WD_%=:\n\t}" :: "r"(_mb), "r"(_p) : "memory"); \
    } \
} while (0)

#define TCGEN05_LD_X32(r, ta) \
    asm volatile("tcgen05.ld.sync.aligned.32x32b.x32.b32 " \
        "{%0, %1, %2, %3, %4, %5, %6, %7, %8, %9, %10, %11, %12, %13, %14, %15, " \
        "%16, %17, %18, %19, %20, %21, %22, %23, %24, %25, %26, %27, %28, %29, %30, %31}, [%32];" \
        : "=r"((r)[0]), "=r"((r)[1]), "=r"((r)[2]), "=r"((r)[3]), \
          "=r"((r)[4]), "=r"((r)[5]), "=r"((r)[6]), "=r"((r)[7]), \
          "=r"((r)[8]), "=r"((r)[9]), "=r"((r)[10]), "=r"((r)[11]), \
          "=r"((r)[12]), "=r"((r)[13]), "=r"((r)[14]), "=r"((r)[15]), \
          "=r"((r)[16]), "=r"((r)[17]), "=r"((r)[18]), "=r"((r)[19]), \
          "=r"((r)[20]), "=r"((r)[21]), "=r"((r)[22]), "=r"((r)[23]), \
          "=r"((r)[24]), "=r"((r)[25]), "=r"((r)[26]), "=r"((r)[27]), \
          "=r"((r)[28]), "=r"((r)[29]), "=r"((r)[30]), "=r"((r)[31]) \
        : "r"(ta))

// cg1 kind::f16 SS-mode MMA (A and B both in SMEM, bf16 in / fp32 accum)
__device__ __forceinline__ void mma_f16_ss(uint32_t d, uint64_t ad, uint64_t bd,
                                           uint32_t idesc, bool acc) {
    uint32_t en = acc ? 1u : 0u;
    asm volatile(
        "{\n\t.reg .pred p;\n\tsetp.ne.u32 p, %5, 0;\n\t"
        "tcgen05.mma.cta_group::1.kind::f16 [%0], %1, %2, %3, {%4, %4, %4, %4}, p;\n\t}"
        :: "r"(d), "l"(ad), "l"(bd), "r"(idesc), "r"(0u), "r"(en) : "memory");
}

// idesc: fp32 accum, bf16 A/B, M=128, N=128, K-major both
static constexpr uint32_t GEMM_IDESC =
    (1u << 4) | (1u << 7) | (1u << 10) | ((128u / 8u) << 17) | ((128u / 16u) << 24);
// idesc for attention MMAs: M=128, N=64, K-major both (validated in R4)
static constexpr uint32_t ATTN_IDESC =
    (1u << 4) | (1u << 7) | (1u << 10) | ((64u / 8u) << 17) | ((128u / 16u) << 24);
#endif  // HAS_TCGEN05

#define SMEM_SWIZZLE_128B(off) ((off) ^ (((off) >> 3) & 0x70))

// ======================= scratch (device globals) =======================
__device__ float g_x2  [NTOK * DMODEL];          // residual after attn proj
__device__ __nv_bfloat16 g_qkv_hi[NTOK * QKVW],  g_qkv_lo[NTOK * QKVW];
__device__ __nv_bfloat16 g_h_hi  [NTOK * DMODEL], g_h_lo  [NTOK * DMODEL];
__device__ __nv_bfloat16 g_attn_hi[NTOK * DMODEL], g_attn_lo[NTOK * DMODEL];
__device__ __nv_bfloat16 g_hh_hi [NTOK * DMODEL], g_hh_lo [NTOK * DMODEL];
__device__ __nv_bfloat16 g_ff_hi [NTOK * FFDIM],  g_ff_lo [NTOK * FFDIM];
__device__ __nv_bfloat16 g_WqkvT_hi[QKVW * DMODEL],  g_WqkvT_lo[QKVW * DMODEL];
__device__ __nv_bfloat16 g_WoT_hi [DMODEL * DMODEL], g_WoT_lo [DMODEL * DMODEL];
__device__ __nv_bfloat16 g_W1T_hi [FFDIM * DMODEL],  g_W1T_lo [FFDIM * DMODEL];
__device__ __nv_bfloat16 g_W2T_hi [DMODEL * FFDIM],  g_W2T_lo [DMODEL * FFDIM];

__device__ __forceinline__ void split_store(__nv_bfloat16* hi, __nv_bfloat16* lo,
                                            long ofs, float v) {
    __nv_bfloat16 h = __float2bfloat16(v);
    hi[ofs] = h;
    lo[ofs] = __float2bfloat16(v - __bfloat162float(h));
}
__device__ __forceinline__ uint32_t pack2bf(float a, float b) {
    __nv_bfloat162 t;
    t.x = __float2bfloat16(a);
    t.y = __float2bfloat16(b);
    return *(uint32_t*)&t;
}
__device__ __forceinline__ float gelu_exact(float x) {
    return 0.5f * x * (1.0f + erff(x * 0.70710678118654752f));
}

// ======================= LayerNorm -> bf16 hi/lo planes =======================
__global__ __launch_bounds__(256) void ln_kernel(const float* __restrict__ x,
                                                 const float* __restrict__ g,
                                                 const float* __restrict__ b,
                                                 __nv_bfloat16* __restrict__ yhi,
                                                 __nv_bfloat16* __restrict__ ylo)
{
    const int row = blockIdx.x;
    const int tid = threadIdx.x;
    const float* xr = x + (long)row * DMODEL;
    float4 v = *(const float4*)(xr + tid * 4);

    float s  = v.x + v.y + v.z + v.w;
    float sq = v.x*v.x + v.y*v.y + v.z*v.z + v.w*v.w;
    #pragma unroll
    for (int off = 16; off > 0; off >>= 1) {
        s  += __shfl_xor_sync(0xffffffffu, s,  off);
        sq += __shfl_xor_sync(0xffffffffu, sq, off);
    }
    __shared__ float reds[8], redq[8];
    const int wid = tid >> 5;
    if ((tid & 31) == 0) { reds[wid] = s; redq[wid] = sq; }
    __syncthreads();
    float st = 0.f, qt = 0.f;
    #pragma unroll
    for (int w = 0; w < 8; w++) { st += reds[w]; qt += redq[w]; }

    const float mu   = st * (1.0f / DMODEL);
    const float var  = qt * (1.0f / DMODEL) - mu * mu;
    const float rstd = rsqrtf(var + 1e-5f);

    float4 gv = *(const float4*)(g + tid * 4);
    float4 bv = *(const float4*)(b + tid * 4);
    float o0 = (v.x - mu) * rstd * gv.x + bv.x;
    float o1 = (v.y - mu) * rstd * gv.y + bv.y;
    float o2 = (v.z - mu) * rstd * gv.z + bv.z;
    float o3 = (v.w - mu) * rstd * gv.w + bv.w;
    const long base = (long)row * DMODEL + tid * 4;
    split_store(yhi, ylo, base + 0, o0);
    split_store(yhi, ylo, base + 1, o1);
    split_store(yhi, ylo, base + 2, o2);
    split_store(yhi, ylo, base + 3, o3);
}

// ============== weight transpose + bf16 hi/lo: W[K,N] -> T[N,K] (coalesced) ==============
__global__ __launch_bounds__(256) void wtrans_kernel(const float* __restrict__ W,
                                                     __nv_bfloat16* __restrict__ Thi,
                                                     __nv_bfloat16* __restrict__ Tlo,
                                                     int K, int N)
{
    __shared__ float tile[64][65];
    const int nb = blockIdx.x * 64;
    const int kb = blockIdx.y * 64;
    const int tid = threadIdx.x;
    #pragma unroll
    for (int i = 0; i < 16; i++) {
        const int idx = tid + i * 256;       // 0..4095
        const int k = idx >> 6, n = idx & 63;
        tile[k][n] = W[(long)(kb + k) * N + nb + n];
    }
    __syncthreads();
    #pragma unroll
    for (int i = 0; i < 4; i++) {
        const int idx = tid + i * 256;       // 0..1023
        const int n  = idx >> 4;
        const int kq = (idx & 15) << 2;      // 4 consecutive K per thread
        float v0 = tile[kq + 0][n], v1 = tile[kq + 1][n];
        float v2 = tile[kq + 2][n], v3 = tile[kq + 3][n];
        const long ofs = (long)(nb + n) * K + kb + kq;
        uint2 hp, lp;
        hp.x = pack2bf(v0, v1); hp.y = pack2bf(v2, v3);
        __nv_bfloat162* h01 = (__nv_bfloat162*)&hp.x;
        __nv_bfloat162* h23 = (__nv_bfloat162*)&hp.y;
        lp.x = pack2bf(v0 - __bfloat162float(h01->x), v1 - __bfloat162float(h01->y));
        lp.y = pack2bf(v2 - __bfloat162float(h23->x), v3 - __bfloat162float(h23->y));
        *(uint2*)(Thi + ofs) = hp;
        *(uint2*)(Tlo + ofs) = lp;
    }
}

// ======================= GEMM =======================
// C[M,N] = A[M,K] @ B[N,K]^T with A,B given as bf16 hi/lo planes (K-major).
// OP: 0 = +bias -> fp32 ; 1 = +bias, GELU -> bf16 hi/lo ; 2 = +bias +res -> fp32 ;
//     3 = +bias -> bf16 hi/lo
#define SM_TMEMPTR 0
#define SM_MBAR    16          // two mbarriers at 16, 24
#define SM_TILES   1024
#define TILE_B     16384       // 128 rows x 128 bytes (64 bf16)
#define STAGE_B    (4 * TILE_B)
#define GEMM_SMEM  (SM_TILES + 2 * STAGE_B)

template<int OP>
__global__ __launch_bounds__(256, 1) void gemm_tc(
    const __nv_bfloat16* __restrict__ Ahi, const __nv_bfloat16* __restrict__ Alo,
    const __nv_bfloat16* __restrict__ Bhi, const __nv_bfloat16* __restrict__ Blo,
    const float* __restrict__ bias, const float* __restrict__ res,
    float* __restrict__ Cf,
    __nv_bfloat16* __restrict__ Chi, __nv_bfloat16* __restrict__ Clo,
    int N, int K)
{
    extern __shared__ __align__(1024) char smem[];
    const int tid = threadIdx.x;
    const int mBase = blockIdx.y * 128;
    const int nBase = blockIdx.x * 128;

#if HAS_TCGEN05
    const uint32_t smem_base = smem_u32_of(smem);
    const int wid = tid >> 5;
    const int lid = tid & 31;

    if (wid == 0) {
        TCGEN05_ALLOC(smem_base + SM_TMEMPTR, 128);
        TCGEN05_RELINQUISH();
    }
    if (tid == 0) {
        MBARRIER_INIT(smem_base + SM_MBAR + 0, 1);
        MBARRIER_INIT(smem_base + SM_MBAR + 8, 1);
    }
    __syncthreads();
    uint32_t tmem;
    asm volatile("ld.shared.b32 %0, [%1];" : "=r"(tmem) : "r"(smem_base + SM_TMEMPTR));

    const int NC = K >> 6;   // K-chunks of 64
    for (int c = 0; c < NC; c++) {
        const int s = c & 1;
        if (c >= 2)
            MBARRIER_WAIT_PARITY(smem_base + SM_MBAR + s * 8, ((c >> 1) - 1) & 1);

        const int k0 = c << 6;
        const __nv_bfloat16* src0 = Ahi + (long)mBase * K + k0;
        const __nv_bfloat16* src1 = Alo + (long)mBase * K + k0;
        const __nv_bfloat16* src2 = Bhi + (long)nBase * K + k0;
        const __nv_bfloat16* src3 = Blo + (long)nBase * K + k0;
        const uint32_t stage = smem_base + SM_TILES + s * STAGE_B;
        #pragma unroll
        for (int i = 0; i < 4; i++) {
            const int idx = tid + i * 256;      // 0..1023
            const int r   = idx >> 3;
            const int c16 = idx & 7;
            const long gofs = (long)r * K + (c16 << 3);
            const uint32_t sofs = stage + SMEM_SWIZZLE_128B((r << 7) | (c16 << 4));
            CP_ASYNC16(sofs + 0 * TILE_B, src0 + gofs);
            CP_ASYNC16(sofs + 1 * TILE_B, src1 + gofs);
            CP_ASYNC16(sofs + 2 * TILE_B, src2 + gofs);
            CP_ASYNC16(sofs + 3 * TILE_B, src3 + gofs);
        }
        CP_COMMIT();
        CP_WAIT_0();
        FENCE_PROXY_ASYNC();
        __syncthreads();

        if (wid == 0) {
            const uint64_t dAhi = MAKE_SMEM_DESC(stage + 0 * TILE_B);
            const uint64_t dAlo = MAKE_SMEM_DESC(stage + 1 * TILE_B);
            const uint64_t dBhi = MAKE_SMEM_DESC(stage + 2 * TILE_B);
            const uint64_t dBlo = MAKE_SMEM_DESC(stage + 3 * TILE_B);
            if (elect_one_pred()) {
                #pragma unroll
                for (int kk = 0; kk < 4; kk++) {
                    mma_f16_ss(tmem, dAhi + kk * 2, dBhi + kk * 2, GEMM_IDESC,
                               !(c == 0 && kk == 0));
                    mma_f16_ss(tmem, dAlo + kk * 2, dBhi + kk * 2, GEMM_IDESC, true);
                    mma_f16_ss(tmem, dAhi + kk * 2, dBlo + kk * 2, GEMM_IDESC, true);
                }
                TCGEN05_COMMIT(smem_base + SM_MBAR + s * 8);
            }
        }
    }

    // wait for ALL MMAs (last commit covers all prior)
    {
        const int s_last = (NC - 1) & 1;
        const int nlast  = ((NC - 1 - s_last) >> 1) + 1;
        MBARRIER_WAIT_PARITY(smem_base + SM_MBAR + s_last * 8, (nlast - 1) & 1);
    }
    TCGEN05_FENCE_AFTER();

    // Epilogue: TMEM -> SMEM (row-stage) -> coalesced global
    float* sout = (float*)(smem + SM_TILES);
    if (wid < 4) {
        const int r = (wid << 5) + lid;
        #pragma unroll
        for (int cb = 0; cb < 4; cb++) {
            uint32_t regs[32];
            TCGEN05_LD_X32(regs, tmem + (cb << 5));
            TCGEN05_WAIT_LD();
            #pragma unroll
            for (int j = 0; j < 32; j += 4) {
                float4 v = make_float4(__uint_as_float(regs[j]),
                                       __uint_as_float(regs[j + 1]),
                                       __uint_as_float(regs[j + 2]),
                                       __uint_as_float(regs[j + 3]));
                *(float4*)&sout[r * 132 + (cb << 5) + j] = v;
            }
        }
    }
    __syncthreads();
    if (wid == 0) TCGEN05_DEALLOC(tmem, 128);

    for (int idx = tid; idx < 128 * 32; idx += 256) {
        const int r = idx >> 5;
        const int cc = (idx & 31) << 2;
        float4 v = *(float4*)&sout[r * 132 + cc];
        const long gr = mBase + r;
        const int  gc = nBase + cc;
        float4 bb = *(const float4*)&bias[gc];
        v.x += bb.x; v.y += bb.y; v.z += bb.z; v.w += bb.w;
        if (OP == 1 || OP == 3) {
            if (OP == 1) {
                v.x = gelu_exact(v.x); v.y = gelu_exact(v.y);
                v.z = gelu_exact(v.z); v.w = gelu_exact(v.w);
            }
            const long o = gr * N + gc;
            split_store(Chi, Clo, o + 0, v.x);
            split_store(Chi, Clo, o + 1, v.y);
            split_store(Chi, Clo, o + 2, v.z);
            split_store(Chi, Clo, o + 3, v.w);
        } else if (OP == 2) {
            float4 rr = *(const float4*)&res[gr * N + gc];
            v.x += rr.x; v.y += rr.y; v.z += rr.z; v.w += rr.w;
            *(float4*)&Cf[gr * N + gc] = v;
        } else {
            *(float4*)&Cf[gr * N + gc] = v;
        }
    }

#else  // =================== FFMA fallback (non-103a passes) ===================
    float* As = (float*)smem;                 // [8][128]
    float* Bs = As + 8 * 128;                 // [8][128]

    const int tx = tid & 15;
    const int ty = tid >> 4;
    const int row  = tid >> 1;                // 0..127
    const int kc   = (tid & 1) << 2;          // 0 or 4

    float acc[8][8];
    #pragma unroll
    for (int i = 0; i < 8; i++)
        #pragma unroll
        for (int j = 0; j < 8; j++) acc[i][j] = 0.f;

    for (int k0 = 0; k0 < K; k0 += 8) {
        {
            const long o = (long)(mBase + row) * K + k0 + kc;
            ushort4 h = *(const ushort4*)(Ahi + o);
            ushort4 l = *(const ushort4*)(Alo + o);
            As[(kc + 0) * 128 + row] = __bfloat162float(*(__nv_bfloat16*)&h.x) + __bfloat162float(*(__nv_bfloat16*)&l.x);
            As[(kc + 1) * 128 + row] = __bfloat162float(*(__nv_bfloat16*)&h.y) + __bfloat162float(*(__nv_bfloat16*)&l.y);
            As[(kc + 2) * 128 + row] = __bfloat162float(*(__nv_bfloat16*)&h.z) + __bfloat162float(*(__nv_bfloat16*)&l.z);
            As[(kc + 3) * 128 + row] = __bfloat162float(*(__nv_bfloat16*)&h.w) + __bfloat162float(*(__nv_bfloat16*)&l.w);
        }
        {
            const long o = (long)(nBase + row) * K + k0 + kc;
            ushort4 h = *(const ushort4*)(Bhi + o);
            ushort4 l = *(const ushort4*)(Blo + o);
            Bs[(kc + 0) * 128 + row] = __bfloat162float(*(__nv_bfloat16*)&h.x) + __bfloat162float(*(__nv_bfloat16*)&l.x);
            Bs[(kc + 1) * 128 + row] = __bfloat162float(*(__nv_bfloat16*)&h.y) + __bfloat162float(*(__nv_bfloat16*)&l.y);
            Bs[(kc + 2) * 128 + row] = __bfloat162float(*(__nv_bfloat16*)&h.z) + __bfloat162float(*(__nv_bfloat16*)&l.z);
            Bs[(kc + 3) * 128 + row] = __bfloat162float(*(__nv_bfloat16*)&h.w) + __bfloat162float(*(__nv_bfloat16*)&l.w);
        }
        __syncthreads();

        #pragma unroll
        for (int k = 0; k < 8; k++) {
            float a[8], bb[8];
            #pragma unroll
            for (int i = 0; i < 8; i++) a[i]  = As[k * 128 + ty * 8 + i];
            #pragma unroll
            for (int j = 0; j < 8; j++) bb[j] = Bs[k * 128 + tx * 8 + j];
            #pragma unroll
            for (int i = 0; i < 8; i++)
                #pragma unroll
                for (int j = 0; j < 8; j++)
                    acc[i][j] = fmaf(a[i], bb[j], acc[i][j]);
        }
        __syncthreads();
    }

    #pragma unroll
    for (int i = 0; i < 8; i++) {
        const long gr = mBase + ty * 8 + i;
        #pragma unroll
        for (int j = 0; j < 8; j++) {
            const int gc = nBase + tx * 8 + j;
            float v = acc[i][j] + bias[gc];
            if (OP == 1) {
                v = gelu_exact(v);
                split_store(Chi, Clo, gr * N + gc, v);
            } else if (OP == 3) {
                split_store(Chi, Clo, gr * N + gc, v);
            } else if (OP == 2) {
                Cf[gr * N + gc] = v + res[gr * N + gc];
            } else {
                Cf[gr * N + gc] = v;
            }
        }
    }
#endif
}

// ======================= tcgen05 causal flash attention =======================
// 64-key tiles, 99 KB SMEM -> 2 CTAs/SM. CTA = (128 q rows, head, batch), qt reversed.
// TMEM: S cols 0..63, O cols 64..127 (alloc 128).
// cp.async for all loads; single K buffer (prefetch after S-MMA frees it);
// V staged into dead P region, transposed in SMEM (R4-validated PV layout);
// softmax + O accumulation split across all 8 warps (col halves of 32).
#define A_TMEMPTR 0
#define A_MBAR0   8
#define A_MBAR1   16
#define A_SMX     32            // float[256]
#define A_SLS     1056          // float[256]
#define A_Q       3072          // hi 16K, lo at +16384
#define A_K       35840         // hi 8K, lo at +8192
#define A_VT      52224         // hi 8K, lo at +8192
#define A_P       68608         // hi 16K, lo at +16384 ; V staging: hi +0, lo +8192
#define ATTN_SMEM 101376

#if HAS_TCGEN05
__device__ __forceinline__ void attn_issue_S(uint32_t tmem, uint32_t sb) {
    const uint64_t dQh = MAKE_SMEM_DESC(sb + A_Q);
    const uint64_t dQl = MAKE_SMEM_DESC(sb + A_Q + 16384);
    const uint64_t dKh = MAKE_SMEM_DESC(sb + A_K);
    const uint64_t dKl = MAKE_SMEM_DESC(sb + A_K + 8192);
    #pragma unroll
    for (int kk = 0; kk < 4; kk++) {
        mma_f16_ss(tmem, dQh + kk * 2, dKh + kk * 2, ATTN_IDESC, kk != 0);
        mma_f16_ss(tmem, dQl + kk * 2, dKh + kk * 2, ATTN_IDESC, true);
        mma_f16_ss(tmem, dQh + kk * 2, dKl + kk * 2, ATTN_IDESC, true);
    }
}
__device__ __forceinline__ void attn_issue_PV(uint32_t tmem, uint32_t sb) {
    const uint64_t dPh = MAKE_SMEM_DESC(sb + A_P);
    const uint64_t dPl = MAKE_SMEM_DESC(sb + A_P + 16384);
    const uint64_t dVh = MAKE_SMEM_DESC(sb + A_VT);
    const uint64_t dVl = MAKE_SMEM_DESC(sb + A_VT + 8192);
    #pragma unroll
    for (int kk = 0; kk < 4; kk++) {
        mma_f16_ss(tmem + 64, dPh + kk * 2, dVh + kk * 2, ATTN_IDESC, kk != 0);
        mma_f16_ss(tmem + 64, dPl + kk * 2, dVh + kk * 2, ATTN_IDESC, true);
        mma_f16_ss(tmem + 64, dPh + kk * 2, dVl + kk * 2, ATTN_IDESC, true);
    }
}
#endif

__global__ __launch_bounds__(256, 2) void attn_tc(
    const __nv_bfloat16* __restrict__ qkv_hi,
    const __nv_bfloat16* __restrict__ qkv_lo,
    __nv_bfloat16* __restrict__ ohi,
    __nv_bfloat16* __restrict__ olo)
{
    extern __shared__ __align__(1024) char smem[];
    const int tid  = threadIdx.x;
    const int wid  = tid >> 5;
    const int lid  = tid & 31;
    const int qt   = gridDim.x - 1 - blockIdx.x;   // reversed: long CTAs first
    const int head = blockIdx.y;
    const int bat  = blockIdx.z;
    const long tok0 = (long)bat * SEQ;

#if HAS_TCGEN05
    const uint32_t sb = smem_u32_of(smem);
    float* smx = (float*)(smem + A_SMX);
    float* sls = (float*)(smem + A_SLS);
    if (wid == 0) {
        TCGEN05_ALLOC(sb + A_TMEMPTR, 128);
        TCGEN05_RELINQUISH();
    }
    if (tid == 0) {
        MBARRIER_INIT(sb + A_MBAR0, 1);
        MBARRIER_INIT(sb + A_MBAR1, 1);
    }
    __syncthreads();
    uint32_t tmem;
    asm volatile("ld.shared.b32 %0, [%1];" : "=r"(tmem) : "r"(sb + A_TMEMPTR));

    // Q tile (128 x 64 hi/lo) + K tile 0 (64 keys) via cp.async
    #pragma unroll
    for (int i = 0; i < 4; i++) {
        const int idx = tid + i * 256;
        const int r = idx >> 3, c8 = idx & 7;
        const uint32_t sofs = SMEM_SWIZZLE_128B((r << 7) | (c8 << 4));
        const long gq = (tok0 + qt * 128 + r) * (long)QKVW + head * 64 + (c8 << 3);
        CP_ASYNC16(sb + A_Q + sofs,         qkv_hi + gq);
        CP_ASYNC16(sb + A_Q + 16384 + sofs, qkv_lo + gq);
    }
    #pragma unroll
    for (int i = 0; i < 2; i++) {
        const int idx = tid + i * 256;       // 0..511
        const int r = idx >> 3, c8 = idx & 7;
        const uint32_t sofs = SMEM_SWIZZLE_128B((r << 7) | (c8 << 4));
        const long gk = (tok0 + r) * (long)QKVW + 1024 + head * 64 + (c8 << 3);
        CP_ASYNC16(sb + A_K + sofs,        qkv_hi + gk);
        CP_ASYNC16(sb + A_K + 8192 + sofs, qkv_lo + gk);
    }
    CP_COMMIT();
    CP_WAIT_0();
    FENCE_PROXY_ASYNC();
    __syncthreads();
    if (wid == 0 && elect_one_pred()) {
        attn_issue_S(tmem, sb);
        TCGEN05_COMMIT(sb + A_MBAR0);
    }

    const int half = wid >> 2;                 // column half (32 key-cols / 32 hd-cols)
    const int row  = ((wid & 3) << 5) + lid;   // q row
    const int grow = qt * 128 + row;
    const int nkt  = 2 * qt + 2;
    const float SCL = 0.125f * 1.4426950408889634f;  // fold 1/sqrt(hd) * log2(e)

    float o[32];
    #pragma unroll
    for (int j = 0; j < 32; j++) o[j] = 0.f;
    float m = -1e30f, l = 0.f;

    for (int kt = 0; kt < nkt; kt++) {
        const bool pre = (kt + 1 < nkt);

        // stage V(kt) into P region (dead after previous PV wait)
        #pragma unroll
        for (int i = 0; i < 2; i++) {
            const int idx = tid + i * 256;
            const int r = idx >> 3, c8 = idx & 7;
            const uint32_t sofs = SMEM_SWIZZLE_128B((r << 7) | (c8 << 4));
            const long gv = (tok0 + kt * 64 + r) * (long)QKVW + 2048 + head * 64 + (c8 << 3);
            CP_ASYNC16(sb + A_P + sofs,        qkv_hi + gv);
            CP_ASYNC16(sb + A_P + 8192 + sofs, qkv_lo + gv);
        }
        CP_COMMIT();   // group V

        // wait S(kt) -> K buffer free -> prefetch K(kt+1)
        MBARRIER_WAIT_PARITY(sb + A_MBAR0, kt & 1);
        TCGEN05_FENCE_AFTER();
        if (pre) {
            #pragma unroll
            for (int i = 0; i < 2; i++) {
                const int idx = tid + i * 256;
                const int r = idx >> 3, c8 = idx & 7;
                const uint32_t sofs = SMEM_SWIZZLE_128B((r << 7) | (c8 << 4));
                const long gk = (tok0 + (kt + 1) * 64 + r) * (long)QKVW + 1024 + head * 64 + (c8 << 3);
                CP_ASYNC16(sb + A_K + sofs,        qkv_hi + gk);
                CP_ASYNC16(sb + A_K + 8192 + sofs, qkv_lo + gk);
            }
            CP_COMMIT();   // group K
        }

        // pull this warp's 32 S columns
        uint32_t r0[32];
        TCGEN05_LD_X32(r0, tmem + half * 32);
        TCGEN05_WAIT_LD();

        // V staged complete (K group may remain in flight)
        if (pre) CP_WAIT_1(); else CP_WAIT_0();
        __syncthreads();   // S1: staged V visible

        // transpose staged V -> Vt[hd][key] (hi + lo)
        #pragma unroll
        for (int i = 0; i < 8; i++) {
            const int idx = tid + i * 256;        // 0..2047
            const int c  = idx & 63;              // hd
            const int kp = idx >> 6;              // key pair 0..31
            const int so0 = SMEM_SWIZZLE_128B(((2 * kp)     << 7) | (c << 1));
            const int so1 = SMEM_SWIZZLE_128B(((2 * kp + 1) << 7) | (c << 1));
            const int dd  = SMEM_SWIZZLE_128B((c << 7) | (kp << 2));
            uint32_t a = *(const uint16_t*)(smem + A_P + so0);
            uint32_t b = *(const uint16_t*)(smem + A_P + so1);
            *(uint32_t*)(smem + A_VT + dd) = a | (b << 16);
            a = *(const uint16_t*)(smem + A_P + 8192 + so0);
            b = *(const uint16_t*)(smem + A_P + 8192 + so1);
            *(uint32_t*)(smem + A_VT + 8192 + dd) = a | (b << 16);
        }

        float s[32];
        #pragma unroll
        for (int j = 0; j < 32; j++) s[j] = __uint_as_float(r0[j]) * SCL;

        if (kt >= 2 * qt) {   // diagonal tiles: causal mask
            const int jbase = kt * 64 + half * 32;
            #pragma unroll
            for (int j = 0; j < 32; j++)
                if (jbase + j > grow) s[j] = -1e30f;
        }
        float lmx = -1e30f;
        #pragma unroll
        for (int j = 0; j < 32; j++) lmx = fmaxf(lmx, s[j]);
        smx[half * 128 + row] = lmx;
        __syncthreads();   // S2: smx visible; transpose reads done

        const float mnew = fmaxf(m, fmaxf(smx[row], smx[128 + row]));
        const float scl  = exp2f(m - mnew);
        m = mnew;
        float ls = 0.f;
        #pragma unroll
        for (int j = 0; j < 32; j++) { s[j] = exp2f(s[j] - mnew); ls += s[j]; }
        sls[half * 128 + row] = ls;

        // store this half's P (hi/lo), overwriting staging
        #pragma unroll
        for (int j8 = 0; j8 < 4; j8++) {
            __align__(16) __nv_bfloat16 hb[8], lb[8];
            #pragma unroll
            for (int j = 0; j < 8; j++) {
                const float v = s[(j8 << 3) + j];
                const __nv_bfloat16 h = __float2bfloat16(v);
                hb[j] = h;
                lb[j] = __float2bfloat16(v - __bfloat162float(h));
            }
            const int so = SMEM_SWIZZLE_128B((row << 7) | (half << 6) | (j8 << 4));
            *(uint4*)(smem + A_P + so)         = *(uint4*)hb;
            *(uint4*)(smem + A_P + 16384 + so) = *(uint4*)lb;
        }
        FENCE_PROXY_ASYNC();
        __syncthreads();   // S3: P + Vt + sls visible

        l = l * scl + sls[row] + sls[128 + row];

        if (wid == 0 && elect_one_pred()) {
            attn_issue_PV(tmem, sb);
            TCGEN05_COMMIT(sb + A_MBAR1);
        }

        // issue S(kt+1) while PV(kt) runs
        if (pre) {
            CP_WAIT_0();
            FENCE_PROXY_ASYNC();
            __syncthreads();   // S4: K(kt+1) visible
            if (wid == 0 && elect_one_pred()) {
                attn_issue_S(tmem, sb);
                TCGEN05_COMMIT(sb + A_MBAR0);
            }
        }

        // wait PV(kt), accumulate O (this half's 32 hd cols)
        MBARRIER_WAIT_PARITY(sb + A_MBAR1, kt & 1);
        TCGEN05_FENCE_AFTER();
        uint32_t p0[32];
        TCGEN05_LD_X32(p0, tmem + 64 + half * 32);
        TCGEN05_WAIT_LD();
        #pragma unroll
        for (int j = 0; j < 32; j++) o[j] = o[j] * scl + __uint_as_float(p0[j]);
    }

    // epilogue: each warp writes its 32 hd cols for its rows
    {
        const float invl = 1.0f / l;
        const long gofs = (tok0 + grow) * (long)DMODEL + head * 64 + half * 32;
        #pragma unroll
        for (int j8 = 0; j8 < 4; j8++) {
            __align__(16) __nv_bfloat16 hb[8], lb[8];
            #pragma unroll
            for (int j = 0; j < 8; j++) {
                const float v = o[(j8 << 3) + j] * invl;
                const __nv_bfloat16 h = __float2bfloat16(v);
                hb[j] = h;
                lb[j] = __float2bfloat16(v - __bfloat162float(h));
            }
            *(uint4*)(ohi + gofs + (j8 << 3)) = *(uint4*)hb;
            *(uint4*)(olo + gofs + (j8 << 3)) = *(uint4*)lb;
        }
    }
    __syncthreads();
    if (wid == 0) TCGEN05_DEALLOC(tmem, 128);

#else  // =================== compile-only FFMA fallback ===================
    if (tid < 128) {
        const int grow2 = qt * 128 + tid;
        const long qofs = (tok0 + grow2) * (long)QKVW + head * 64;
        float q[64], o2[64];
        #pragma unroll
        for (int c = 0; c < 64; c++) {
            q[c] = (__bfloat162float(qkv_hi[qofs + c]) +
                    __bfloat162float(qkv_lo[qofs + c])) * 0.125f;
            o2[c] = 0.f;
        }
        float m2 = -1e30f, l2 = 0.f;
        for (int j = 0; j <= grow2; j++) {
            const long kofs = (tok0 + j) * (long)QKVW + 1024 + head * 64;
            float s = 0.f;
            for (int c = 0; c < 64; c++)
                s += q[c] * (__bfloat162float(qkv_hi[kofs + c]) +
                             __bfloat162float(qkv_lo[kofs + c]));
            const float mnew = fmaxf(m2, s);
            const float scf = expf(m2 - mnew);
            const float p = expf(s - mnew);
            l2 = l2 * scf + p;
            m2 = mnew;
            const long vofs = kofs + 1024;
            for (int c = 0; c < 64; c++)
                o2[c] = o2[c] * scf + p * (__bfloat162float(qkv_hi[vofs + c]) +
                                           __bfloat162float(qkv_lo[vofs + c]));
        }
        const long gofs = (tok0 + grow2) * (long)DMODEL + head * 64;
        for (int c = 0; c < 64; c++)
            split_store(ohi, olo, gofs + c, o2[c] / l2);
    }
#endif
}

// ======================= driver =======================
extern "C" void kernel_launch(void* const* d_in, const int* in_sizes, int n_in,
                              void* d_out, int out_size)
{
    const float* x    = (const float*)d_in[0];
    const float* g1   = (const float*)d_in[1];
    const float* b1   = (const float*)d_in[2];
    const float* Wqkv = (const float*)d_in[3];
    const float* bqkv = (const float*)d_in[4];
    const float* Wo   = (const float*)d_in[5];
    const float* bo   = (const float*)d_in[6];
    const float* g2   = (const float*)d_in[7];
    const float* b2   = (const float*)d_in[8];
    const float* W1   = (const float*)d_in[9];
    const float* b1f  = (const float*)d_in[10];
    const float* W2   = (const float*)d_in[11];
    const float* b2f  = (const float*)d_in[12];
    float* out = (float*)d_out;

    float *x2;
    __nv_bfloat16 *qkv_hi, *qkv_lo;
    __nv_bfloat16 *h_hi, *h_lo, *attn_hi, *attn_lo, *hh_hi, *hh_lo, *ff_hi, *ff_lo;
    __nv_bfloat16 *WqkvT_hi, *WqkvT_lo, *WoT_hi, *WoT_lo, *W1T_hi, *W1T_lo, *W2T_hi, *W2T_lo;
    cudaGetSymbolAddress((void**)&x2,       g_x2);
    cudaGetSymbolAddress((void**)&qkv_hi,   g_qkv_hi);
    cudaGetSymbolAddress((void**)&qkv_lo,   g_qkv_lo);
    cudaGetSymbolAddress((void**)&h_hi,     g_h_hi);
    cudaGetSymbolAddress((void**)&h_lo,     g_h_lo);
    cudaGetSymbolAddress((void**)&attn_hi,  g_attn_hi);
    cudaGetSymbolAddress((void**)&attn_lo,  g_attn_lo);
    cudaGetSymbolAddress((void**)&hh_hi,    g_hh_hi);
    cudaGetSymbolAddress((void**)&hh_lo,    g_hh_lo);
    cudaGetSymbolAddress((void**)&ff_hi,    g_ff_hi);
    cudaGetSymbolAddress((void**)&ff_lo,    g_ff_lo);
    cudaGetSymbolAddress((void**)&WqkvT_hi, g_WqkvT_hi);
    cudaGetSymbolAddress((void**)&WqkvT_lo, g_WqkvT_lo);
    cudaGetSymbolAddress((void**)&WoT_hi,   g_WoT_hi);
    cudaGetSymbolAddress((void**)&WoT_lo,   g_WoT_lo);
    cudaGetSymbolAddress((void**)&W1T_hi,   g_W1T_hi);
    cudaGetSymbolAddress((void**)&W1T_lo,   g_W1T_lo);
    cudaGetSymbolAddress((void**)&W2T_hi,   g_W2T_hi);
    cudaGetSymbolAddress((void**)&W2T_lo,   g_W2T_lo);

    cudaFuncSetAttribute(attn_tc,    cudaFuncAttributeMaxDynamicSharedMemorySize, ATTN_SMEM);
    cudaFuncSetAttribute(gemm_tc<1>, cudaFuncAttributeMaxDynamicSharedMemorySize, GEMM_SMEM);
    cudaFuncSetAttribute(gemm_tc<2>, cudaFuncAttributeMaxDynamicSharedMemorySize, GEMM_SMEM);
    cudaFuncSetAttribute(gemm_tc<3>, cudaFuncAttributeMaxDynamicSharedMemorySize, GEMM_SMEM);

    // weight conversion + transpose (K-major for MMA B operand), 64x64 tiles
    wtrans_kernel<<<dim3(QKVW / 64, DMODEL / 64), 256>>>(Wqkv, WqkvT_hi, WqkvT_lo, DMODEL, QKVW);
    wtrans_kernel<<<dim3(DMODEL / 64, DMODEL / 64), 256>>>(Wo, WoT_hi, WoT_lo, DMODEL, DMODEL);
    wtrans_kernel<<<dim3(FFDIM / 64, DMODEL / 64), 256>>>(W1, W1T_hi, W1T_lo, DMODEL, FFDIM);
    wtrans_kernel<<<dim3(DMODEL / 64, FFDIM / 64), 256>>>(W2, W2T_hi, W2T_lo, FFDIM, DMODEL);

    // LN1 -> hi/lo
    ln_kernel<<<NTOK, 256>>>(x, g1, b1, h_hi, h_lo);
    // QKV projection -> bf16 hi/lo (attention input)
    gemm_tc<3><<<dim3(QKVW / 128, NTOK / 128), 256, GEMM_SMEM>>>(
        h_hi, h_lo, WqkvT_hi, WqkvT_lo, bqkv, nullptr, nullptr, qkv_hi, qkv_lo, QKVW, DMODEL);
    // causal attention (tcgen05, 64-key pipelined, occ 2) -> hi/lo
    attn_tc<<<dim3(SEQ / 128, NH, BATCH), 256, ATTN_SMEM>>>(qkv_hi, qkv_lo, attn_hi, attn_lo);
    // output projection + residual -> x2 (fp32)
    gemm_tc<2><<<dim3(DMODEL / 128, NTOK / 128), 256, GEMM_SMEM>>>(
        attn_hi, attn_lo, WoT_hi, WoT_lo, bo, x, x2, nullptr, nullptr, DMODEL, DMODEL);
    // LN2 -> hi/lo
    ln_kernel<<<NTOK, 256>>>(x2, g2, b2, hh_hi, hh_lo);
    // FF1 + GELU -> hi/lo
    gemm_tc<1><<<dim3(FFDIM / 128, NTOK / 128), 256, GEMM_SMEM>>>(
        hh_hi, hh_lo, W1T_hi, W1T_lo, b1f, nullptr, nullptr, ff_hi, ff_lo, FFDIM, DMODEL);
    // FF2 + residual -> out (fp32)
    gemm_tc<2><<<dim3(DMODEL / 128, NTOK / 128), 256, GEMM_SMEM>>>(
        ff_hi, ff_lo, W2T_hi, W2T_lo, b2f, x2, out, nullptr, nullptr, DMODEL, FFDIM);
}

// round 8
// speedup vs baseline: 5.7283x; 1.2567x over previous
#include <cuda_runtime.h>
#include <cuda_bf16.h>
#include <math.h>
#include <stdint.h>

// Problem dims (fixed by the reference)
#define NTOK   4096      // B*T = 2*2048
#define SEQ    2048
#define BATCH  2
#define DMODEL 1024
#define NH     16
#define HDIM   64
#define FFDIM  4096
#define QKVW   3072      // 3*DMODEL

// tcgen05 only exists in the arch-specific (sm_103a / sm_103f) compilation pass.
#if defined(__CUDA_ARCH__) && (__CUDA_ARCH__ == 1030) && \
    (defined(__CUDA_ARCH_FEAT_SM103_ALL) || defined(__CUDA_ARCH_SPECIFIC__) || \
     defined(__CUDA_ARCH_FAMILY_SPECIFIC__))
#define HAS_TCGEN05 1
#else
#define HAS_TCGEN05 0
#endif

// cp.async works on all passes (sm_80+)
#define CP_ASYNC16(smem_u32, gptr) \
    asm volatile("cp.async.cg.shared.global [%0], [%1], 16;" \
                 :: "r"((uint32_t)(smem_u32)), "l"(gptr) : "memory")
#define CP_COMMIT() asm volatile("cp.async.commit_group;" ::: "memory")
#define CP_WAIT_0() asm volatile("cp.async.wait_group 0;" ::: "memory")
#define CP_WAIT_1() asm volatile("cp.async.wait_group 1;" ::: "memory")

__device__ __forceinline__ uint32_t smem_u32_of(const void* p) {
    uint32_t a;
    asm("{ .reg .u64 t; cvta.to.shared.u64 t, %1; cvt.u32.u64 %0, t; }" : "=r"(a) : "l"(p));
    return a;
}

#if HAS_TCGEN05
// ======================= PTX helpers (arch-specific pass only) =======================
__device__ __forceinline__ uint32_t elect_one_pred() {
    uint32_t pred;
    asm volatile("{\n\t.reg .pred p;\n\telect.sync _|p, 0xFFFFFFFF;\n\tselp.b32 %0, 1, 0, p;\n\t}"
                 : "=r"(pred));
    return pred;
}

static constexpr uint64_t SMEM_DESC_BASE_SW128 =
    (uint64_t(2) << 61) | (uint64_t(1) << 46) | (uint64_t(64) << 32) | (uint64_t(1) << 16);
#define MAKE_SMEM_DESC(base_addr) \
    (SMEM_DESC_BASE_SW128 | ((uint64_t)((base_addr) >> 4) & 0x3FFF))

#define TCGEN05_ALLOC(sa, n) \
    asm volatile("tcgen05.alloc.cta_group::1.sync.aligned.shared::cta.b32 [%0], %1;" \
                 :: "r"((uint32_t)(sa)), "r"((uint32_t)(n)) : "memory")
#define TCGEN05_DEALLOC(t, n) \
    asm volatile("tcgen05.dealloc.cta_group::1.sync.aligned.b32 %0, %1;" :: "r"(t), "r"((uint32_t)(n)))
#define TCGEN05_RELINQUISH() \
    asm volatile("tcgen05.relinquish_alloc_permit.cta_group::1.sync.aligned;")
#define TCGEN05_COMMIT(mb) \
    asm volatile("tcgen05.commit.cta_group::1.mbarrier::arrive::one.shared::cluster.b64 [%0];" \
                 :: "r"((uint32_t)(mb)) : "memory")
#define TCGEN05_FENCE_AFTER() asm volatile("tcgen05.fence::after_thread_sync;" ::: "memory")
#define TCGEN05_WAIT_LD() asm volatile("tcgen05.wait::ld.sync.aligned;" ::: "memory")
#define FENCE_PROXY_ASYNC() asm volatile("fence.proxy.async.shared::cta;" ::: "memory")

#define MBARRIER_INIT(mb, cnt) \
    asm volatile("mbarrier.init.shared.b64 [%0], %1;" :: "r"((uint32_t)(mb)), "r"((uint32_t)(cnt)) : "memory")

#define MBARRIER_WAIT_PARITY(mb, par) do { \
    uint32_t _mb = (uint32_t)(mb), _p = (uint32_t)(par), _d; \
    asm volatile("{\n\t.reg .pred p;\n\t" \
        "mbarrier.try_wait.parity.acquire.cta.shared::cta.b64 p, [%1], %2;\n\t" \
        "selp.b32 %0, 1, 0, p;\n\t}" : "=r"(_d) : "r"(_mb), "r"(_p) : "memory"); \
    if (!_d) { \
        asm volatile("{\n\t.reg .pred P1;\n\t" \
            "WL_%=:\n\t" \
            "mbarrier.try_wait.parity.acquire.cta.shared::cta.b64 P1, [%0], %1, 0x989680;\n\t" \
            "@P1 bra.uni WD_%=;\n\t" \
            "bra.uni WL_%=;\n\t" \
            "WD_%=:\n\t}" :: "r"(_mb), "r"(_p) : "memory"); \
    } \
} while (0)

#define TCGEN05_LD_X32(r, ta) \
    asm volatile("tcgen05.ld.sync.aligned.32x32b.x32.b32 " \
        "{%0, %1, %2, %3, %4, %5, %6, %7, %8, %9, %10, %11, %12, %13, %14, %15, " \
        "%16, %17, %18, %19, %20, %21, %22, %23, %24, %25, %26, %27, %28, %29, %30, %31}, [%32];" \
        : "=r"((r)[0]), "=r"((r)[1]), "=r"((r)[2]), "=r"((r)[3]), \
          "=r"((r)[4]), "=r"((r)[5]), "=r"((r)[6]), "=r"((r)[7]), \
          "=r"((r)[8]), "=r"((r)[9]), "=r"((r)[10]), "=r"((r)[11]), \
          "=r"((r)[12]), "=r"((r)[13]), "=r"((r)[14]), "=r"((r)[15]), \
          "=r"((r)[16]), "=r"((r)[17]), "=r"((r)[18]), "=r"((r)[19]), \
          "=r"((r)[20]), "=r"((r)[21]), "=r"((r)[22]), "=r"((r)[23]), \
          "=r"((r)[24]), "=r"((r)[25]), "=r"((r)[26]), "=r"((r)[27]), \
          "=r"((r)[28]), "=r"((r)[29]), "=r"((r)[30]), "=r"((r)[31]) \
        : "r"(ta))

// cg1 kind::f16 SS-mode MMA (A and B both in SMEM, bf16 in / fp32 accum)
__device__ __forceinline__ void mma_f16_ss(uint32_t d, uint64_t ad, uint64_t bd,
                                           uint32_t idesc, bool acc) {
    uint32_t en = acc ? 1u : 0u;
    asm volatile(
        "{\n\t.reg .pred p;\n\tsetp.ne.u32 p, %5, 0;\n\t"
        "tcgen05.mma.cta_group::1.kind::f16 [%0], %1, %2, %3, {%4, %4, %4, %4}, p;\n\t}"
        :: "r"(d), "l"(ad), "l"(bd), "r"(idesc), "r"(0u), "r"(en) : "memory");
}

// idesc: fp32 accum, bf16 A/B, M=128, N=128, K-major both
static constexpr uint32_t GEMM_IDESC =
    (1u << 4) | (1u << 7) | (1u << 10) | ((128u / 8u) << 17) | ((128u / 16u) << 24);
// idesc for attention MMAs: M=128, N=64, K-major both (validated in R4)
static constexpr uint32_t ATTN_IDESC =
    (1u << 4) | (1u << 7) | (1u << 10) | ((64u / 8u) << 17) | ((128u / 16u) << 24);
#endif  // HAS_TCGEN05

#define SMEM_SWIZZLE_128B(off) ((off) ^ (((off) >> 3) & 0x70))

// ======================= scratch (device globals) =======================
__device__ float g_x2  [NTOK * DMODEL];          // residual after attn proj
__device__ __nv_bfloat16 g_qkv_hi[NTOK * QKVW],  g_qkv_lo[NTOK * QKVW];
__device__ __nv_bfloat16 g_h_hi  [NTOK * DMODEL], g_h_lo  [NTOK * DMODEL];
__device__ __nv_bfloat16 g_attn_hi[NTOK * DMODEL], g_attn_lo[NTOK * DMODEL];
__device__ __nv_bfloat16 g_hh_hi [NTOK * DMODEL], g_hh_lo [NTOK * DMODEL];
__device__ __nv_bfloat16 g_ff_hi [NTOK * FFDIM],  g_ff_lo [NTOK * FFDIM];
__device__ __nv_bfloat16 g_WqkvT_hi[QKVW * DMODEL],  g_WqkvT_lo[QKVW * DMODEL];
__device__ __nv_bfloat16 g_WoT_hi [DMODEL * DMODEL], g_WoT_lo [DMODEL * DMODEL];
__device__ __nv_bfloat16 g_W1T_hi [FFDIM * DMODEL],  g_W1T_lo [FFDIM * DMODEL];
__device__ __nv_bfloat16 g_W2T_hi [DMODEL * FFDIM],  g_W2T_lo [DMODEL * FFDIM];

__device__ __forceinline__ void split_store(__nv_bfloat16* hi, __nv_bfloat16* lo,
                                            long ofs, float v) {
    __nv_bfloat16 h = __float2bfloat16(v);
    hi[ofs] = h;
    lo[ofs] = __float2bfloat16(v - __bfloat162float(h));
}
__device__ __forceinline__ uint32_t pack2bf(float a, float b) {
    __nv_bfloat162 t;
    t.x = __float2bfloat16(a);
    t.y = __float2bfloat16(b);
    return *(uint32_t*)&t;
}
__device__ __forceinline__ float gelu_exact(float x) {
    return 0.5f * x * (1.0f + erff(x * 0.70710678118654752f));
}

// ======================= LayerNorm -> bf16 hi/lo planes =======================
__global__ __launch_bounds__(256) void ln_kernel(const float* __restrict__ x,
                                                 const float* __restrict__ g,
                                                 const float* __restrict__ b,
                                                 __nv_bfloat16* __restrict__ yhi,
                                                 __nv_bfloat16* __restrict__ ylo)
{
    const int row = blockIdx.x;
    const int tid = threadIdx.x;
    const float* xr = x + (long)row * DMODEL;
    float4 v = *(const float4*)(xr + tid * 4);

    float s  = v.x + v.y + v.z + v.w;
    float sq = v.x*v.x + v.y*v.y + v.z*v.z + v.w*v.w;
    #pragma unroll
    for (int off = 16; off > 0; off >>= 1) {
        s  += __shfl_xor_sync(0xffffffffu, s,  off);
        sq += __shfl_xor_sync(0xffffffffu, sq, off);
    }
    __shared__ float reds[8], redq[8];
    const int wid = tid >> 5;
    if ((tid & 31) == 0) { reds[wid] = s; redq[wid] = sq; }
    __syncthreads();
    float st = 0.f, qt = 0.f;
    #pragma unroll
    for (int w = 0; w < 8; w++) { st += reds[w]; qt += redq[w]; }

    const float mu   = st * (1.0f / DMODEL);
    const float var  = qt * (1.0f / DMODEL) - mu * mu;
    const float rstd = rsqrtf(var + 1e-5f);

    float4 gv = *(const float4*)(g + tid * 4);
    float4 bv = *(const float4*)(b + tid * 4);
    float o0 = (v.x - mu) * rstd * gv.x + bv.x;
    float o1 = (v.y - mu) * rstd * gv.y + bv.y;
    float o2 = (v.z - mu) * rstd * gv.z + bv.z;
    float o3 = (v.w - mu) * rstd * gv.w + bv.w;
    const long base = (long)row * DMODEL + tid * 4;
    split_store(yhi, ylo, base + 0, o0);
    split_store(yhi, ylo, base + 1, o1);
    split_store(yhi, ylo, base + 2, o2);
    split_store(yhi, ylo, base + 3, o3);
}

// ============== weight transpose + bf16 hi/lo: W[K,N] -> T[N,K] (coalesced) ==============
__global__ __launch_bounds__(256) void wtrans_kernel(const float* __restrict__ W,
                                                     __nv_bfloat16* __restrict__ Thi,
                                                     __nv_bfloat16* __restrict__ Tlo,
                                                     int K, int N)
{
    __shared__ float tile[64][65];
    const int nb = blockIdx.x * 64;
    const int kb = blockIdx.y * 64;
    const int tid = threadIdx.x;
    #pragma unroll
    for (int i = 0; i < 4; i++) {
        const int idx = tid + i * 256;       // 0..1023
        const int k = idx >> 4;
        const int n4 = (idx & 15) << 2;
        float4 v = *(const float4*)&W[(long)(kb + k) * N + nb + n4];
        tile[k][n4 + 0] = v.x;
        tile[k][n4 + 1] = v.y;
        tile[k][n4 + 2] = v.z;
        tile[k][n4 + 3] = v.w;
    }
    __syncthreads();
    #pragma unroll
    for (int i = 0; i < 4; i++) {
        const int idx = tid + i * 256;       // 0..1023
        const int n  = idx >> 4;
        const int kq = (idx & 15) << 2;      // 4 consecutive K per thread
        float v0 = tile[kq + 0][n], v1 = tile[kq + 1][n];
        float v2 = tile[kq + 2][n], v3 = tile[kq + 3][n];
        const long ofs = (long)(nb + n) * K + kb + kq;
        uint2 hp, lp;
        hp.x = pack2bf(v0, v1); hp.y = pack2bf(v2, v3);
        __nv_bfloat162* h01 = (__nv_bfloat162*)&hp.x;
        __nv_bfloat162* h23 = (__nv_bfloat162*)&hp.y;
        lp.x = pack2bf(v0 - __bfloat162float(h01->x), v1 - __bfloat162float(h01->y));
        lp.y = pack2bf(v2 - __bfloat162float(h23->x), v3 - __bfloat162float(h23->y));
        *(uint2*)(Thi + ofs) = hp;
        *(uint2*)(Tlo + ofs) = lp;
    }
}

// ======================= GEMM (3-stage cp.async pipeline) =======================
// C[M,N] = A[M,K] @ B[N,K]^T with A,B given as bf16 hi/lo planes (K-major).
// OP: 0 = +bias -> fp32 ; 1 = +bias, GELU -> bf16 hi/lo ; 2 = +bias +res -> fp32 ;
//     3 = +bias -> bf16 hi/lo
#define SM_TMEMPTR 0
#define SM_MBAR    16          // three mbarriers at 16, 24, 32
#define SM_TILES   1024
#define TILE_B     16384       // 128 rows x 128 bytes (64 bf16)
#define STAGE_B    (4 * TILE_B)
#define GEMM_SMEM  (SM_TILES + 3 * STAGE_B)

template<int OP>
__global__ __launch_bounds__(256, 1) void gemm_tc(
    const __nv_bfloat16* __restrict__ Ahi, const __nv_bfloat16* __restrict__ Alo,
    const __nv_bfloat16* __restrict__ Bhi, const __nv_bfloat16* __restrict__ Blo,
    const float* __restrict__ bias, const float* __restrict__ res,
    float* __restrict__ Cf,
    __nv_bfloat16* __restrict__ Chi, __nv_bfloat16* __restrict__ Clo,
    int N, int K)
{
    extern __shared__ __align__(1024) char smem[];
    const int tid = threadIdx.x;
    const int mBase = blockIdx.y * 128;
    const int nBase = blockIdx.x * 128;

#if HAS_TCGEN05
    const uint32_t smem_base = smem_u32_of(smem);
    const int wid = tid >> 5;
    const int lid = tid & 31;

    if (wid == 0) {
        TCGEN05_ALLOC(smem_base + SM_TMEMPTR, 128);
        TCGEN05_RELINQUISH();
    }
    if (tid == 0) {
        MBARRIER_INIT(smem_base + SM_MBAR + 0,  1);
        MBARRIER_INIT(smem_base + SM_MBAR + 8,  1);
        MBARRIER_INIT(smem_base + SM_MBAR + 16, 1);
    }
    __syncthreads();
    uint32_t tmem;
    asm volatile("ld.shared.b32 %0, [%1];" : "=r"(tmem) : "r"(smem_base + SM_TMEMPTR));

    auto load_chunk = [&](int c, int s) {
        const int k0 = c << 6;
        const __nv_bfloat16* src0 = Ahi + (long)mBase * K + k0;
        const __nv_bfloat16* src1 = Alo + (long)mBase * K + k0;
        const __nv_bfloat16* src2 = Bhi + (long)nBase * K + k0;
        const __nv_bfloat16* src3 = Blo + (long)nBase * K + k0;
        const uint32_t stage = smem_base + SM_TILES + s * STAGE_B;
        #pragma unroll
        for (int i = 0; i < 4; i++) {
            const int idx = tid + i * 256;      // 0..1023
            const int r   = idx >> 3;
            const int c16 = idx & 7;
            const long gofs = (long)r * K + (c16 << 3);
            const uint32_t sofs = stage + SMEM_SWIZZLE_128B((r << 7) | (c16 << 4));
            CP_ASYNC16(sofs + 0 * TILE_B, src0 + gofs);
            CP_ASYNC16(sofs + 1 * TILE_B, src1 + gofs);
            CP_ASYNC16(sofs + 2 * TILE_B, src2 + gofs);
            CP_ASYNC16(sofs + 3 * TILE_B, src3 + gofs);
        }
        CP_COMMIT();
    };

    const int NC = K >> 6;   // K-chunks of 64 (always >= 3 here)
    load_chunk(0, 0);
    load_chunk(1, 1);

    for (int c = 0; c < NC; c++) {
        const int s = c % 3;
        if (c + 1 < NC) CP_WAIT_1(); else CP_WAIT_0();
        FENCE_PROXY_ASYNC();
        __syncthreads();

        if (wid == 0) {
            const uint32_t stage = smem_base + SM_TILES + s * STAGE_B;
            const uint64_t dAhi = MAKE_SMEM_DESC(stage + 0 * TILE_B);
            const uint64_t dAlo = MAKE_SMEM_DESC(stage + 1 * TILE_B);
            const uint64_t dBhi = MAKE_SMEM_DESC(stage + 2 * TILE_B);
            const uint64_t dBlo = MAKE_SMEM_DESC(stage + 3 * TILE_B);
            if (elect_one_pred()) {
                #pragma unroll
                for (int kk = 0; kk < 4; kk++) {
                    mma_f16_ss(tmem, dAhi + kk * 2, dBhi + kk * 2, GEMM_IDESC,
                               !(c == 0 && kk == 0));
                    mma_f16_ss(tmem, dAlo + kk * 2, dBhi + kk * 2, GEMM_IDESC, true);
                    mma_f16_ss(tmem, dAhi + kk * 2, dBlo + kk * 2, GEMM_IDESC, true);
                }
                TCGEN05_COMMIT(smem_base + SM_MBAR + s * 8);
            }
        }

        // prefetch chunk c+2 into stage (c+2)%3 (held chunk c-1 -> need MMA c-1 done)
        if (c + 2 < NC) {
            if (c >= 1)
                MBARRIER_WAIT_PARITY(smem_base + SM_MBAR + ((c - 1) % 3) * 8,
                                     (((c - 1) / 3) & 1));
            load_chunk(c + 2, (c + 2) % 3);
        }
    }

    // wait for ALL MMAs (in-order pipe: last commit covers all prior)
    MBARRIER_WAIT_PARITY(smem_base + SM_MBAR + ((NC - 1) % 3) * 8, ((NC - 1) / 3) & 1);
    TCGEN05_FENCE_AFTER();

    // Epilogue: TMEM -> SMEM (row-stage) -> coalesced global
    float* sout = (float*)(smem + SM_TILES);
    if (wid < 4) {
        const int r = (wid << 5) + lid;
        #pragma unroll
        for (int cb = 0; cb < 4; cb++) {
            uint32_t regs[32];
            TCGEN05_LD_X32(regs, tmem + (cb << 5));
            TCGEN05_WAIT_LD();
            #pragma unroll
            for (int j = 0; j < 32; j += 4) {
                float4 v = make_float4(__uint_as_float(regs[j]),
                                       __uint_as_float(regs[j + 1]),
                                       __uint_as_float(regs[j + 2]),
                                       __uint_as_float(regs[j + 3]));
                *(float4*)&sout[r * 132 + (cb << 5) + j] = v;
            }
        }
    }
    __syncthreads();
    if (wid == 0) TCGEN05_DEALLOC(tmem, 128);

    for (int idx = tid; idx < 128 * 32; idx += 256) {
        const int r = idx >> 5;
        const int cc = (idx & 31) << 2;
        float4 v = *(float4*)&sout[r * 132 + cc];
        const long gr = mBase + r;
        const int  gc = nBase + cc;
        float4 bb = *(const float4*)&bias[gc];
        v.x += bb.x; v.y += bb.y; v.z += bb.z; v.w += bb.w;
        if (OP == 1 || OP == 3) {
            if (OP == 1) {
                v.x = gelu_exact(v.x); v.y = gelu_exact(v.y);
                v.z = gelu_exact(v.z); v.w = gelu_exact(v.w);
            }
            const long o = gr * N + gc;
            split_store(Chi, Clo, o + 0, v.x);
            split_store(Chi, Clo, o + 1, v.y);
            split_store(Chi, Clo, o + 2, v.z);
            split_store(Chi, Clo, o + 3, v.w);
        } else if (OP == 2) {
            float4 rr = *(const float4*)&res[gr * N + gc];
            v.x += rr.x; v.y += rr.y; v.z += rr.z; v.w += rr.w;
            *(float4*)&Cf[gr * N + gc] = v;
        } else {
            *(float4*)&Cf[gr * N + gc] = v;
        }
    }

#else  // =================== FFMA fallback (non-103a passes) ===================
    float* As = (float*)smem;                 // [8][128]
    float* Bs = As + 8 * 128;                 // [8][128]

    const int tx = tid & 15;
    const int ty = tid >> 4;
    const int row  = tid >> 1;                // 0..127
    const int kc   = (tid & 1) << 2;          // 0 or 4

    float acc[8][8];
    #pragma unroll
    for (int i = 0; i < 8; i++)
        #pragma unroll
        for (int j = 0; j < 8; j++) acc[i][j] = 0.f;

    for (int k0 = 0; k0 < K; k0 += 8) {
        {
            const long o = (long)(mBase + row) * K + k0 + kc;
            ushort4 h = *(const ushort4*)(Ahi + o);
            ushort4 l = *(const ushort4*)(Alo + o);
            As[(kc + 0) * 128 + row] = __bfloat162float(*(__nv_bfloat16*)&h.x) + __bfloat162float(*(__nv_bfloat16*)&l.x);
            As[(kc + 1) * 128 + row] = __bfloat162float(*(__nv_bfloat16*)&h.y) + __bfloat162float(*(__nv_bfloat16*)&l.y);
            As[(kc + 2) * 128 + row] = __bfloat162float(*(__nv_bfloat16*)&h.z) + __bfloat162float(*(__nv_bfloat16*)&l.z);
            As[(kc + 3) * 128 + row] = __bfloat162float(*(__nv_bfloat16*)&h.w) + __bfloat162float(*(__nv_bfloat16*)&l.w);
        }
        {
            const long o = (long)(nBase + row) * K + k0 + kc;
            ushort4 h = *(const ushort4*)(Bhi + o);
            ushort4 l = *(const ushort4*)(Blo + o);
            Bs[(kc + 0) * 128 + row] = __bfloat162float(*(__nv_bfloat16*)&h.x) + __bfloat162float(*(__nv_bfloat16*)&l.x);
            Bs[(kc + 1) * 128 + row] = __bfloat162float(*(__nv_bfloat16*)&h.y) + __bfloat162float(*(__nv_bfloat16*)&l.y);
            Bs[(kc + 2) * 128 + row] = __bfloat162float(*(__nv_bfloat16*)&h.z) + __bfloat162float(*(__nv_bfloat16*)&l.z);
            Bs[(kc + 3) * 128 + row] = __bfloat162float(*(__nv_bfloat16*)&h.w) + __bfloat162float(*(__nv_bfloat16*)&l.w);
        }
        __syncthreads();

        #pragma unroll
        for (int k = 0; k < 8; k++) {
            float a[8], bb[8];
            #pragma unroll
            for (int i = 0; i < 8; i++) a[i]  = As[k * 128 + ty * 8 + i];
            #pragma unroll
            for (int j = 0; j < 8; j++) bb[j] = Bs[k * 128 + tx * 8 + j];
            #pragma unroll
            for (int i = 0; i < 8; i++)
                #pragma unroll
                for (int j = 0; j < 8; j++)
                    acc[i][j] = fmaf(a[i], bb[j], acc[i][j]);
        }
        __syncthreads();
    }

    #pragma unroll
    for (int i = 0; i < 8; i++) {
        const long gr = mBase + ty * 8 + i;
        #pragma unroll
        for (int j = 0; j < 8; j++) {
            const int gc = nBase + tx * 8 + j;
            float v = acc[i][j] + bias[gc];
            if (OP == 1) {
                v = gelu_exact(v);
                split_store(Chi, Clo, gr * N + gc, v);
            } else if (OP == 3) {
                split_store(Chi, Clo, gr * N + gc, v);
            } else if (OP == 2) {
                Cf[gr * N + gc] = v + res[gr * N + gc];
            } else {
                Cf[gr * N + gc] = v;
            }
        }
    }
#endif
}

// ======================= tcgen05 causal flash attention =======================
// 64-key tiles, 99 KB SMEM -> 2 CTAs/SM. CTA = (128 q rows, head, batch), qt reversed.
// TMEM: S cols 0..63, O cols 64..127 (alloc 128).
// cp.async for all loads; single K buffer (prefetch after S-MMA frees it);
// V staged into dead P region, transposed in SMEM (R4-validated PV layout);
// softmax + O accumulation split across all 8 warps (col halves of 32).
#define A_TMEMPTR 0
#define A_MBAR0   8
#define A_MBAR1   16
#define A_SMX     32            // float[256]
#define A_SLS     1056          // float[256]
#define A_Q       3072          // hi 16K, lo at +16384
#define A_K       35840         // hi 8K, lo at +8192
#define A_VT      52224         // hi 8K, lo at +8192
#define A_P       68608         // hi 16K, lo at +16384 ; V staging: hi +0, lo +8192
#define ATTN_SMEM 101376

#if HAS_TCGEN05
__device__ __forceinline__ void attn_issue_S(uint32_t tmem, uint32_t sb) {
    const uint64_t dQh = MAKE_SMEM_DESC(sb + A_Q);
    const uint64_t dQl = MAKE_SMEM_DESC(sb + A_Q + 16384);
    const uint64_t dKh = MAKE_SMEM_DESC(sb + A_K);
    const uint64_t dKl = MAKE_SMEM_DESC(sb + A_K + 8192);
    #pragma unroll
    for (int kk = 0; kk < 4; kk++) {
        mma_f16_ss(tmem, dQh + kk * 2, dKh + kk * 2, ATTN_IDESC, kk != 0);
        mma_f16_ss(tmem, dQl + kk * 2, dKh + kk * 2, ATTN_IDESC, true);
        mma_f16_ss(tmem, dQh + kk * 2, dKl + kk * 2, ATTN_IDESC, true);
    }
}
__device__ __forceinline__ void attn_issue_PV(uint32_t tmem, uint32_t sb) {
    const uint64_t dPh = MAKE_SMEM_DESC(sb + A_P);
    const uint64_t dPl = MAKE_SMEM_DESC(sb + A_P + 16384);
    const uint64_t dVh = MAKE_SMEM_DESC(sb + A_VT);
    const uint64_t dVl = MAKE_SMEM_DESC(sb + A_VT + 8192);
    #pragma unroll
    for (int kk = 0; kk < 4; kk++) {
        mma_f16_ss(tmem + 64, dPh + kk * 2, dVh + kk * 2, ATTN_IDESC, kk != 0);
        mma_f16_ss(tmem + 64, dPl + kk * 2, dVh + kk * 2, ATTN_IDESC, true);
        mma_f16_ss(tmem + 64, dPh + kk * 2, dVl + kk * 2, ATTN_IDESC, true);
    }
}
#endif

__global__ __launch_bounds__(256, 2) void attn_tc(
    const __nv_bfloat16* __restrict__ qkv_hi,
    const __nv_bfloat16* __restrict__ qkv_lo,
    __nv_bfloat16* __restrict__ ohi,
    __nv_bfloat16* __restrict__ olo)
{
    extern __shared__ __align__(1024) char smem[];
    const int tid  = threadIdx.x;
    const int wid  = tid >> 5;
    const int lid  = tid & 31;
    const int qt   = gridDim.x - 1 - blockIdx.x;   // reversed: long CTAs first
    const int head = blockIdx.y;
    const int bat  = blockIdx.z;
    const long tok0 = (long)bat * SEQ;

#if HAS_TCGEN05
    const uint32_t sb = smem_u32_of(smem);
    float* smx = (float*)(smem + A_SMX);
    float* sls = (float*)(smem + A_SLS);
    if (wid == 0) {
        TCGEN05_ALLOC(sb + A_TMEMPTR, 128);
        TCGEN05_RELINQUISH();
    }
    if (tid == 0) {
        MBARRIER_INIT(sb + A_MBAR0, 1);
        MBARRIER_INIT(sb + A_MBAR1, 1);
    }
    __syncthreads();
    uint32_t tmem;
    asm volatile("ld.shared.b32 %0, [%1];" : "=r"(tmem) : "r"(sb + A_TMEMPTR));

    // Q tile (128 x 64 hi/lo) + K tile 0 (64 keys) via cp.async
    #pragma unroll
    for (int i = 0; i < 4; i++) {
        const int idx = tid + i * 256;
        const int r = idx >> 3, c8 = idx & 7;
        const uint32_t sofs = SMEM_SWIZZLE_128B((r << 7) | (c8 << 4));
        const long gq = (tok0 + qt * 128 + r) * (long)QKVW + head * 64 + (c8 << 3);
        CP_ASYNC16(sb + A_Q + sofs,         qkv_hi + gq);
        CP_ASYNC16(sb + A_Q + 16384 + sofs, qkv_lo + gq);
    }
    #pragma unroll
    for (int i = 0; i < 2; i++) {
        const int idx = tid + i * 256;       // 0..511
        const int r = idx >> 3, c8 = idx & 7;
        const uint32_t sofs = SMEM_SWIZZLE_128B((r << 7) | (c8 << 4));
        const long gk = (tok0 + r) * (long)QKVW + 1024 + head * 64 + (c8 << 3);
        CP_ASYNC16(sb + A_K + sofs,        qkv_hi + gk);
        CP_ASYNC16(sb + A_K + 8192 + sofs, qkv_lo + gk);
    }
    CP_COMMIT();
    CP_WAIT_0();
    FENCE_PROXY_ASYNC();
    __syncthreads();
    if (wid == 0 && elect_one_pred()) {
        attn_issue_S(tmem, sb);
        TCGEN05_COMMIT(sb + A_MBAR0);
    }

    const int half = wid >> 2;                 // column half (32 key-cols / 32 hd-cols)
    const int row  = ((wid & 3) << 5) + lid;   // q row
    const int grow = qt * 128 + row;
    const int nkt  = 2 * qt + 2;
    const float SCL = 0.125f * 1.4426950408889634f;  // fold 1/sqrt(hd) * log2(e)

    float o[32];
    #pragma unroll
    for (int j = 0; j < 32; j++) o[j] = 0.f;
    float m = -1e30f, l = 0.f;

    for (int kt = 0; kt < nkt; kt++) {
        const bool pre = (kt + 1 < nkt);

        // stage V(kt) into P region (dead after previous PV wait)
        #pragma unroll
        for (int i = 0; i < 2; i++) {
            const int idx = tid + i * 256;
            const int r = idx >> 3, c8 = idx & 7;
            const uint32_t sofs = SMEM_SWIZZLE_128B((r << 7) | (c8 << 4));
            const long gv = (tok0 + kt * 64 + r) * (long)QKVW + 2048 + head * 64 + (c8 << 3);
            CP_ASYNC16(sb + A_P + sofs,        qkv_hi + gv);
            CP_ASYNC16(sb + A_P + 8192 + sofs, qkv_lo + gv);
        }
        CP_COMMIT();   // group V

        // wait S(kt) -> K buffer free -> prefetch K(kt+1)
        MBARRIER_WAIT_PARITY(sb + A_MBAR0, kt & 1);
        TCGEN05_FENCE_AFTER();
        if (pre) {
            #pragma unroll
            for (int i = 0; i < 2; i++) {
                const int idx = tid + i * 256;
                const int r = idx >> 3, c8 = idx & 7;
                const uint32_t sofs = SMEM_SWIZZLE_128B((r << 7) | (c8 << 4));
                const long gk = (tok0 + (kt + 1) * 64 + r) * (long)QKVW + 1024 + head * 64 + (c8 << 3);
                CP_ASYNC16(sb + A_K + sofs,        qkv_hi + gk);
                CP_ASYNC16(sb + A_K + 8192 + sofs, qkv_lo + gk);
            }
            CP_COMMIT();   // group K
        }

        // pull this warp's 32 S columns
        uint32_t r0[32];
        TCGEN05_LD_X32(r0, tmem + half * 32);
        TCGEN05_WAIT_LD();

        // V staged complete (K group may remain in flight)
        if (pre) CP_WAIT_1(); else CP_WAIT_0();
        __syncthreads();   // S1: staged V visible

        // transpose staged V -> Vt[hd][key] (hi + lo)
        #pragma unroll
        for (int i = 0; i < 8; i++) {
            const int idx = tid + i * 256;        // 0..2047
            const int c  = idx & 63;              // hd
            const int kp = idx >> 6;              // key pair 0..31
            const int so0 = SMEM_SWIZZLE_128B(((2 * kp)     << 7) | (c << 1));
            const int so1 = SMEM_SWIZZLE_128B(((2 * kp + 1) << 7) | (c << 1));
            const int dd  = SMEM_SWIZZLE_128B((c << 7) | (kp << 2));
            uint32_t a = *(const uint16_t*)(smem + A_P + so0);
            uint32_t b = *(const uint16_t*)(smem + A_P + so1);
            *(uint32_t*)(smem + A_VT + dd) = a | (b << 16);
            a = *(const uint16_t*)(smem + A_P + 8192 + so0);
            b = *(const uint16_t*)(smem + A_P + 8192 + so1);
            *(uint32_t*)(smem + A_VT + 8192 + dd) = a | (b << 16);
        }

        float s[32];
        #pragma unroll
        for (int j = 0; j < 32; j++) s[j] = __uint_as_float(r0[j]) * SCL;

        if (kt >= 2 * qt) {   // diagonal tiles: causal mask
            const int jbase = kt * 64 + half * 32;
            #pragma unroll
            for (int j = 0; j < 32; j++)
                if (jbase + j > grow) s[j] = -1e30f;
        }
        float lmx = -1e30f;
        #pragma unroll
        for (int j = 0; j < 32; j++) lmx = fmaxf(lmx, s[j]);
        smx[half * 128 + row] = lmx;
        __syncthreads();   // S2: smx visible; transpose reads done

        const float mnew = fmaxf(m, fmaxf(smx[row], smx[128 + row]));
        const float scl  = exp2f(m - mnew);
        m = mnew;
        float ls = 0.f;
        #pragma unroll
        for (int j = 0; j < 32; j++) { s[j] = exp2f(s[j] - mnew); ls += s[j]; }
        sls[half * 128 + row] = ls;

        // store this half's P (hi/lo), overwriting staging
        #pragma unroll
        for (int j8 = 0; j8 < 4; j8++) {
            __align__(16) __nv_bfloat16 hb[8], lb[8];
            #pragma unroll
            for (int j = 0; j < 8; j++) {
                const float v = s[(j8 << 3) + j];
                const __nv_bfloat16 h = __float2bfloat16(v);
                hb[j] = h;
                lb[j] = __float2bfloat16(v - __bfloat162float(h));
            }
            const int so = SMEM_SWIZZLE_128B((row << 7) | (half << 6) | (j8 << 4));
            *(uint4*)(smem + A_P + so)         = *(uint4*)hb;
            *(uint4*)(smem + A_P + 16384 + so) = *(uint4*)lb;
        }
        FENCE_PROXY_ASYNC();
        __syncthreads();   // S3: P + Vt + sls visible

        l = l * scl + sls[row] + sls[128 + row];

        if (wid == 0 && elect_one_pred()) {
            attn_issue_PV(tmem, sb);
            TCGEN05_COMMIT(sb + A_MBAR1);
        }

        // issue S(kt+1) while PV(kt) runs
        if (pre) {
            CP_WAIT_0();
            FENCE_PROXY_ASYNC();
            __syncthreads();   // S4: K(kt+1) visible
            if (wid == 0 && elect_one_pred()) {
                attn_issue_S(tmem, sb);
                TCGEN05_COMMIT(sb + A_MBAR0);
            }
        }

        // wait PV(kt), accumulate O (this half's 32 hd cols)
        MBARRIER_WAIT_PARITY(sb + A_MBAR1, kt & 1);
        TCGEN05_FENCE_AFTER();
        uint32_t p0[32];
        TCGEN05_LD_X32(p0, tmem + 64 + half * 32);
        TCGEN05_WAIT_LD();
        #pragma unroll
        for (int j = 0; j < 32; j++) o[j] = o[j] * scl + __uint_as_float(p0[j]);
    }

    // epilogue: each warp writes its 32 hd cols for its rows
    {
        const float invl = 1.0f / l;
        const long gofs = (tok0 + grow) * (long)DMODEL + head * 64 + half * 32;
        #pragma unroll
        for (int j8 = 0; j8 < 4; j8++) {
            __align__(16) __nv_bfloat16 hb[8], lb[8];
            #pragma unroll
            for (int j = 0; j < 8; j++) {
                const float v = o[(j8 << 3) + j] * invl;
                const __nv_bfloat16 h = __float2bfloat16(v);
                hb[j] = h;
                lb[j] = __float2bfloat16(v - __bfloat162float(h));
            }
            *(uint4*)(ohi + gofs + (j8 << 3)) = *(uint4*)hb;
            *(uint4*)(olo + gofs + (j8 << 3)) = *(uint4*)lb;
        }
    }
    __syncthreads();
    if (wid == 0) TCGEN05_DEALLOC(tmem, 128);

#else  // =================== compile-only FFMA fallback ===================
    if (tid < 128) {
        const int grow2 = qt * 128 + tid;
        const long qofs = (tok0 + grow2) * (long)QKVW + head * 64;
        float q[64], o2[64];
        #pragma unroll
        for (int c = 0; c < 64; c++) {
            q[c] = (__bfloat162float(qkv_hi[qofs + c]) +
                    __bfloat162float(qkv_lo[qofs + c])) * 0.125f;
            o2[c] = 0.f;
        }
        float m2 = -1e30f, l2 = 0.f;
        for (int j = 0; j <= grow2; j++) {
            const long kofs = (tok0 + j) * (long)QKVW + 1024 + head * 64;
            float s = 0.f;
            for (int c = 0; c < 64; c++)
                s += q[c] * (__bfloat162float(qkv_hi[kofs + c]) +
                             __bfloat162float(qkv_lo[kofs + c]));
            const float mnew = fmaxf(m2, s);
            const float scf = expf(m2 - mnew);
            const float p = expf(s - mnew);
            l2 = l2 * scf + p;
            m2 = mnew;
            const long vofs = kofs + 1024;
            for (int c = 0; c < 64; c++)
                o2[c] = o2[c] * scf + p * (__bfloat162float(qkv_hi[vofs + c]) +
                                           __bfloat162float(qkv_lo[vofs + c]));
        }
        const long gofs = (tok0 + grow2) * (long)DMODEL + head * 64;
        for (int c = 0; c < 64; c++)
            split_store(ohi, olo, gofs + c, o2[c] / l2);
    }
#endif
}

// ======================= driver =======================
extern "C" void kernel_launch(void* const* d_in, const int* in_sizes, int n_in,
                              void* d_out, int out_size)
{
    const float* x    = (const float*)d_in[0];
    const float* g1   = (const float*)d_in[1];
    const float* b1   = (const float*)d_in[2];
    const float* Wqkv = (const float*)d_in[3];
    const float* bqkv = (const float*)d_in[4];
    const float* Wo   = (const float*)d_in[5];
    const float* bo   = (const float*)d_in[6];
    const float* g2   = (const float*)d_in[7];
    const float* b2   = (const float*)d_in[8];
    const float* W1   = (const float*)d_in[9];
    const float* b1f  = (const float*)d_in[10];
    const float* W2   = (const float*)d_in[11];
    const float* b2f  = (const float*)d_in[12];
    float* out = (float*)d_out;

    float *x2;
    __nv_bfloat16 *qkv_hi, *qkv_lo;
    __nv_bfloat16 *h_hi, *h_lo, *attn_hi, *attn_lo, *hh_hi, *hh_lo, *ff_hi, *ff_lo;
    __nv_bfloat16 *WqkvT_hi, *WqkvT_lo, *WoT_hi, *WoT_lo, *W1T_hi, *W1T_lo, *W2T_hi, *W2T_lo;
    cudaGetSymbolAddress((void**)&x2,       g_x2);
    cudaGetSymbolAddress((void**)&qkv_hi,   g_qkv_hi);
    cudaGetSymbolAddress((void**)&qkv_lo,   g_qkv_lo);
    cudaGetSymbolAddress((void**)&h_hi,     g_h_hi);
    cudaGetSymbolAddress((void**)&h_lo,     g_h_lo);
    cudaGetSymbolAddress((void**)&attn_hi,  g_attn_hi);
    cudaGetSymbolAddress((void**)&attn_lo,  g_attn_lo);
    cudaGetSymbolAddress((void**)&hh_hi,    g_hh_hi);
    cudaGetSymbolAddress((void**)&hh_lo,    g_hh_lo);
    cudaGetSymbolAddress((void**)&ff_hi,    g_ff_hi);
    cudaGetSymbolAddress((void**)&ff_lo,    g_ff_lo);
    cudaGetSymbolAddress((void**)&WqkvT_hi, g_WqkvT_hi);
    cudaGetSymbolAddress((void**)&WqkvT_lo, g_WqkvT_lo);
    cudaGetSymbolAddress((void**)&WoT_hi,   g_WoT_hi);
    cudaGetSymbolAddress((void**)&WoT_lo,   g_WoT_lo);
    cudaGetSymbolAddress((void**)&W1T_hi,   g_W1T_hi);
    cudaGetSymbolAddress((void**)&W1T_lo,   g_W1T_lo);
    cudaGetSymbolAddress((void**)&W2T_hi,   g_W2T_hi);
    cudaGetSymbolAddress((void**)&W2T_lo,   g_W2T_lo);

    cudaFuncSetAttribute(attn_tc,    cudaFuncAttributeMaxDynamicSharedMemorySize, ATTN_SMEM);
    cudaFuncSetAttribute(gemm_tc<1>, cudaFuncAttributeMaxDynamicSharedMemorySize, GEMM_SMEM);
    cudaFuncSetAttribute(gemm_tc<2>, cudaFuncAttributeMaxDynamicSharedMemorySize, GEMM_SMEM);
    cudaFuncSetAttribute(gemm_tc<3>, cudaFuncAttributeMaxDynamicSharedMemorySize, GEMM_SMEM);

    // weight conversion + transpose (K-major for MMA B operand), 64x64 tiles
    wtrans_kernel<<<dim3(QKVW / 64, DMODEL / 64), 256>>>(Wqkv, WqkvT_hi, WqkvT_lo, DMODEL, QKVW);
    wtrans_kernel<<<dim3(DMODEL / 64, DMODEL / 64), 256>>>(Wo, WoT_hi, WoT_lo, DMODEL, DMODEL);
    wtrans_kernel<<<dim3(FFDIM / 64, DMODEL / 64), 256>>>(W1, W1T_hi, W1T_lo, DMODEL, FFDIM);
    wtrans_kernel<<<dim3(DMODEL / 64, FFDIM / 64), 256>>>(W2, W2T_hi, W2T_lo, FFDIM, DMODEL);

    // LN1 -> hi/lo
    ln_kernel<<<NTOK, 256>>>(x, g1, b1, h_hi, h_lo);
    // QKV projection -> bf16 hi/lo (attention input)
    gemm_tc<3><<<dim3(QKVW / 128, NTOK / 128), 256, GEMM_SMEM>>>(
        h_hi, h_lo, WqkvT_hi, WqkvT_lo, bqkv, nullptr, nullptr, qkv_hi, qkv_lo, QKVW, DMODEL);
    // causal attention (tcgen05, 64-key pipelined, occ 2) -> hi/lo
    attn_tc<<<dim3(SEQ / 128, NH, BATCH), 256, ATTN_SMEM>>>(qkv_hi, qkv_lo, attn_hi, attn_lo);
    // output projection + residual -> x2 (fp32)
    gemm_tc<2><<<dim3(DMODEL / 128, NTOK / 128), 256, GEMM_SMEM>>>(
        attn_hi, attn_lo, WoT_hi, WoT_lo, bo, x, x2, nullptr, nullptr, DMODEL, DMODEL);
    // LN2 -> hi/lo
    ln_kernel<<<NTOK, 256>>>(x2, g2, b2, hh_hi, hh_lo);
    // FF1 + GELU -> hi/lo
    gemm_tc<1><<<dim3(FFDIM / 128, NTOK / 128), 256, GEMM_SMEM>>>(
        hh_hi, hh_lo, W1T_hi, W1T_lo, b1f, nullptr, nullptr, ff_hi, ff_lo, FFDIM, DMODEL);
    // FF2 + residual -> out (fp32)
    gemm_tc<2><<<dim3(DMODEL / 128, NTOK / 128), 256, GEMM_SMEM>>>(
        ff_hi, ff_lo, W2T_hi, W2T_lo, b2f, x2, out, nullptr, nullptr, DMODEL, FFDIM);
}

// round 10
// speedup vs baseline: 5.7964x; 1.0119x over previous
#include <cuda_runtime.h>
#include <cuda_bf16.h>
#include <math.h>
#include <stdint.h>

// Problem dims (fixed by the reference)
#define NTOK   4096      // B*T = 2*2048
#define SEQ    2048
#define BATCH  2
#define DMODEL 1024
#define NH     16
#define HDIM   64
#define FFDIM  4096
#define QKVW   3072      // 3*DMODEL

// tcgen05 only exists in the arch-specific (sm_103a / sm_103f) compilation pass.
#if defined(__CUDA_ARCH__) && (__CUDA_ARCH__ == 1030) && \
    (defined(__CUDA_ARCH_FEAT_SM103_ALL) || defined(__CUDA_ARCH_SPECIFIC__) || \
     defined(__CUDA_ARCH_FAMILY_SPECIFIC__))
#define HAS_TCGEN05 1
#else
#define HAS_TCGEN05 0
#endif

// cp.async works on all passes (sm_80+)
#define CP_ASYNC16(smem_u32, gptr) \
    asm volatile("cp.async.cg.shared.global [%0], [%1], 16;" \
                 :: "r"((uint32_t)(smem_u32)), "l"(gptr) : "memory")
#define CP_COMMIT() asm volatile("cp.async.commit_group;" ::: "memory")
#define CP_WAIT_0() asm volatile("cp.async.wait_group 0;" ::: "memory")
#define CP_WAIT_1() asm volatile("cp.async.wait_group 1;" ::: "memory")

__device__ __forceinline__ uint32_t smem_u32_of(const void* p) {
    uint32_t a;
    asm("{ .reg .u64 t; cvta.to.shared.u64 t, %1; cvt.u32.u64 %0, t; }" : "=r"(a) : "l"(p));
    return a;
}

#if HAS_TCGEN05
// ======================= PTX helpers (arch-specific pass only) =======================
__device__ __forceinline__ uint32_t elect_one_pred() {
    uint32_t pred;
    asm volatile("{\n\t.reg .pred p;\n\telect.sync _|p, 0xFFFFFFFF;\n\tselp.b32 %0, 1, 0, p;\n\t}"
                 : "=r"(pred));
    return pred;
}

static constexpr uint64_t SMEM_DESC_BASE_SW128 =
    (uint64_t(2) << 61) | (uint64_t(1) << 46) | (uint64_t(64) << 32) | (uint64_t(1) << 16);
#define MAKE_SMEM_DESC(base_addr) \
    (SMEM_DESC_BASE_SW128 | ((uint64_t)((base_addr) >> 4) & 0x3FFF))

#define TCGEN05_ALLOC(sa, n) \
    asm volatile("tcgen05.alloc.cta_group::1.sync.aligned.shared::cta.b32 [%0], %1;" \
                 :: "r"((uint32_t)(sa)), "r"((uint32_t)(n)) : "memory")
#define TCGEN05_DEALLOC(t, n) \
    asm volatile("tcgen05.dealloc.cta_group::1.sync.aligned.b32 %0, %1;" :: "r"(t), "r"((uint32_t)(n)))
#define TCGEN05_RELINQUISH() \
    asm volatile("tcgen05.relinquish_alloc_permit.cta_group::1.sync.aligned;")
#define TCGEN05_COMMIT(mb) \
    asm volatile("tcgen05.commit.cta_group::1.mbarrier::arrive::one.shared::cluster.b64 [%0];" \
                 :: "r"((uint32_t)(mb)) : "memory")
#define TCGEN05_FENCE_AFTER() asm volatile("tcgen05.fence::after_thread_sync;" ::: "memory")
#define TCGEN05_WAIT_LD() asm volatile("tcgen05.wait::ld.sync.aligned;" ::: "memory")
#define FENCE_PROXY_ASYNC() asm volatile("fence.proxy.async.shared::cta;" ::: "memory")

#define MBARRIER_INIT(mb, cnt) \
    asm volatile("mbarrier.init.shared.b64 [%0], %1;" :: "r"((uint32_t)(mb)), "r"((uint32_t)(cnt)) : "memory")

#define MBARRIER_WAIT_PARITY(mb, par) do { \
    uint32_t _mb = (uint32_t)(mb), _p = (uint32_t)(par), _d; \
    asm volatile("{\n\t.reg .pred p;\n\t" \
        "mbarrier.try_wait.parity.acquire.cta.shared::cta.b64 p, [%1], %2;\n\t" \
        "selp.b32 %0, 1, 0, p;\n\t}" : "=r"(_d) : "r"(_mb), "r"(_p) : "memory"); \
    if (!_d) { \
        asm volatile("{\n\t.reg .pred P1;\n\t" \
            "WL_%=:\n\t" \
            "mbarrier.try_wait.parity.acquire.cta.shared::cta.b64 P1, [%0], %1, 0x989680;\n\t" \
            "@P1 bra.uni WD_%=;\n\t" \
            "bra.uni WL_%=;\n\t" \
            "WD_%=:\n\t}" :: "r"(_mb), "r"(_p) : "memory"); \
    } \
} while (0)

#define TCGEN05_LD_X32(r, ta) \
    asm volatile("tcgen05.ld.sync.aligned.32x32b.x32.b32 " \
        "{%0, %1, %2, %3, %4, %5, %6, %7, %8, %9, %10, %11, %12, %13, %14, %15, " \
        "%16, %17, %18, %19, %20, %21, %22, %23, %24, %25, %26, %27, %28, %29, %30, %31}, [%32];" \
        : "=r"((r)[0]), "=r"((r)[1]), "=r"((r)[2]), "=r"((r)[3]), \
          "=r"((r)[4]), "=r"((r)[5]), "=r"((r)[6]), "=r"((r)[7]), \
          "=r"((r)[8]), "=r"((r)[9]), "=r"((r)[10]), "=r"((r)[11]), \
          "=r"((r)[12]), "=r"((r)[13]), "=r"((r)[14]), "=r"((r)[15]), \
          "=r"((r)[16]), "=r"((r)[17]), "=r"((r)[18]), "=r"((r)[19]), \
          "=r"((r)[20]), "=r"((r)[21]), "=r"((r)[22]), "=r"((r)[23]), \
          "=r"((r)[24]), "=r"((r)[25]), "=r"((r)[26]), "=r"((r)[27]), \
          "=r"((r)[28]), "=r"((r)[29]), "=r"((r)[30]), "=r"((r)[31]) \
        : "r"(ta))

// cg1 kind::f16 SS-mode MMA (A and B both in SMEM, bf16 in / fp32 accum)
__device__ __forceinline__ void mma_f16_ss(uint32_t d, uint64_t ad, uint64_t bd,
                                           uint32_t idesc, bool acc) {
    uint32_t en = acc ? 1u : 0u;
    asm volatile(
        "{\n\t.reg .pred p;\n\tsetp.ne.u32 p, %5, 0;\n\t"
        "tcgen05.mma.cta_group::1.kind::f16 [%0], %1, %2, %3, {%4, %4, %4, %4}, p;\n\t}"
        :: "r"(d), "l"(ad), "l"(bd), "r"(idesc), "r"(0u), "r"(en) : "memory");
}

// idesc: fp32 accum, bf16 A/B, M=128, N=256, K-major both
static constexpr uint32_t GEMM_IDESC_N256 =
    (1u << 4) | (1u << 7) | (1u << 10) | ((256u / 8u) << 17) | ((128u / 16u) << 24);
// idesc for attention MMAs: M=128, N=64, K-major both (validated in R4)
static constexpr uint32_t ATTN_IDESC =
    (1u << 4) | (1u << 7) | (1u << 10) | ((64u / 8u) << 17) | ((128u / 16u) << 24);
#endif  // HAS_TCGEN05

#define SMEM_SWIZZLE_128B(off) ((off) ^ (((off) >> 3) & 0x70))

// ======================= scratch (device globals) =======================
__device__ float g_x2  [NTOK * DMODEL];          // residual after attn proj
__device__ __nv_bfloat16 g_qkv_hi[NTOK * QKVW],  g_qkv_lo[NTOK * QKVW];
__device__ __nv_bfloat16 g_h_hi  [NTOK * DMODEL], g_h_lo  [NTOK * DMODEL];
__device__ __nv_bfloat16 g_attn_hi[NTOK * DMODEL], g_attn_lo[NTOK * DMODEL];
__device__ __nv_bfloat16 g_hh_hi [NTOK * DMODEL], g_hh_lo [NTOK * DMODEL];
__device__ __nv_bfloat16 g_ff_hi [NTOK * FFDIM],  g_ff_lo [NTOK * FFDIM];
__device__ __nv_bfloat16 g_WqkvT_hi[QKVW * DMODEL],  g_WqkvT_lo[QKVW * DMODEL];
__device__ __nv_bfloat16 g_WoT_hi [DMODEL * DMODEL], g_WoT_lo [DMODEL * DMODEL];
__device__ __nv_bfloat16 g_W1T_hi [FFDIM * DMODEL],  g_W1T_lo [FFDIM * DMODEL];
__device__ __nv_bfloat16 g_W2T_hi [DMODEL * FFDIM],  g_W2T_lo [DMODEL * FFDIM];

__device__ __forceinline__ void split_store(__nv_bfloat16* hi, __nv_bfloat16* lo,
                                            long ofs, float v) {
    __nv_bfloat16 h = __float2bfloat16(v);
    hi[ofs] = h;
    lo[ofs] = __float2bfloat16(v - __bfloat162float(h));
}
__device__ __forceinline__ uint32_t pack2bf(float a, float b) {
    __nv_bfloat162 t;
    t.x = __float2bfloat16(a);
    t.y = __float2bfloat16(b);
    return *(uint32_t*)&t;
}
__device__ __forceinline__ float gelu_exact(float x) {
    return 0.5f * x * (1.0f + erff(x * 0.70710678118654752f));
}

// ======================= LayerNorm -> bf16 hi/lo planes =======================
__global__ __launch_bounds__(256) void ln_kernel(const float* __restrict__ x,
                                                 const float* __restrict__ g,
                                                 const float* __restrict__ b,
                                                 __nv_bfloat16* __restrict__ yhi,
                                                 __nv_bfloat16* __restrict__ ylo)
{
    const int row = blockIdx.x;
    const int tid = threadIdx.x;
    const float* xr = x + (long)row * DMODEL;
    float4 v = *(const float4*)(xr + tid * 4);

    float s  = v.x + v.y + v.z + v.w;
    float sq = v.x*v.x + v.y*v.y + v.z*v.z + v.w*v.w;
    #pragma unroll
    for (int off = 16; off > 0; off >>= 1) {
        s  += __shfl_xor_sync(0xffffffffu, s,  off);
        sq += __shfl_xor_sync(0xffffffffu, sq, off);
    }
    __shared__ float reds[8], redq[8];
    const int wid = tid >> 5;
    if ((tid & 31) == 0) { reds[wid] = s; redq[wid] = sq; }
    __syncthreads();
    float st = 0.f, qt = 0.f;
    #pragma unroll
    for (int w = 0; w < 8; w++) { st += reds[w]; qt += redq[w]; }

    const float mu   = st * (1.0f / DMODEL);
    const float var  = qt * (1.0f / DMODEL) - mu * mu;
    const float rstd = rsqrtf(var + 1e-5f);

    float4 gv = *(const float4*)(g + tid * 4);
    float4 bv = *(const float4*)(b + tid * 4);
    float o0 = (v.x - mu) * rstd * gv.x + bv.x;
    float o1 = (v.y - mu) * rstd * gv.y + bv.y;
    float o2 = (v.z - mu) * rstd * gv.z + bv.z;
    float o3 = (v.w - mu) * rstd * gv.w + bv.w;
    const long base = (long)row * DMODEL + tid * 4;
    split_store(yhi, ylo, base + 0, o0);
    split_store(yhi, ylo, base + 1, o1);
    split_store(yhi, ylo, base + 2, o2);
    split_store(yhi, ylo, base + 3, o3);
}

// ============== weight transpose + bf16 hi/lo: W[K,N] -> T[N,K] (coalesced) ==============
__global__ __launch_bounds__(256) void wtrans_kernel(const float* __restrict__ W,
                                                     __nv_bfloat16* __restrict__ Thi,
                                                     __nv_bfloat16* __restrict__ Tlo,
                                                     int K, int N)
{
    __shared__ float tile[64][65];
    const int nb = blockIdx.x * 64;
    const int kb = blockIdx.y * 64;
    const int tid = threadIdx.x;
    #pragma unroll
    for (int i = 0; i < 4; i++) {
        const int idx = tid + i * 256;       // 0..1023
        const int k = idx >> 4;
        const int n4 = (idx & 15) << 2;
        float4 v = *(const float4*)&W[(long)(kb + k) * N + nb + n4];
        tile[k][n4 + 0] = v.x;
        tile[k][n4 + 1] = v.y;
        tile[k][n4 + 2] = v.z;
        tile[k][n4 + 3] = v.w;
    }
    __syncthreads();
    #pragma unroll
    for (int i = 0; i < 4; i++) {
        const int idx = tid + i * 256;       // 0..1023
        const int n  = idx >> 4;
        const int kq = (idx & 15) << 2;      // 4 consecutive K per thread
        float v0 = tile[kq + 0][n], v1 = tile[kq + 1][n];
        float v2 = tile[kq + 2][n], v3 = tile[kq + 3][n];
        const long ofs = (long)(nb + n) * K + kb + kq;
        uint2 hp, lp;
        hp.x = pack2bf(v0, v1); hp.y = pack2bf(v2, v3);
        __nv_bfloat162* h01 = (__nv_bfloat162*)&hp.x;
        __nv_bfloat162* h23 = (__nv_bfloat162*)&hp.y;
        lp.x = pack2bf(v0 - __bfloat162float(h01->x), v1 - __bfloat162float(h01->y));
        lp.y = pack2bf(v2 - __bfloat162float(h23->x), v3 - __bfloat162float(h23->y));
        *(uint2*)(Thi + ofs) = hp;
        *(uint2*)(Tlo + ofs) = lp;
    }
}

// ======================= GEMM (128x256 tile, 2-stage cp.async pipeline) =======================
// C[M,N] = A[M,K] @ B[N,K]^T, bf16 hi/lo planes (K-major). CTA tile 128(M) x 256(N).
// OP: 1 = +bias, GELU -> bf16 hi/lo ; 2 = +bias +res -> fp32 ; 3 = +bias -> bf16 hi/lo
#define SM_TMEMPTR 0
#define SM_MBAR    16          // two done mbarriers at 16, 24
#define SM_TILES   1024
#define ST_AHI     0
#define ST_ALO     16384
#define ST_BHI     32768       // 256 rows x 128B
#define ST_BLO     65536
#define STAGE_B    98304       // 96 KB per stage
#define GEMM_SMEM  (SM_TILES + 2 * STAGE_B)    // 197632

template<int OP>
__global__ __launch_bounds__(256, 1) void gemm_tc(
    const __nv_bfloat16* __restrict__ Ahi, const __nv_bfloat16* __restrict__ Alo,
    const __nv_bfloat16* __restrict__ Bhi, const __nv_bfloat16* __restrict__ Blo,
    const float* __restrict__ bias, const float* __restrict__ res,
    float* __restrict__ Cf,
    __nv_bfloat16* __restrict__ Chi, __nv_bfloat16* __restrict__ Clo,
    int N, int K)
{
    extern __shared__ __align__(1024) char smem[];
    const int tid = threadIdx.x;
    const int mBase = blockIdx.y * 128;
    const int nBase = blockIdx.x * 256;

#if HAS_TCGEN05
    const uint32_t smem_base = smem_u32_of(smem);
    const int wid = tid >> 5;
    const int lid = tid & 31;

    if (wid == 0) {
        TCGEN05_ALLOC(smem_base + SM_TMEMPTR, 256);
        TCGEN05_RELINQUISH();
    }
    if (tid == 0) {
        MBARRIER_INIT(smem_base + SM_MBAR + 0, 1);
        MBARRIER_INIT(smem_base + SM_MBAR + 8, 1);
    }
    __syncthreads();
    uint32_t tmem;
    asm volatile("ld.shared.b32 %0, [%1];" : "=r"(tmem) : "r"(smem_base + SM_TMEMPTR));

    auto load_chunk = [&](int c, int s) {
        const int k0 = c << 6;
        const __nv_bfloat16* srcAh = Ahi + (long)mBase * K + k0;
        const __nv_bfloat16* srcAl = Alo + (long)mBase * K + k0;
        const __nv_bfloat16* srcBh = Bhi + (long)nBase * K + k0;
        const __nv_bfloat16* srcBl = Blo + (long)nBase * K + k0;
        const uint32_t stage = smem_base + SM_TILES + s * STAGE_B;
        #pragma unroll
        for (int i = 0; i < 4; i++) {        // A: 128 rows x 8 c16
            const int idx = tid + i * 256;
            const int r   = idx >> 3;
            const int c16 = idx & 7;
            const long gofs = (long)r * K + (c16 << 3);
            const uint32_t sofs = stage + SMEM_SWIZZLE_128B((r << 7) | (c16 << 4));
            CP_ASYNC16(sofs + ST_AHI, srcAh + gofs);
            CP_ASYNC16(sofs + ST_ALO, srcAl + gofs);
        }
        #pragma unroll
        for (int i = 0; i < 8; i++) {        // B: 256 rows x 8 c16
            const int idx = tid + i * 256;
            const int r   = idx >> 3;
            const int c16 = idx & 7;
            const long gofs = (long)r * K + (c16 << 3);
            const uint32_t sofs = stage + SMEM_SWIZZLE_128B((r << 7) | (c16 << 4));
            CP_ASYNC16(sofs + ST_BHI, srcBh + gofs);
            CP_ASYNC16(sofs + ST_BLO, srcBl + gofs);
        }
        CP_COMMIT();
    };

    const int NC = K >> 6;   // K-chunks of 64 (>= 16 here)
    load_chunk(0, 0);
    load_chunk(1, 1);

    for (int c = 0; c < NC; c++) {
        const int s = c & 1;
        if (c + 1 < NC) CP_WAIT_1(); else CP_WAIT_0();
        FENCE_PROXY_ASYNC();
        __syncthreads();

        if (wid == 0) {
            const uint32_t stage = smem_base + SM_TILES + s * STAGE_B;
            const uint64_t dAhi = MAKE_SMEM_DESC(stage + ST_AHI);
            const uint64_t dAlo = MAKE_SMEM_DESC(stage + ST_ALO);
            const uint64_t dBhi = MAKE_SMEM_DESC(stage + ST_BHI);
            const uint64_t dBlo = MAKE_SMEM_DESC(stage + ST_BLO);
            if (elect_one_pred()) {
                #pragma unroll
                for (int kk = 0; kk < 4; kk++) {
                    mma_f16_ss(tmem, dAhi + kk * 2, dBhi + kk * 2, GEMM_IDESC_N256,
                               !(c == 0 && kk == 0));
                    mma_f16_ss(tmem, dAlo + kk * 2, dBhi + kk * 2, GEMM_IDESC_N256, true);
                    mma_f16_ss(tmem, dAhi + kk * 2, dBlo + kk * 2, GEMM_IDESC_N256, true);
                }
                TCGEN05_COMMIT(smem_base + SM_MBAR + s * 8);
            }
        }

        // prefetch chunk c+2 into stage s (held chunk c -> need MMA(c) done)
        if (c + 2 < NC) {
            MBARRIER_WAIT_PARITY(smem_base + SM_MBAR + s * 8, (c >> 1) & 1);
            load_chunk(c + 2, s);
        }
    }

    // wait for ALL MMAs (in-order pipe: last commit covers all prior)
    MBARRIER_WAIT_PARITY(smem_base + SM_MBAR + ((NC - 1) & 1) * 8, ((NC - 1) >> 1) & 1);
    TCGEN05_FENCE_AFTER();

    // Epilogue: two 128-col halves through the SMEM staging buffer
    float* sout = (float*)(smem + SM_TILES);
    #pragma unroll
    for (int h2 = 0; h2 < 2; h2++) {
        if (wid < 4) {
            const int r = (wid << 5) + lid;
            #pragma unroll
            for (int cb = 0; cb < 4; cb++) {
                uint32_t regs[32];
                TCGEN05_LD_X32(regs, tmem + h2 * 128 + (cb << 5));
                TCGEN05_WAIT_LD();
                #pragma unroll
                for (int j = 0; j < 32; j += 4) {
                    float4 v = make_float4(__uint_as_float(regs[j]),
                                           __uint_as_float(regs[j + 1]),
                                           __uint_as_float(regs[j + 2]),
                                           __uint_as_float(regs[j + 3]));
                    *(float4*)&sout[r * 132 + (cb << 5) + j] = v;
                }
            }
        }
        __syncthreads();

        for (int idx = tid; idx < 128 * 32; idx += 256) {
            const int r = idx >> 5;
            const int cc = (idx & 31) << 2;
            float4 v = *(float4*)&sout[r * 132 + cc];
            const long gr = mBase + r;
            const int  gc = nBase + h2 * 128 + cc;
            float4 bb = *(const float4*)&bias[gc];
            v.x += bb.x; v.y += bb.y; v.z += bb.z; v.w += bb.w;
            if (OP == 1 || OP == 3) {
                if (OP == 1) {
                    v.x = gelu_exact(v.x); v.y = gelu_exact(v.y);
                    v.z = gelu_exact(v.z); v.w = gelu_exact(v.w);
                }
                const long o = gr * N + gc;
                split_store(Chi, Clo, o + 0, v.x);
                split_store(Chi, Clo, o + 1, v.y);
                split_store(Chi, Clo, o + 2, v.z);
                split_store(Chi, Clo, o + 3, v.w);
            } else if (OP == 2) {
                float4 rr = *(const float4*)&res[gr * N + gc];
                v.x += rr.x; v.y += rr.y; v.z += rr.z; v.w += rr.w;
                *(float4*)&Cf[gr * N + gc] = v;
            } else {
                *(float4*)&Cf[gr * N + gc] = v;
            }
        }
        __syncthreads();
    }
    if (wid == 0) TCGEN05_DEALLOC(tmem, 256);

#else  // =================== FFMA fallback (non-103a passes; never runs on GB300) ===================
    float* As = (float*)smem;                 // [8][128]
    float* Bs = As + 8 * 128;                 // [8][128]

    const int tx = tid & 15;
    const int ty = tid >> 4;
    const int row  = tid >> 1;                // 0..127
    const int kc   = (tid & 1) << 2;          // 0 or 4

    for (int h2 = 0; h2 < 2; h2++) {
        const int nB = nBase + h2 * 128;
        float acc[8][8];
        #pragma unroll
        for (int i = 0; i < 8; i++)
            #pragma unroll
            for (int j = 0; j < 8; j++) acc[i][j] = 0.f;

        for (int k0 = 0; k0 < K; k0 += 8) {
            {
                const long o = (long)(mBase + row) * K + k0 + kc;
                ushort4 h = *(const ushort4*)(Ahi + o);
                ushort4 l = *(const ushort4*)(Alo + o);
                As[(kc + 0) * 128 + row] = __bfloat162float(*(__nv_bfloat16*)&h.x) + __bfloat162float(*(__nv_bfloat16*)&l.x);
                As[(kc + 1) * 128 + row] = __bfloat162float(*(__nv_bfloat16*)&h.y) + __bfloat162float(*(__nv_bfloat16*)&l.y);
                As[(kc + 2) * 128 + row] = __bfloat162float(*(__nv_bfloat16*)&h.z) + __bfloat162float(*(__nv_bfloat16*)&l.z);
                As[(kc + 3) * 128 + row] = __bfloat162float(*(__nv_bfloat16*)&h.w) + __bfloat162float(*(__nv_bfloat16*)&l.w);
            }
            {
                const long o = (long)(nB + row) * K + k0 + kc;
                ushort4 h = *(const ushort4*)(Bhi + o);
                ushort4 l = *(const ushort4*)(Blo + o);
                Bs[(kc + 0) * 128 + row] = __bfloat162float(*(__nv_bfloat16*)&h.x) + __bfloat162float(*(__nv_bfloat16*)&l.x);
                Bs[(kc + 1) * 128 + row] = __bfloat162float(*(__nv_bfloat16*)&h.y) + __bfloat162float(*(__nv_bfloat16*)&l.y);
                Bs[(kc + 2) * 128 + row] = __bfloat162float(*(__nv_bfloat16*)&h.z) + __bfloat162float(*(__nv_bfloat16*)&l.z);
                Bs[(kc + 3) * 128 + row] = __bfloat162float(*(__nv_bfloat16*)&h.w) + __bfloat162float(*(__nv_bfloat16*)&l.w);
            }
            __syncthreads();

            #pragma unroll
            for (int k = 0; k < 8; k++) {
                float a[8], bb[8];
                #pragma unroll
                for (int i = 0; i < 8; i++) a[i]  = As[k * 128 + ty * 8 + i];
                #pragma unroll
                for (int j = 0; j < 8; j++) bb[j] = Bs[k * 128 + tx * 8 + j];
                #pragma unroll
                for (int i = 0; i < 8; i++)
                    #pragma unroll
                    for (int j = 0; j < 8; j++)
                        acc[i][j] = fmaf(a[i], bb[j], acc[i][j]);
            }
            __syncthreads();
        }

        #pragma unroll
        for (int i = 0; i < 8; i++) {
            const long gr = mBase + ty * 8 + i;
            #pragma unroll
            for (int j = 0; j < 8; j++) {
                const int gc = nB + tx * 8 + j;
                float v = acc[i][j] + bias[gc];
                if (OP == 1) {
                    v = gelu_exact(v);
                    split_store(Chi, Clo, gr * N + gc, v);
                } else if (OP == 3) {
                    split_store(Chi, Clo, gr * N + gc, v);
                } else if (OP == 2) {
                    Cf[gr * N + gc] = v + res[gr * N + gc];
                } else {
                    Cf[gr * N + gc] = v;
                }
            }
        }
        __syncthreads();
    }
#endif
}

// ======================= tcgen05 causal flash attention =======================
// (unchanged from R8: 64-key tiles, occ 2, cp.async, in-SMEM V transpose)
#define A_TMEMPTR 0
#define A_MBAR0   8
#define A_MBAR1   16
#define A_SMX     32            // float[256]
#define A_SLS     1056          // float[256]
#define A_Q       3072          // hi 16K, lo at +16384
#define A_K       35840         // hi 8K, lo at +8192
#define A_VT      52224         // hi 8K, lo at +8192
#define A_P       68608         // hi 16K, lo at +16384 ; V staging: hi +0, lo +8192
#define ATTN_SMEM 101376

#if HAS_TCGEN05
__device__ __forceinline__ void attn_issue_S(uint32_t tmem, uint32_t sb) {
    const uint64_t dQh = MAKE_SMEM_DESC(sb + A_Q);
    const uint64_t dQl = MAKE_SMEM_DESC(sb + A_Q + 16384);
    const uint64_t dKh = MAKE_SMEM_DESC(sb + A_K);
    const uint64_t dKl = MAKE_SMEM_DESC(sb + A_K + 8192);
    #pragma unroll
    for (int kk = 0; kk < 4; kk++) {
        mma_f16_ss(tmem, dQh + kk * 2, dKh + kk * 2, ATTN_IDESC, kk != 0);
        mma_f16_ss(tmem, dQl + kk * 2, dKh + kk * 2, ATTN_IDESC, true);
        mma_f16_ss(tmem, dQh + kk * 2, dKl + kk * 2, ATTN_IDESC, true);
    }
}
__device__ __forceinline__ void attn_issue_PV(uint32_t tmem, uint32_t sb) {
    const uint64_t dPh = MAKE_SMEM_DESC(sb + A_P);
    const uint64_t dPl = MAKE_SMEM_DESC(sb + A_P + 16384);
    const uint64_t dVh = MAKE_SMEM_DESC(sb + A_VT);
    const uint64_t dVl = MAKE_SMEM_DESC(sb + A_VT + 8192);
    #pragma unroll
    for (int kk = 0; kk < 4; kk++) {
        mma_f16_ss(tmem + 64, dPh + kk * 2, dVh + kk * 2, ATTN_IDESC, kk != 0);
        mma_f16_ss(tmem + 64, dPl + kk * 2, dVh + kk * 2, ATTN_IDESC, true);
        mma_f16_ss(tmem + 64, dPh + kk * 2, dVl + kk * 2, ATTN_IDESC, true);
    }
}
#endif

__global__ __launch_bounds__(256, 2) void attn_tc(
    const __nv_bfloat16* __restrict__ qkv_hi,
    const __nv_bfloat16* __restrict__ qkv_lo,
    __nv_bfloat16* __restrict__ ohi,
    __nv_bfloat16* __restrict__ olo)
{
    extern __shared__ __align__(1024) char smem[];
    const int tid  = threadIdx.x;
    const int wid  = tid >> 5;
    const int lid  = tid & 31;
    const int qt   = gridDim.x - 1 - blockIdx.x;   // reversed: long CTAs first
    const int head = blockIdx.y;
    const int bat  = blockIdx.z;
    const long tok0 = (long)bat * SEQ;

#if HAS_TCGEN05
    const uint32_t sb = smem_u32_of(smem);
    float* smx = (float*)(smem + A_SMX);
    float* sls = (float*)(smem + A_SLS);
    if (wid == 0) {
        TCGEN05_ALLOC(sb + A_TMEMPTR, 128);
        TCGEN05_RELINQUISH();
    }
    if (tid == 0) {
        MBARRIER_INIT(sb + A_MBAR0, 1);
        MBARRIER_INIT(sb + A_MBAR1, 1);
    }
    __syncthreads();
    uint32_t tmem;
    asm volatile("ld.shared.b32 %0, [%1];" : "=r"(tmem) : "r"(sb + A_TMEMPTR));

    // Q tile (128 x 64 hi/lo) + K tile 0 (64 keys) via cp.async
    #pragma unroll
    for (int i = 0; i < 4; i++) {
        const int idx = tid + i * 256;
        const int r = idx >> 3, c8 = idx & 7;
        const uint32_t sofs = SMEM_SWIZZLE_128B((r << 7) | (c8 << 4));
        const long gq = (tok0 + qt * 128 + r) * (long)QKVW + head * 64 + (c8 << 3);
        CP_ASYNC16(sb + A_Q + sofs,         qkv_hi + gq);
        CP_ASYNC16(sb + A_Q + 16384 + sofs, qkv_lo + gq);
    }
    #pragma unroll
    for (int i = 0; i < 2; i++) {
        const int idx = tid + i * 256;       // 0..511
        const int r = idx >> 3, c8 = idx & 7;
        const uint32_t sofs = SMEM_SWIZZLE_128B((r << 7) | (c8 << 4));
        const long gk = (tok0 + r) * (long)QKVW + 1024 + head * 64 + (c8 << 3);
        CP_ASYNC16(sb + A_K + sofs,        qkv_hi + gk);
        CP_ASYNC16(sb + A_K + 8192 + sofs, qkv_lo + gk);
    }
    CP_COMMIT();
    CP_WAIT_0();
    FENCE_PROXY_ASYNC();
    __syncthreads();
    if (wid == 0 && elect_one_pred()) {
        attn_issue_S(tmem, sb);
        TCGEN05_COMMIT(sb + A_MBAR0);
    }

    const int half = wid >> 2;                 // column half (32 key-cols / 32 hd-cols)
    const int row  = ((wid & 3) << 5) + lid;   // q row
    const int grow = qt * 128 + row;
    const int nkt  = 2 * qt + 2;
    const float SCL = 0.125f * 1.4426950408889634f;  // fold 1/sqrt(hd) * log2(e)

    float o[32];
    #pragma unroll
    for (int j = 0; j < 32; j++) o[j] = 0.f;
    float m = -1e30f, l = 0.f;

    for (int kt = 0; kt < nkt; kt++) {
        const bool pre = (kt + 1 < nkt);

        // stage V(kt) into P region (dead after previous PV wait)
        #pragma unroll
        for (int i = 0; i < 2; i++) {
            const int idx = tid + i * 256;
            const int r = idx >> 3, c8 = idx & 7;
            const uint32_t sofs = SMEM_SWIZZLE_128B((r << 7) | (c8 << 4));
            const long gv = (tok0 + kt * 64 + r) * (long)QKVW + 2048 + head * 64 + (c8 << 3);
            CP_ASYNC16(sb + A_P + sofs,        qkv_hi + gv);
            CP_ASYNC16(sb + A_P + 8192 + sofs, qkv_lo + gv);
        }
        CP_COMMIT();   // group V

        // wait S(kt) -> K buffer free -> prefetch K(kt+1)
        MBARRIER_WAIT_PARITY(sb + A_MBAR0, kt & 1);
        TCGEN05_FENCE_AFTER();
        if (pre) {
            #pragma unroll
            for (int i = 0; i < 2; i++) {
                const int idx = tid + i * 256;
                const int r = idx >> 3, c8 = idx & 7;
                const uint32_t sofs = SMEM_SWIZZLE_128B((r << 7) | (c8 << 4));
                const long gk = (tok0 + (kt + 1) * 64 + r) * (long)QKVW + 1024 + head * 64 + (c8 << 3);
                CP_ASYNC16(sb + A_K + sofs,        qkv_hi + gk);
                CP_ASYNC16(sb + A_K + 8192 + sofs, qkv_lo + gk);
            }
            CP_COMMIT();   // group K
        }

        // pull this warp's 32 S columns
        uint32_t r0[32];
        TCGEN05_LD_X32(r0, tmem + half * 32);
        TCGEN05_WAIT_LD();

        // V staged complete (K group may remain in flight)
        if (pre) CP_WAIT_1(); else CP_WAIT_0();
        __syncthreads();   // S1: staged V visible

        // transpose staged V -> Vt[hd][key] (hi + lo)
        #pragma unroll
        for (int i = 0; i < 8; i++) {
            const int idx = tid + i * 256;        // 0..2047
            const int c  = idx & 63;              // hd
            const int kp = idx >> 6;              // key pair 0..31
            const int so0 = SMEM_SWIZZLE_128B(((2 * kp)     << 7) | (c << 1));
            const int so1 = SMEM_SWIZZLE_128B(((2 * kp + 1) << 7) | (c << 1));
            const int dd  = SMEM_SWIZZLE_128B((c << 7) | (kp << 2));
            uint32_t a = *(const uint16_t*)(smem + A_P + so0);
            uint32_t b = *(const uint16_t*)(smem + A_P + so1);
            *(uint32_t*)(smem + A_VT + dd) = a | (b << 16);
            a = *(const uint16_t*)(smem + A_P + 8192 + so0);
            b = *(const uint16_t*)(smem + A_P + 8192 + so1);
            *(uint32_t*)(smem + A_VT + 8192 + dd) = a | (b << 16);
        }

        float s[32];
        #pragma unroll
        for (int j = 0; j < 32; j++) s[j] = __uint_as_float(r0[j]) * SCL;

        if (kt >= 2 * qt) {   // diagonal tiles: causal mask
            const int jbase = kt * 64 + half * 32;
            #pragma unroll
            for (int j = 0; j < 32; j++)
                if (jbase + j > grow) s[j] = -1e30f;
        }
        float lmx = -1e30f;
        #pragma unroll
        for (int j = 0; j < 32; j++) lmx = fmaxf(lmx, s[j]);
        smx[half * 128 + row] = lmx;
        __syncthreads();   // S2: smx visible; transpose reads done

        const float mnew = fmaxf(m, fmaxf(smx[row], smx[128 + row]));
        const float scl  = exp2f(m - mnew);
        m = mnew;
        float ls = 0.f;
        #pragma unroll
        for (int j = 0; j < 32; j++) { s[j] = exp2f(s[j] - mnew); ls += s[j]; }
        sls[half * 128 + row] = ls;

        // store this half's P (hi/lo), overwriting staging
        #pragma unroll
        for (int j8 = 0; j8 < 4; j8++) {
            __align__(16) __nv_bfloat16 hb[8], lb[8];
            #pragma unroll
            for (int j = 0; j < 8; j++) {
                const float v = s[(j8 << 3) + j];
                const __nv_bfloat16 h = __float2bfloat16(v);
                hb[j] = h;
                lb[j] = __float2bfloat16(v - __bfloat162float(h));
            }
            const int so = SMEM_SWIZZLE_128B((row << 7) | (half << 6) | (j8 << 4));
            *(uint4*)(smem + A_P + so)         = *(uint4*)hb;
            *(uint4*)(smem + A_P + 16384 + so) = *(uint4*)lb;
        }
        FENCE_PROXY_ASYNC();
        __syncthreads();   // S3: P + Vt + sls visible

        l = l * scl + sls[row] + sls[128 + row];

        if (wid == 0 && elect_one_pred()) {
            attn_issue_PV(tmem, sb);
            TCGEN05_COMMIT(sb + A_MBAR1);
        }

        // issue S(kt+1) while PV(kt) runs
        if (pre) {
            CP_WAIT_0();
            FENCE_PROXY_ASYNC();
            __syncthreads();   // S4: K(kt+1) visible
            if (wid == 0 && elect_one_pred()) {
                attn_issue_S(tmem, sb);
                TCGEN05_COMMIT(sb + A_MBAR0);
            }
        }

        // wait PV(kt), accumulate O (this half's 32 hd cols)
        MBARRIER_WAIT_PARITY(sb + A_MBAR1, kt & 1);
        TCGEN05_FENCE_AFTER();
        uint32_t p0[32];
        TCGEN05_LD_X32(p0, tmem + 64 + half * 32);
        TCGEN05_WAIT_LD();
        #pragma unroll
        for (int j = 0; j < 32; j++) o[j] = o[j] * scl + __uint_as_float(p0[j]);
    }

    // epilogue: each warp writes its 32 hd cols for its rows
    {
        const float invl = 1.0f / l;
        const long gofs = (tok0 + grow) * (long)DMODEL + head * 64 + half * 32;
        #pragma unroll
        for (int j8 = 0; j8 < 4; j8++) {
            __align__(16) __nv_bfloat16 hb[8], lb[8];
            #pragma unroll
            for (int j = 0; j < 8; j++) {
                const float v = o[(j8 << 3) + j] * invl;
                const __nv_bfloat16 h = __float2bfloat16(v);
                hb[j] = h;
                lb[j] = __float2bfloat16(v - __bfloat162float(h));
            }
            *(uint4*)(ohi + gofs + (j8 << 3)) = *(uint4*)hb;
            *(uint4*)(olo + gofs + (j8 << 3)) = *(uint4*)lb;
        }
    }
    __syncthreads();
    if (wid == 0) TCGEN05_DEALLOC(tmem, 128);

#else  // =================== compile-only FFMA fallback ===================
    if (tid < 128) {
        const int grow2 = qt * 128 + tid;
        const long qofs = (tok0 + grow2) * (long)QKVW + head * 64;
        float q[64], o2[64];
        #pragma unroll
        for (int c = 0; c < 64; c++) {
            q[c] = (__bfloat162float(qkv_hi[qofs + c]) +
                    __bfloat162float(qkv_lo[qofs + c])) * 0.125f;
            o2[c] = 0.f;
        }
        float m2 = -1e30f, l2 = 0.f;
        for (int j = 0; j <= grow2; j++) {
            const long kofs = (tok0 + j) * (long)QKVW + 1024 + head * 64;
            float s = 0.f;
            for (int c = 0; c < 64; c++)
                s += q[c] * (__bfloat162float(qkv_hi[kofs + c]) +
                             __bfloat162float(qkv_lo[kofs + c]));
            const float mnew = fmaxf(m2, s);
            const float scf = expf(m2 - mnew);
            const float p = expf(s - mnew);
            l2 = l2 * scf + p;
            m2 = mnew;
            const long vofs = kofs + 1024;
            for (int c = 0; c < 64; c++)
                o2[c] = o2[c] * scf + p * (__bfloat162float(qkv_hi[vofs + c]) +
                                           __bfloat162float(qkv_lo[vofs + c]));
        }
        const long gofs = (tok0 + grow2) * (long)DMODEL + head * 64;
        for (int c = 0; c < 64; c++)
            split_store(ohi, olo, gofs + c, o2[c] / l2);
    }
#endif
}

// ======================= driver =======================
extern "C" void kernel_launch(void* const* d_in, const int* in_sizes, int n_in,
                              void* d_out, int out_size)
{
    const float* x    = (const float*)d_in[0];
    const float* g1   = (const float*)d_in[1];
    const float* b1   = (const float*)d_in[2];
    const float* Wqkv = (const float*)d_in[3];
    const float* bqkv = (const float*)d_in[4];
    const float* Wo   = (const float*)d_in[5];
    const float* bo   = (const float*)d_in[6];
    const float* g2   = (const float*)d_in[7];
    const float* b2   = (const float*)d_in[8];
    const float* W1   = (const float*)d_in[9];
    const float* b1f  = (const float*)d_in[10];
    const float* W2   = (const float*)d_in[11];
    const float* b2f  = (const float*)d_in[12];
    float* out = (float*)d_out;

    float *x2;
    __nv_bfloat16 *qkv_hi, *qkv_lo;
    __nv_bfloat16 *h_hi, *h_lo, *attn_hi, *attn_lo, *hh_hi, *hh_lo, *ff_hi, *ff_lo;
    __nv_bfloat16 *WqkvT_hi, *WqkvT_lo, *WoT_hi, *WoT_lo, *W1T_hi, *W1T_lo, *W2T_hi, *W2T_lo;
    cudaGetSymbolAddress((void**)&x2,       g_x2);
    cudaGetSymbolAddress((void**)&qkv_hi,   g_qkv_hi);
    cudaGetSymbolAddress((void**)&qkv_lo,   g_qkv_lo);
    cudaGetSymbolAddress((void**)&h_hi,     g_h_hi);
    cudaGetSymbolAddress((void**)&h_lo,     g_h_lo);
    cudaGetSymbolAddress((void**)&attn_hi,  g_attn_hi);
    cudaGetSymbolAddress((void**)&attn_lo,  g_attn_lo);
    cudaGetSymbolAddress((void**)&hh_hi,    g_hh_hi);
    cudaGetSymbolAddress((void**)&hh_lo,    g_hh_lo);
    cudaGetSymbolAddress((void**)&ff_hi,    g_ff_hi);
    cudaGetSymbolAddress((void**)&ff_lo,    g_ff_lo);
    cudaGetSymbolAddress((void**)&WqkvT_hi, g_WqkvT_hi);
    cudaGetSymbolAddress((void**)&WqkvT_lo, g_WqkvT_lo);
    cudaGetSymbolAddress((void**)&WoT_hi,   g_WoT_hi);
    cudaGetSymbolAddress((void**)&WoT_lo,   g_WoT_lo);
    cudaGetSymbolAddress((void**)&W1T_hi,   g_W1T_hi);
    cudaGetSymbolAddress((void**)&W1T_lo,   g_W1T_lo);
    cudaGetSymbolAddress((void**)&W2T_hi,   g_W2T_hi);
    cudaGetSymbolAddress((void**)&W2T_lo,   g_W2T_lo);

    cudaFuncSetAttribute(attn_tc,    cudaFuncAttributeMaxDynamicSharedMemorySize, ATTN_SMEM);
    cudaFuncSetAttribute(gemm_tc<1>, cudaFuncAttributeMaxDynamicSharedMemorySize, GEMM_SMEM);
    cudaFuncSetAttribute(gemm_tc<2>, cudaFuncAttributeMaxDynamicSharedMemorySize, GEMM_SMEM);
    cudaFuncSetAttribute(gemm_tc<3>, cudaFuncAttributeMaxDynamicSharedMemorySize, GEMM_SMEM);

    // weight conversion + transpose (K-major for MMA B operand), 64x64 tiles
    wtrans_kernel<<<dim3(QKVW / 64, DMODEL / 64), 256>>>(Wqkv, WqkvT_hi, WqkvT_lo, DMODEL, QKVW);
    wtrans_kernel<<<dim3(DMODEL / 64, DMODEL / 64), 256>>>(Wo, WoT_hi, WoT_lo, DMODEL, DMODEL);
    wtrans_kernel<<<dim3(FFDIM / 64, DMODEL / 64), 256>>>(W1, W1T_hi, W1T_lo, DMODEL, FFDIM);
    wtrans_kernel<<<dim3(DMODEL / 64, FFDIM / 64), 256>>>(W2, W2T_hi, W2T_lo, FFDIM, DMODEL);

    // LN1 -> hi/lo
    ln_kernel<<<NTOK, 256>>>(x, g1, b1, h_hi, h_lo);
    // QKV projection -> bf16 hi/lo (attention input)
    gemm_tc<3><<<dim3(QKVW / 256, NTOK / 128), 256, GEMM_SMEM>>>(
        h_hi, h_lo, WqkvT_hi, WqkvT_lo, bqkv, nullptr, nullptr, qkv_hi, qkv_lo, QKVW, DMODEL);
    // causal attention (tcgen05, 64-key pipelined, occ 2) -> hi/lo
    attn_tc<<<dim3(SEQ / 128, NH, BATCH), 256, ATTN_SMEM>>>(qkv_hi, qkv_lo, attn_hi, attn_lo);
    // output projection + residual -> x2 (fp32)
    gemm_tc<2><<<dim3(DMODEL / 256, NTOK / 128), 256, GEMM_SMEM>>>(
        attn_hi, attn_lo, WoT_hi, WoT_lo, bo, x, x2, nullptr, nullptr, DMODEL, DMODEL);
    // LN2 -> hi/lo
    ln_kernel<<<NTOK, 256>>>(x2, g2, b2, hh_hi, hh_lo);
    // FF1 + GELU -> hi/lo
    gemm_tc<1><<<dim3(FFDIM / 256, NTOK / 128), 256, GEMM_SMEM>>>(
        hh_hi, hh_lo, W1T_hi, W1T_lo, b1f, nullptr, nullptr, ff_hi, ff_lo, FFDIM, DMODEL);
    // FF2 + residual -> out (fp32)
    gemm_tc<2><<<dim3(DMODEL / 256, NTOK / 128), 256, GEMM_SMEM>>>(
        ff_hi, ff_lo, W2T_hi, W2T_lo, b2f, x2, out, nullptr, nullptr, DMODEL, FFDIM);
}